// round 5
// baseline (speedup 1.0000x reference)
#include <cuda_runtime.h>
#include <math.h>
#include <cstdint>

// Problem constants
#define BATCH 2
#define TSEQ  2048
#define DMODEL 1024
#define NHEADS 16
#define HDIM  64
#define ROWS (BATCH * TSEQ)          // 4096
#define QKV_N (3 * DMODEL)           // 3072

// ---------------- scratch (no allocation allowed) ----------------
__device__ float g_qkv[ROWS * QKV_N];               // [B*T, 3*D]
__device__ float g_q[BATCH * NHEADS * TSEQ * HDIM]; // [B,H,T,Dh]
__device__ float g_k[BATCH * NHEADS * TSEQ * HDIM];
__device__ float g_v[BATCH * NHEADS * TSEQ * HDIM];
__device__ float g_attn[ROWS * DMODEL];             // [B*T, D]
__device__ float g_cs[TSEQ * 32 * 2];               // cos,sin per (t, freq)

// ---------------- tiled fp32 GEMM: C = A[M,K] @ B[N,K]^T + bias ----------------
#define BM 128
#define BN 128
#define BKD 8
#define TM 8
#define TN 8

template<int M, int N, int K>
__device__ __forceinline__ void gemm_body(const float* __restrict__ A,
                                          const float* __restrict__ B,
                                          const float* __restrict__ bias,
                                          float* __restrict__ C)
{
    __shared__ float As[BKD][BM];
    __shared__ float Bs[BKD][BN];

    const int tid = threadIdx.x;           // 256 threads
    const int tx = tid & 15;
    const int ty = tid >> 4;
    const int bm = blockIdx.y * BM;
    const int bn = blockIdx.x * BN;

    const int lrow = tid >> 1;
    const int lk4  = (tid & 1) * 4;

    const float* Aptr = A + (size_t)(bm + lrow) * K + lk4;
    const float* Bptr = B + (size_t)(bn + lrow) * K + lk4;

    float acc[TM][TN];
    #pragma unroll
    for (int m = 0; m < TM; m++)
        #pragma unroll
        for (int n = 0; n < TN; n++)
            acc[m][n] = 0.f;

    for (int k0 = 0; k0 < K; k0 += BKD) {
        float4 av = *(const float4*)(Aptr + k0);
        float4 bv = *(const float4*)(Bptr + k0);
        As[lk4 + 0][lrow] = av.x; As[lk4 + 1][lrow] = av.y;
        As[lk4 + 2][lrow] = av.z; As[lk4 + 3][lrow] = av.w;
        Bs[lk4 + 0][lrow] = bv.x; Bs[lk4 + 1][lrow] = bv.y;
        Bs[lk4 + 2][lrow] = bv.z; Bs[lk4 + 3][lrow] = bv.w;
        __syncthreads();

        #pragma unroll
        for (int k = 0; k < BKD; k++) {
            float ra[TM], rb[TN];
            float4 a0 = *(const float4*)&As[k][ty * TM];
            float4 a1 = *(const float4*)&As[k][ty * TM + 4];
            ra[0]=a0.x; ra[1]=a0.y; ra[2]=a0.z; ra[3]=a0.w;
            ra[4]=a1.x; ra[5]=a1.y; ra[6]=a1.z; ra[7]=a1.w;
            float4 b0 = *(const float4*)&Bs[k][tx * TN];
            float4 b1 = *(const float4*)&Bs[k][tx * TN + 4];
            rb[0]=b0.x; rb[1]=b0.y; rb[2]=b0.z; rb[3]=b0.w;
            rb[4]=b1.x; rb[5]=b1.y; rb[6]=b1.z; rb[7]=b1.w;
            #pragma unroll
            for (int m = 0; m < TM; m++)
                #pragma unroll
                for (int n = 0; n < TN; n++)
                    acc[m][n] = fmaf(ra[m], rb[n], acc[m][n]);
        }
        __syncthreads();
    }

    #pragma unroll
    for (int m = 0; m < TM; m++) {
        const int row = bm + ty * TM + m;
        float* cp = C + (size_t)row * N + bn + tx * TN;
        const float* bp = bias + bn + tx * TN;
        #pragma unroll
        for (int n = 0; n < TN; n += 4) {
            float4 o;
            o.x = acc[m][n + 0] + bp[n + 0];
            o.y = acc[m][n + 1] + bp[n + 1];
            o.z = acc[m][n + 2] + bp[n + 2];
            o.w = acc[m][n + 3] + bp[n + 3];
            *(float4*)(cp + n) = o;
        }
    }
}

__global__ __launch_bounds__(256) void qkv_gemm_kernel(const float* __restrict__ x,
                                                       const float* __restrict__ w,
                                                       const float* __restrict__ b)
{
    gemm_body<ROWS, QKV_N, DMODEL>(x, w, b, g_qkv);
}

__global__ __launch_bounds__(256) void proj_gemm_kernel(const float* __restrict__ w,
                                                        const float* __restrict__ b,
                                                        float* __restrict__ out)
{
    gemm_body<ROWS, DMODEL, DMODEL>(g_attn, w, b, out);
}

// ---------------- RoPE table ----------------
__global__ void rope_table_kernel()
{
    int idx = blockIdx.x * blockDim.x + threadIdx.x;
    if (idx >= TSEQ * 32) return;
    int t = idx >> 5;
    int j = idx & 31;
    float invf = powf(10000.0f, -((float)(2 * j) / 64.0f));
    float angle = (float)t * invf;
    double a = (double)angle;
    double s, c;
    sincos(a, &s, &c);
    g_cs[idx * 2 + 0] = (float)c;
    g_cs[idx * 2 + 1] = (float)s;
}

// ---------------- RoPE apply + transpose to [B,H,T,Dh] ----------------
__global__ void rope_apply_kernel()
{
    int idx = blockIdx.x * blockDim.x + threadIdx.x;
    if (idx >= BATCH * TSEQ * NHEADS * 32) return;
    int j = idx & 31;
    int h = (idx >> 5) & (NHEADS - 1);
    int t = (idx >> 9) & (TSEQ - 1);
    int b = idx >> 20;

    int row = b * TSEQ + t;
    const float* base = g_qkv + (size_t)row * QKV_N + h * HDIM;

    float c  = g_cs[(t * 32 + j) * 2 + 0];
    float sn = g_cs[(t * 32 + j) * 2 + 1];

    float q1 = base[j],          q2 = base[j + 32];
    float k1 = base[DMODEL + j], k2 = base[DMODEL + j + 32];

    size_t od = (((size_t)b * NHEADS + h) * TSEQ + t) * HDIM;
    g_q[od + j]      = q1 * c - q2 * sn;
    g_q[od + j + 32] = q2 * c + q1 * sn;
    g_k[od + j]      = k1 * c - k2 * sn;
    g_k[od + j + 32] = k2 * c + k1 * sn;
    g_v[od + j]      = base[2 * DMODEL + j];
    g_v[od + j + 32] = base[2 * DMODEL + j + 32];
}

// ---------------- flash attention v3 ----------------
// 256 threads: thread = (row-pair u, quarter qd). Rows 2u,2u+1 x 16 dims each.
// K/V float4 reused across both rows -> 8 FMA per LDS.128 (2x v2).
// 16B XOR swizzle makes the 4 quarter addresses bank-disjoint.
#define BQ 128
#define BKV 32
#define SB 8

__device__ __forceinline__ float ex2(float x) {
    float y;
    asm("ex2.approx.ftz.f32 %0, %1;" : "=f"(y) : "f"(x));
    return y;
}

// word offset of 16B chunk w (0..15) within a 64-float row, swizzled
__device__ __forceinline__ int swz(int w) { return (w * 4) ^ ((w & 8) >> 1); }

__global__ __launch_bounds__(256, 2) void flash_kernel()
{
    const int tid = threadIdx.x;
    const int qd = tid & 3;                         // dim quarter (16 floats)
    const int u  = tid >> 2;                        // row pair 0..63
    const int qt = (gridDim.x - 1) - blockIdx.x;    // heaviest tiles first
    const int h = blockIdx.y;
    const int b = blockIdx.z;
    const int qi0 = qt * BQ + 2 * u;
    const int qi1 = qi0 + 1;

    const size_t bh = ((size_t)b * NHEADS + h) * TSEQ * HDIM;

    __shared__ float smK[BKV * HDIM];
    __shared__ float smV[BKV * HDIM];

    // per-quarter swizzled chunk offsets (w = qd*4 + i)
    int koff[4];
    #pragma unroll
    for (int i = 0; i < 4; i++) koff[i] = swz(qd * 4 + i);

    // q quarter-rows in registers (pre-scaled by 1/sqrt(Dh)*log2e)
    const float pre = 0.125f * 1.4426950408889634f;
    float4 qa[4], qb[4];
    {
        const float4* qp0 = (const float4*)(g_q + bh + (size_t)qi0 * HDIM + qd * 16);
        const float4* qp1 = (const float4*)(g_q + bh + (size_t)qi1 * HDIM + qd * 16);
        #pragma unroll
        for (int i = 0; i < 4; i++) {
            float4 v = qp0[i];
            v.x *= pre; v.y *= pre; v.z *= pre; v.w *= pre;
            qa[i] = v;
            v = qp1[i];
            v.x *= pre; v.y *= pre; v.z *= pre; v.w *= pre;
            qb[i] = v;
        }
    }

    float acc0[16], acc1[16];
    #pragma unroll
    for (int d = 0; d < 16; d++) { acc0[d] = 0.f; acc1[d] = 0.f; }
    float m0 = -INFINITY, l0 = 0.f;
    float m1 = -INFINITY, l1 = 0.f;

    const int warp_min_qi = qt * BQ + ((tid >> 5) << 4);  // warp covers 16 aligned rows
    const int ntiles = (qt + 1) * (BQ / BKV);

    for (int t0 = 0; t0 < ntiles; t0++) {
        const int j0 = t0 * BKV;
        // cooperative swizzled K/V tile load (32 keys x 64 floats each)
        {
            const float4* ksrc = (const float4*)(g_k + bh + (size_t)j0 * HDIM);
            const float4* vsrc = (const float4*)(g_v + bh + (size_t)j0 * HDIM);
            #pragma unroll
            for (int i = 0; i < 2; i++) {
                const int idx = i * 256 + tid;     // 0..511 float4
                const int j = idx >> 4;
                const int w = idx & 15;
                const int dst = j * HDIM + swz(w);
                *(float4*)&smK[dst] = ksrc[idx];
                *(float4*)&smV[dst] = vsrc[idx];
            }
        }
        __syncthreads();

        if (warp_min_qi >= j0) {   // warp-uniform (j0 multiple of 32, warp rows 16-aligned)
            #pragma unroll
            for (int sb = 0; sb < BKV / SB; sb++) {
                const int jb = j0 + sb * SB;
                float s0[SB], s1[SB];
                float mt0 = m0, mt1 = m1;
                #pragma unroll
                for (int jj = 0; jj < SB; jj++) {
                    const float* kr = &smK[(sb * SB + jj) * HDIM];
                    float pa = 0.f, pb = 0.f;
                    #pragma unroll
                    for (int i = 0; i < 4; i++) {
                        float4 kk = *(const float4*)&kr[koff[i]];
                        pa = fmaf(qa[i].x, kk.x, pa); pb = fmaf(qb[i].x, kk.x, pb);
                        pa = fmaf(qa[i].y, kk.y, pa); pb = fmaf(qb[i].y, kk.y, pb);
                        pa = fmaf(qa[i].z, kk.z, pa); pb = fmaf(qb[i].z, kk.z, pb);
                        pa = fmaf(qa[i].w, kk.w, pa); pb = fmaf(qb[i].w, kk.w, pb);
                    }
                    pa += __shfl_xor_sync(0xffffffffu, pa, 1);
                    pa += __shfl_xor_sync(0xffffffffu, pa, 2);
                    pb += __shfl_xor_sync(0xffffffffu, pb, 1);
                    pb += __shfl_xor_sync(0xffffffffu, pb, 2);
                    s0[jj] = pa; s1[jj] = pb;
                    if (jb + jj <= qi0) mt0 = fmaxf(mt0, pa);
                    if (jb + jj <= qi1) mt1 = fmaxf(mt1, pb);
                }
                const float c0 = ex2(m0 - mt0);    // -inf path -> 0
                const float c1 = ex2(m1 - mt1);
                m0 = mt0; m1 = mt1;
                l0 *= c0; l1 *= c1;
                #pragma unroll
                for (int d = 0; d < 16; d++) { acc0[d] *= c0; acc1[d] *= c1; }

                #pragma unroll
                for (int jj = 0; jj < SB; jj++) {
                    const float p0 = (jb + jj <= qi0) ? ex2(s0[jj] - mt0) : 0.f;
                    const float p1 = (jb + jj <= qi1) ? ex2(s1[jj] - mt1) : 0.f;
                    l0 += p0; l1 += p1;
                    const float* vr = &smV[(sb * SB + jj) * HDIM];
                    #pragma unroll
                    for (int i = 0; i < 4; i++) {
                        float4 vv = *(const float4*)&vr[koff[i]];
                        acc0[4*i+0] = fmaf(p0, vv.x, acc0[4*i+0]);
                        acc1[4*i+0] = fmaf(p1, vv.x, acc1[4*i+0]);
                        acc0[4*i+1] = fmaf(p0, vv.y, acc0[4*i+1]);
                        acc1[4*i+1] = fmaf(p1, vv.y, acc1[4*i+1]);
                        acc0[4*i+2] = fmaf(p0, vv.z, acc0[4*i+2]);
                        acc1[4*i+2] = fmaf(p1, vv.z, acc1[4*i+2]);
                        acc0[4*i+3] = fmaf(p0, vv.w, acc0[4*i+3]);
                        acc1[4*i+3] = fmaf(p1, vv.w, acc1[4*i+3]);
                    }
                }
            }
        }
        __syncthreads();
    }

    // write O quarters for both rows as [B,T,H,Dh]
    const float il0 = 1.f / l0;
    const float il1 = 1.f / l1;
    float* op0 = g_attn + (((size_t)b * TSEQ + qi0) * NHEADS + h) * HDIM + qd * 16;
    float* op1 = g_attn + (((size_t)b * TSEQ + qi1) * NHEADS + h) * HDIM + qd * 16;
    #pragma unroll
    for (int i = 0; i < 4; i++) {
        float4 o0, o1;
        o0.x = acc0[4*i+0] * il0; o0.y = acc0[4*i+1] * il0;
        o0.z = acc0[4*i+2] * il0; o0.w = acc0[4*i+3] * il0;
        o1.x = acc1[4*i+0] * il1; o1.y = acc1[4*i+1] * il1;
        o1.z = acc1[4*i+2] * il1; o1.w = acc1[4*i+3] * il1;
        *(float4*)(op0 + 4*i) = o0;
        *(float4*)(op1 + 4*i) = o1;
    }
}

// ---------------- launch ----------------
extern "C" void kernel_launch(void* const* d_in, const int* in_sizes, int n_in,
                              void* d_out, int out_size)
{
    const float* x      = (const float*)d_in[0];
    const float* qkv_w  = (const float*)d_in[1];
    const float* qkv_b  = (const float*)d_in[2];
    const float* proj_w = (const float*)d_in[3];
    const float* proj_b = (const float*)d_in[4];
    float* out = (float*)d_out;

    // 1) QKV = x @ qkv_w^T + qkv_b
    qkv_gemm_kernel<<<dim3(QKV_N / BN, ROWS / BM), 256>>>(x, qkv_w, qkv_b);

    // 2) RoPE cos/sin table
    rope_table_kernel<<<(TSEQ * 32 + 255) / 256, 256>>>();

    // 3) RoPE apply + layout to [B,H,T,Dh]
    rope_apply_kernel<<<(BATCH * TSEQ * NHEADS * 32) / 256, 256>>>();

    // 4) causal flash attention v3
    flash_kernel<<<dim3(TSEQ / BQ, NHEADS, BATCH), 256>>>();

    // 5) out = attn @ proj_w^T + proj_b
    proj_gemm_kernel<<<dim3(DMODEL / BN, ROWS / BM), 256>>>(proj_w, proj_b, out);
}

// round 6
// speedup vs baseline: 1.0400x; 1.0400x over previous
#include <cuda_runtime.h>
#include <math.h>
#include <cstdint>

// Problem constants
#define BATCH 2
#define TSEQ  2048
#define DMODEL 1024
#define NHEADS 16
#define HDIM  64
#define ROWS (BATCH * TSEQ)          // 4096
#define QKV_N (3 * DMODEL)           // 3072

// ---------------- scratch (no allocation allowed) ----------------
__device__ float g_qkv[ROWS * QKV_N];               // [B*T, 3*D]
__device__ float g_q[BATCH * NHEADS * TSEQ * HDIM]; // [B,H,T,Dh]
__device__ float g_k[BATCH * NHEADS * TSEQ * HDIM];
__device__ float g_v[BATCH * NHEADS * TSEQ * HDIM];
__device__ float g_attn[ROWS * DMODEL];             // [B*T, D]
__device__ float g_cs[TSEQ * 32 * 2];               // cos,sin per (t, freq)

// ---------------- tiled fp32 GEMM: C = A[M,K] @ B[N,K]^T + bias ----------------
#define BM 128
#define BN 128
#define BKD 8
#define TM 8
#define TN 8

template<int M, int N, int K>
__device__ __forceinline__ void gemm_body(const float* __restrict__ A,
                                          const float* __restrict__ B,
                                          const float* __restrict__ bias,
                                          float* __restrict__ C)
{
    __shared__ float As[BKD][BM];
    __shared__ float Bs[BKD][BN];

    const int tid = threadIdx.x;           // 256 threads
    const int tx = tid & 15;
    const int ty = tid >> 4;
    const int bm = blockIdx.y * BM;
    const int bn = blockIdx.x * BN;

    const int lrow = tid >> 1;
    const int lk4  = (tid & 1) * 4;

    const float* Aptr = A + (size_t)(bm + lrow) * K + lk4;
    const float* Bptr = B + (size_t)(bn + lrow) * K + lk4;

    float acc[TM][TN];
    #pragma unroll
    for (int m = 0; m < TM; m++)
        #pragma unroll
        for (int n = 0; n < TN; n++)
            acc[m][n] = 0.f;

    for (int k0 = 0; k0 < K; k0 += BKD) {
        float4 av = *(const float4*)(Aptr + k0);
        float4 bv = *(const float4*)(Bptr + k0);
        As[lk4 + 0][lrow] = av.x; As[lk4 + 1][lrow] = av.y;
        As[lk4 + 2][lrow] = av.z; As[lk4 + 3][lrow] = av.w;
        Bs[lk4 + 0][lrow] = bv.x; Bs[lk4 + 1][lrow] = bv.y;
        Bs[lk4 + 2][lrow] = bv.z; Bs[lk4 + 3][lrow] = bv.w;
        __syncthreads();

        #pragma unroll
        for (int k = 0; k < BKD; k++) {
            float ra[TM], rb[TN];
            float4 a0 = *(const float4*)&As[k][ty * TM];
            float4 a1 = *(const float4*)&As[k][ty * TM + 4];
            ra[0]=a0.x; ra[1]=a0.y; ra[2]=a0.z; ra[3]=a0.w;
            ra[4]=a1.x; ra[5]=a1.y; ra[6]=a1.z; ra[7]=a1.w;
            float4 b0 = *(const float4*)&Bs[k][tx * TN];
            float4 b1 = *(const float4*)&Bs[k][tx * TN + 4];
            rb[0]=b0.x; rb[1]=b0.y; rb[2]=b0.z; rb[3]=b0.w;
            rb[4]=b1.x; rb[5]=b1.y; rb[6]=b1.z; rb[7]=b1.w;
            #pragma unroll
            for (int m = 0; m < TM; m++)
                #pragma unroll
                for (int n = 0; n < TN; n++)
                    acc[m][n] = fmaf(ra[m], rb[n], acc[m][n]);
        }
        __syncthreads();
    }

    #pragma unroll
    for (int m = 0; m < TM; m++) {
        const int row = bm + ty * TM + m;
        float* cp = C + (size_t)row * N + bn + tx * TN;
        const float* bp = bias + bn + tx * TN;
        #pragma unroll
        for (int n = 0; n < TN; n += 4) {
            float4 o;
            o.x = acc[m][n + 0] + bp[n + 0];
            o.y = acc[m][n + 1] + bp[n + 1];
            o.z = acc[m][n + 2] + bp[n + 2];
            o.w = acc[m][n + 3] + bp[n + 3];
            *(float4*)(cp + n) = o;
        }
    }
}

__global__ __launch_bounds__(256) void qkv_gemm_kernel(const float* __restrict__ x,
                                                       const float* __restrict__ w,
                                                       const float* __restrict__ b)
{
    gemm_body<ROWS, QKV_N, DMODEL>(x, w, b, g_qkv);
}

__global__ __launch_bounds__(256) void proj_gemm_kernel(const float* __restrict__ w,
                                                        const float* __restrict__ b,
                                                        float* __restrict__ out)
{
    gemm_body<ROWS, DMODEL, DMODEL>(g_attn, w, b, out);
}

// ---------------- RoPE table ----------------
__global__ void rope_table_kernel()
{
    int idx = blockIdx.x * blockDim.x + threadIdx.x;
    if (idx >= TSEQ * 32) return;
    int t = idx >> 5;
    int j = idx & 31;
    float invf = powf(10000.0f, -((float)(2 * j) / 64.0f));
    float angle = (float)t * invf;
    double a = (double)angle;
    double s, c;
    sincos(a, &s, &c);
    g_cs[idx * 2 + 0] = (float)c;
    g_cs[idx * 2 + 1] = (float)s;
}

// ---------------- RoPE apply + transpose to [B,H,T,Dh] ----------------
__global__ void rope_apply_kernel()
{
    int idx = blockIdx.x * blockDim.x + threadIdx.x;
    if (idx >= BATCH * TSEQ * NHEADS * 32) return;
    int j = idx & 31;
    int h = (idx >> 5) & (NHEADS - 1);
    int t = (idx >> 9) & (TSEQ - 1);
    int b = idx >> 20;

    int row = b * TSEQ + t;
    const float* base = g_qkv + (size_t)row * QKV_N + h * HDIM;

    float c  = g_cs[(t * 32 + j) * 2 + 0];
    float sn = g_cs[(t * 32 + j) * 2 + 1];

    float q1 = base[j],          q2 = base[j + 32];
    float k1 = base[DMODEL + j], k2 = base[DMODEL + j + 32];

    size_t od = (((size_t)b * NHEADS + h) * TSEQ + t) * HDIM;
    g_q[od + j]      = q1 * c - q2 * sn;
    g_q[od + j + 32] = q2 * c + q1 * sn;
    g_k[od + j]      = k1 * c - k2 * sn;
    g_k[od + j + 32] = k2 * c + k1 * sn;
    g_v[od + j]      = base[2 * DMODEL + j];
    g_v[od + j + 32] = base[2 * DMODEL + j + 32];
}

// ---------------- flash attention v4: v2 layout + 2 CTAs/SM ----------------
#define BQ 128
#define BKV 32
#define SB 8
#define HB_OFF 1028     // floats: 1024 + 4 (16B skew -> conflict-free dual-broadcast)

__device__ __forceinline__ float ex2(float x) {
    float y;
    asm("ex2.approx.ftz.f32 %0, %1;" : "=f"(y) : "f"(x));
    return y;
}

__global__ __launch_bounds__(256, 2) void flash_kernel()
{
    const int tid = threadIdx.x;
    const int r = tid >> 1;                         // q-row within CTA
    const int half = tid & 1;                       // dim half
    const int qt = (gridDim.x - 1) - blockIdx.x;    // heaviest tiles first
    const int h = blockIdx.y;
    const int b = blockIdx.z;
    const int qi = qt * BQ + r;

    const size_t bh = ((size_t)b * NHEADS + h) * TSEQ * HDIM;

    __shared__ float smK[2 * 1024 + 4];
    __shared__ float smV[2 * 1024 + 4];

    // q half-row in registers (pre-scaled by 1/sqrt(Dh) * log2(e))
    const float pre = 0.125f * 1.4426950408889634f;
    float4 q4[8];
    {
        const float4* qp = (const float4*)(g_q + bh + (size_t)qi * HDIM + half * 32);
        #pragma unroll
        for (int i = 0; i < 8; i++) {
            float4 v = qp[i];
            v.x *= pre; v.y *= pre; v.z *= pre; v.w *= pre;
            q4[i] = v;
        }
    }

    float acc[32];
    #pragma unroll
    for (int d = 0; d < 32; d++) acc[d] = 0.f;
    float m = -INFINITY, l = 0.f;

    const int hoff = half ? HB_OFF : 0;
    const int ntiles = (qt + 1) * (BQ / BKV);

    for (int t0 = 0; t0 < ntiles; t0++) {
        const int j0 = t0 * BKV;
        // cooperative K/V tile load with half-split + 16B skew
        {
            const float4* ksrc = (const float4*)(g_k + bh + (size_t)j0 * HDIM);
            const float4* vsrc = (const float4*)(g_v + bh + (size_t)j0 * HDIM);
            #pragma unroll
            for (int i = 0; i < 2; i++) {
                const int idx = i * 256 + tid;       // 0..511 float4 of 32x64 tile
                const int j = idx >> 4;
                const int c = idx & 15;
                const int dst = (c < 8) ? (j * 32 + c * 4)
                                        : (HB_OFF + j * 32 + (c - 8) * 4);
                *(float4*)&smK[dst] = ksrc[idx];
                *(float4*)&smV[dst] = vsrc[idx];
            }
        }
        __syncthreads();

        if (qi >= j0) {   // warp-uniform (warp rows 16-aligned, j0 multiple of 32)
            #pragma unroll
            for (int sb = 0; sb < BKV / SB; sb++) {
                const int jb = j0 + sb * SB;
                float s[SB];
                float mt = m;
                #pragma unroll
                for (int jj = 0; jj < SB; jj++) {
                    const float4* kr = (const float4*)&smK[hoff + (sb * SB + jj) * 32];
                    float s0 = 0.f, s1 = 0.f, s2 = 0.f, s3 = 0.f;
                    #pragma unroll
                    for (int i = 0; i < 8; i += 4) {
                        float4 k0 = kr[i], k1 = kr[i+1], k2 = kr[i+2], k3 = kr[i+3];
                        s0 = fmaf(q4[i].x,   k0.x, s0); s0 = fmaf(q4[i].y,   k0.y, s0);
                        s0 = fmaf(q4[i].z,   k0.z, s0); s0 = fmaf(q4[i].w,   k0.w, s0);
                        s1 = fmaf(q4[i+1].x, k1.x, s1); s1 = fmaf(q4[i+1].y, k1.y, s1);
                        s1 = fmaf(q4[i+1].z, k1.z, s1); s1 = fmaf(q4[i+1].w, k1.w, s1);
                        s2 = fmaf(q4[i+2].x, k2.x, s2); s2 = fmaf(q4[i+2].y, k2.y, s2);
                        s2 = fmaf(q4[i+2].z, k2.z, s2); s2 = fmaf(q4[i+2].w, k2.w, s2);
                        s3 = fmaf(q4[i+3].x, k3.x, s3); s3 = fmaf(q4[i+3].y, k3.y, s3);
                        s3 = fmaf(q4[i+3].z, k3.z, s3); s3 = fmaf(q4[i+3].w, k3.w, s3);
                    }
                    float part = (s0 + s1) + (s2 + s3);
                    float sj = part + __shfl_xor_sync(0xffffffffu, part, 1);
                    s[jj] = sj;
                    if (jb + jj <= qi) mt = fmaxf(mt, sj);
                }
                const float corr = ex2(m - mt);   // m=-inf first subtile -> 0
                m = mt;
                l *= corr;
                #pragma unroll
                for (int d = 0; d < 32; d++) acc[d] *= corr;

                #pragma unroll
                for (int jj = 0; jj < SB; jj++) {
                    const float p = (jb + jj <= qi) ? ex2(s[jj] - mt) : 0.f;
                    l += p;
                    const float4* vr = (const float4*)&smV[hoff + (sb * SB + jj) * 32];
                    #pragma unroll
                    for (int i = 0; i < 8; i++) {
                        float4 vv = vr[i];
                        acc[4*i + 0] = fmaf(p, vv.x, acc[4*i + 0]);
                        acc[4*i + 1] = fmaf(p, vv.y, acc[4*i + 1]);
                        acc[4*i + 2] = fmaf(p, vv.z, acc[4*i + 2]);
                        acc[4*i + 3] = fmaf(p, vv.w, acc[4*i + 3]);
                    }
                }
            }
        }
        __syncthreads();
    }

    // write O as [B,T,H,Dh] rows for the proj GEMM
    const float inv_l = 1.f / l;
    float* op = g_attn + (((size_t)b * TSEQ + qi) * NHEADS + h) * HDIM + half * 32;
    #pragma unroll
    for (int d = 0; d < 32; d += 4) {
        float4 o;
        o.x = acc[d + 0] * inv_l;
        o.y = acc[d + 1] * inv_l;
        o.z = acc[d + 2] * inv_l;
        o.w = acc[d + 3] * inv_l;
        *(float4*)(op + d) = o;
    }
}

// ---------------- launch ----------------
extern "C" void kernel_launch(void* const* d_in, const int* in_sizes, int n_in,
                              void* d_out, int out_size)
{
    const float* x      = (const float*)d_in[0];
    const float* qkv_w  = (const float*)d_in[1];
    const float* qkv_b  = (const float*)d_in[2];
    const float* proj_w = (const float*)d_in[3];
    const float* proj_b = (const float*)d_in[4];
    float* out = (float*)d_out;

    // 1) QKV = x @ qkv_w^T + qkv_b
    qkv_gemm_kernel<<<dim3(QKV_N / BN, ROWS / BM), 256>>>(x, qkv_w, qkv_b);

    // 2) RoPE cos/sin table
    rope_table_kernel<<<(TSEQ * 32 + 255) / 256, 256>>>();

    // 3) RoPE apply + layout to [B,H,T,Dh]
    rope_apply_kernel<<<(BATCH * TSEQ * NHEADS * 32) / 256, 256>>>();

    // 4) causal flash attention v4
    flash_kernel<<<dim3(TSEQ / BQ, NHEADS, BATCH), 256>>>();

    // 5) out = attn @ proj_w^T + proj_b
    proj_gemm_kernel<<<dim3(DMODEL / BN, ROWS / BM), 256>>>(proj_w, proj_b, out);
}

// round 7
// speedup vs baseline: 1.5998x; 1.5382x over previous
#include <cuda_runtime.h>
#include <math.h>
#include <cstdint>

// Problem constants
#define BATCH 2
#define TSEQ  2048
#define DMODEL 1024
#define NHEADS 16
#define HDIM  64
#define ROWS (BATCH * TSEQ)          // 4096
#define QKV_N (3 * DMODEL)           // 3072

// ---------------- scratch (no allocation allowed) ----------------
__device__ float g_qkv[ROWS * QKV_N];               // [B*T, 3*D]
__device__ float g_q[BATCH * NHEADS * TSEQ * HDIM]; // [B,H,T,Dh]
__device__ float g_k[BATCH * NHEADS * TSEQ * HDIM];
__device__ float g_v[BATCH * NHEADS * TSEQ * HDIM];
__device__ float g_attn[ROWS * DMODEL];             // [B*T, D]
__device__ float g_cs[TSEQ * 32 * 2];               // cos,sin per (t, freq)

// ---------------- tiled fp32 GEMM: C = A[M,K] @ B[N,K]^T + bias ----------------
#define BM 128
#define BN 128
#define BKD 8
#define TM 8
#define TN 8

template<int M, int N, int K>
__device__ __forceinline__ void gemm_body(const float* __restrict__ A,
                                          const float* __restrict__ B,
                                          const float* __restrict__ bias,
                                          float* __restrict__ C)
{
    __shared__ float As[BKD][BM];
    __shared__ float Bs[BKD][BN];

    const int tid = threadIdx.x;           // 256 threads
    const int tx = tid & 15;
    const int ty = tid >> 4;
    const int bm = blockIdx.y * BM;
    const int bn = blockIdx.x * BN;

    const int lrow = tid >> 1;
    const int lk4  = (tid & 1) * 4;

    const float* Aptr = A + (size_t)(bm + lrow) * K + lk4;
    const float* Bptr = B + (size_t)(bn + lrow) * K + lk4;

    float acc[TM][TN];
    #pragma unroll
    for (int m = 0; m < TM; m++)
        #pragma unroll
        for (int n = 0; n < TN; n++)
            acc[m][n] = 0.f;

    for (int k0 = 0; k0 < K; k0 += BKD) {
        float4 av = *(const float4*)(Aptr + k0);
        float4 bv = *(const float4*)(Bptr + k0);
        As[lk4 + 0][lrow] = av.x; As[lk4 + 1][lrow] = av.y;
        As[lk4 + 2][lrow] = av.z; As[lk4 + 3][lrow] = av.w;
        Bs[lk4 + 0][lrow] = bv.x; Bs[lk4 + 1][lrow] = bv.y;
        Bs[lk4 + 2][lrow] = bv.z; Bs[lk4 + 3][lrow] = bv.w;
        __syncthreads();

        #pragma unroll
        for (int k = 0; k < BKD; k++) {
            float ra[TM], rb[TN];
            float4 a0 = *(const float4*)&As[k][ty * TM];
            float4 a1 = *(const float4*)&As[k][ty * TM + 4];
            ra[0]=a0.x; ra[1]=a0.y; ra[2]=a0.z; ra[3]=a0.w;
            ra[4]=a1.x; ra[5]=a1.y; ra[6]=a1.z; ra[7]=a1.w;
            float4 b0 = *(const float4*)&Bs[k][tx * TN];
            float4 b1 = *(const float4*)&Bs[k][tx * TN + 4];
            rb[0]=b0.x; rb[1]=b0.y; rb[2]=b0.z; rb[3]=b0.w;
            rb[4]=b1.x; rb[5]=b1.y; rb[6]=b1.z; rb[7]=b1.w;
            #pragma unroll
            for (int m = 0; m < TM; m++)
                #pragma unroll
                for (int n = 0; n < TN; n++)
                    acc[m][n] = fmaf(ra[m], rb[n], acc[m][n]);
        }
        __syncthreads();
    }

    #pragma unroll
    for (int m = 0; m < TM; m++) {
        const int row = bm + ty * TM + m;
        float* cp = C + (size_t)row * N + bn + tx * TN;
        const float* bp = bias + bn + tx * TN;
        #pragma unroll
        for (int n = 0; n < TN; n += 4) {
            float4 o;
            o.x = acc[m][n + 0] + bp[n + 0];
            o.y = acc[m][n + 1] + bp[n + 1];
            o.z = acc[m][n + 2] + bp[n + 2];
            o.w = acc[m][n + 3] + bp[n + 3];
            *(float4*)(cp + n) = o;
        }
    }
}

__global__ __launch_bounds__(256) void qkv_gemm_kernel(const float* __restrict__ x,
                                                       const float* __restrict__ w,
                                                       const float* __restrict__ b)
{
    gemm_body<ROWS, QKV_N, DMODEL>(x, w, b, g_qkv);
}

__global__ __launch_bounds__(256) void proj_gemm_kernel(const float* __restrict__ w,
                                                        const float* __restrict__ b,
                                                        float* __restrict__ out)
{
    gemm_body<ROWS, DMODEL, DMODEL>(g_attn, w, b, out);
}

// ---------------- RoPE table ----------------
__global__ void rope_table_kernel()
{
    int idx = blockIdx.x * blockDim.x + threadIdx.x;
    if (idx >= TSEQ * 32) return;
    int t = idx >> 5;
    int j = idx & 31;
    float invf = powf(10000.0f, -((float)(2 * j) / 64.0f));
    float angle = (float)t * invf;
    double a = (double)angle;
    double s, c;
    sincos(a, &s, &c);
    g_cs[idx * 2 + 0] = (float)c;
    g_cs[idx * 2 + 1] = (float)s;
}

// ---------------- RoPE apply + transpose to [B,H,T,Dh] ----------------
__global__ void rope_apply_kernel()
{
    int idx = blockIdx.x * blockDim.x + threadIdx.x;
    if (idx >= BATCH * TSEQ * NHEADS * 32) return;
    int j = idx & 31;
    int h = (idx >> 5) & (NHEADS - 1);
    int t = (idx >> 9) & (TSEQ - 1);
    int b = idx >> 20;

    int row = b * TSEQ + t;
    const float* base = g_qkv + (size_t)row * QKV_N + h * HDIM;

    float c  = g_cs[(t * 32 + j) * 2 + 0];
    float sn = g_cs[(t * 32 + j) * 2 + 1];

    float q1 = base[j],          q2 = base[j + 32];
    float k1 = base[DMODEL + j], k2 = base[DMODEL + j + 32];

    size_t od = (((size_t)b * NHEADS + h) * TSEQ + t) * HDIM;
    g_q[od + j]      = q1 * c - q2 * sn;
    g_q[od + j + 32] = q2 * c + q1 * sn;
    g_k[od + j]      = k1 * c - k2 * sn;
    g_k[od + j + 32] = k2 * c + k1 * sn;
    g_v[od + j]      = base[2 * DMODEL + j];
    g_v[od + j + 32] = base[2 * DMODEL + j + 32];
}

// ================= flash attention v5: tf32 mma.sync (FA-2 style) =================
// CTA: 128 q-rows, 256 threads = 8 warps, each warp m16 rows. 32-key tiles.
// Q fragments register-resident; K/V staged in smem pre-converted to tf32.
// S/P/O kept in mma fragments; softmax via quad shuffles.
#define FBQ 128
#define FBKV 32
#define KSTR 68      // Ks row stride (floats): QK B-frag reads conflict-free
#define VSTR 72      // Vs row stride (floats): PV B-frag reads conflict-free

__device__ __forceinline__ float ex2(float x) {
    float y;
    asm("ex2.approx.ftz.f32 %0, %1;" : "=f"(y) : "f"(x));
    return y;
}
__device__ __forceinline__ uint32_t f2tf32(float f) {
    uint32_t r;
    asm("cvt.rna.tf32.f32 %0, %1;" : "=r"(r) : "f"(f));
    return r;
}
__device__ __forceinline__ void mma8(float* d, const uint32_t* a, uint32_t b0, uint32_t b1) {
    asm volatile(
        "mma.sync.aligned.m16n8k8.row.col.f32.tf32.tf32.f32 "
        "{%0,%1,%2,%3}, {%4,%5,%6,%7}, {%8,%9}, {%0,%1,%2,%3};"
        : "+f"(d[0]), "+f"(d[1]), "+f"(d[2]), "+f"(d[3])
        : "r"(a[0]), "r"(a[1]), "r"(a[2]), "r"(a[3]), "r"(b0), "r"(b1));
}

__global__ __launch_bounds__(256, 2) void flash_mma_kernel()
{
    const int tid  = threadIdx.x;
    const int w    = tid >> 5;
    const int lane = tid & 31;
    const int g    = lane >> 2;    // 0..7
    const int tg   = lane & 3;     // 0..3
    const int qt = (gridDim.x - 1) - blockIdx.x;   // heaviest tiles first
    const int h  = blockIdx.y;
    const int b  = blockIdx.z;
    const int qb = qt * FBQ;
    const int wb = qb + w * 16;        // warp's first row
    const int rA = wb + g;             // fragment row (lower 8)
    const int rB = rA + 8;             // fragment row (upper 8)

    const size_t bh = ((size_t)b * NHEADS + h) * TSEQ * HDIM;
    const float NEG = __int_as_float(0xff800000);   // -inf

    __shared__ float Ks[FBKV * KSTR];
    __shared__ float Vs[FBKV * VSTR];

    // ---- Q fragments (tf32, prescaled by 1/sqrt(Dh)*log2e), resident all kernel ----
    const float pre = 0.125f * 1.4426950408889634f;
    uint32_t qf[8][4];
    {
        const float* q0 = g_q + bh + (size_t)rA * HDIM;
        const float* q1 = g_q + bh + (size_t)rB * HDIM;
        #pragma unroll
        for (int kc = 0; kc < 8; kc++) {
            qf[kc][0] = f2tf32(q0[kc * 8 + tg]     * pre);
            qf[kc][1] = f2tf32(q1[kc * 8 + tg]     * pre);
            qf[kc][2] = f2tf32(q0[kc * 8 + tg + 4] * pre);
            qf[kc][3] = f2tf32(q1[kc * 8 + tg + 4] * pre);
        }
    }

    float o[8][4];                     // O fragments over 8 n-tiles of Dh
    #pragma unroll
    for (int n = 0; n < 8; n++)
        #pragma unroll
        for (int j = 0; j < 4; j++) o[n][j] = 0.f;
    float mA = NEG, mB = NEG, lA = 0.f, lB = 0.f;

    const int ntiles = qb / FBKV + 4;  // keys 0 .. qb+127
    for (int t0 = 0; t0 < ntiles; t0++) {
        const int j0 = t0 * FBKV;

        // ---- cooperative K/V tile load, converting to tf32 in smem ----
        {
            const float4* ksrc = (const float4*)(g_k + bh + (size_t)j0 * HDIM);
            const float4* vsrc = (const float4*)(g_v + bh + (size_t)j0 * HDIM);
            #pragma unroll
            for (int i = 0; i < 2; i++) {
                const int idx = i * 256 + tid;      // 0..511 float4 of 32x64 tile
                const int key = idx >> 4;
                const int c   = idx & 15;
                float4 kv = ksrc[idx];
                uint4 kt;
                kt.x = f2tf32(kv.x); kt.y = f2tf32(kv.y);
                kt.z = f2tf32(kv.z); kt.w = f2tf32(kv.w);
                *(uint4*)&Ks[key * KSTR + c * 4] = kt;
                kv = vsrc[idx];
                kt.x = f2tf32(kv.x); kt.y = f2tf32(kv.y);
                kt.z = f2tf32(kv.z); kt.w = f2tf32(kv.w);
                *(uint4*)&Vs[key * VSTR + c * 4] = kt;
            }
        }
        __syncthreads();

        if (j0 <= wb) {                // warp has unmasked keys in this tile
            // ---- S = Q @ K^T : 4 n-tiles x 8 k-chunks ----
            float s[4][4];
            #pragma unroll
            for (int nt = 0; nt < 4; nt++) {
                s[nt][0] = 0.f; s[nt][1] = 0.f; s[nt][2] = 0.f; s[nt][3] = 0.f;
                #pragma unroll
                for (int kc = 0; kc < 8; kc++) {
                    uint32_t b0 = *(const uint32_t*)&Ks[(nt * 8 + g) * KSTR + kc * 8 + tg];
                    uint32_t b1 = *(const uint32_t*)&Ks[(nt * 8 + g) * KSTR + kc * 8 + tg + 4];
                    mma8(s[nt], qf[kc], b0, b1);
                }
            }

            // ---- causal mask + row max (rows rA, rB; cols j0+nt*8+2tg+{0,1}) ----
            float mtA = mA, mtB = mB;
            #pragma unroll
            for (int nt = 0; nt < 4; nt++) {
                const int jc = j0 + nt * 8 + 2 * tg;
                s[nt][0] = (jc     <= rA) ? s[nt][0] : NEG;
                s[nt][1] = (jc + 1 <= rA) ? s[nt][1] : NEG;
                s[nt][2] = (jc     <= rB) ? s[nt][2] : NEG;
                s[nt][3] = (jc + 1 <= rB) ? s[nt][3] : NEG;
                mtA = fmaxf(mtA, fmaxf(s[nt][0], s[nt][1]));
                mtB = fmaxf(mtB, fmaxf(s[nt][2], s[nt][3]));
            }
            mtA = fmaxf(mtA, __shfl_xor_sync(0xffffffffu, mtA, 1));
            mtA = fmaxf(mtA, __shfl_xor_sync(0xffffffffu, mtA, 2));
            mtB = fmaxf(mtB, __shfl_xor_sync(0xffffffffu, mtB, 1));
            mtB = fmaxf(mtB, __shfl_xor_sync(0xffffffffu, mtB, 2));

            const float corrA = ex2(mA - mtA);   // first tile: -inf -> 0
            const float corrB = ex2(mB - mtB);
            mA = mtA; mB = mtB;

            // ---- P = exp2(S - m) (tf32), row sums ----
            uint32_t pf[4][4];
            float sumA = 0.f, sumB = 0.f;
            #pragma unroll
            for (int nt = 0; nt < 4; nt++) {
                pf[nt][0] = f2tf32(ex2(s[nt][0] - mtA));
                pf[nt][1] = f2tf32(ex2(s[nt][1] - mtA));
                pf[nt][2] = f2tf32(ex2(s[nt][2] - mtB));
                pf[nt][3] = f2tf32(ex2(s[nt][3] - mtB));
                sumA += __uint_as_float(pf[nt][0]) + __uint_as_float(pf[nt][1]);
                sumB += __uint_as_float(pf[nt][2]) + __uint_as_float(pf[nt][3]);
            }
            sumA += __shfl_xor_sync(0xffffffffu, sumA, 1);
            sumA += __shfl_xor_sync(0xffffffffu, sumA, 2);
            sumB += __shfl_xor_sync(0xffffffffu, sumB, 1);
            sumB += __shfl_xor_sync(0xffffffffu, sumB, 2);
            lA = lA * corrA + sumA;
            lB = lB * corrB + sumB;

            // ---- rescale O ----
            #pragma unroll
            for (int n = 0; n < 8; n++) {
                o[n][0] *= corrA; o[n][1] *= corrA;
                o[n][2] *= corrB; o[n][3] *= corrB;
            }

            // ---- O += P @ V : remap P C-layout -> A-layout via quad shuffles ----
            const int srcL = tg >> 1;
            #pragma unroll
            for (int kc = 0; kc < 4; kc++) {
                uint32_t v0 = __shfl_sync(0xffffffffu, pf[kc][0], srcL, 4);
                uint32_t v1 = __shfl_sync(0xffffffffu, pf[kc][1], srcL, 4);
                uint32_t v2 = __shfl_sync(0xffffffffu, pf[kc][0], srcL + 2, 4);
                uint32_t v3 = __shfl_sync(0xffffffffu, pf[kc][1], srcL + 2, 4);
                uint32_t u0 = __shfl_sync(0xffffffffu, pf[kc][2], srcL, 4);
                uint32_t u1 = __shfl_sync(0xffffffffu, pf[kc][3], srcL, 4);
                uint32_t u2 = __shfl_sync(0xffffffffu, pf[kc][2], srcL + 2, 4);
                uint32_t u3 = __shfl_sync(0xffffffffu, pf[kc][3], srcL + 2, 4);
                uint32_t af[4];
                af[0] = (tg & 1) ? v1 : v0;   // P[rA][kc*8+tg]
                af[1] = (tg & 1) ? u1 : u0;   // P[rB][kc*8+tg]
                af[2] = (tg & 1) ? v3 : v2;   // P[rA][kc*8+tg+4]
                af[3] = (tg & 1) ? u3 : u2;   // P[rB][kc*8+tg+4]
                #pragma unroll
                for (int nt2 = 0; nt2 < 8; nt2++) {
                    uint32_t b0 = *(const uint32_t*)&Vs[(kc * 8 + tg) * VSTR + nt2 * 8 + g];
                    uint32_t b1 = *(const uint32_t*)&Vs[(kc * 8 + tg + 4) * VSTR + nt2 * 8 + g];
                    mma8(o[nt2], af, b0, b1);
                }
            }
        }
        __syncthreads();
    }

    // ---- epilogue: O / l, write as [B,T,H,Dh] rows ----
    const float iA = 1.f / lA;
    const float iB = 1.f / lB;
    float* opA = g_attn + (((size_t)b * TSEQ + rA) * NHEADS + h) * HDIM;
    float* opB = g_attn + (((size_t)b * TSEQ + rB) * NHEADS + h) * HDIM;
    #pragma unroll
    for (int nt2 = 0; nt2 < 8; nt2++) {
        const int cc = nt2 * 8 + 2 * tg;
        *(float2*)(opA + cc) = make_float2(o[nt2][0] * iA, o[nt2][1] * iA);
        *(float2*)(opB + cc) = make_float2(o[nt2][2] * iB, o[nt2][3] * iB);
    }
}

// ---------------- launch ----------------
extern "C" void kernel_launch(void* const* d_in, const int* in_sizes, int n_in,
                              void* d_out, int out_size)
{
    const float* x      = (const float*)d_in[0];
    const float* qkv_w  = (const float*)d_in[1];
    const float* qkv_b  = (const float*)d_in[2];
    const float* proj_w = (const float*)d_in[3];
    const float* proj_b = (const float*)d_in[4];
    float* out = (float*)d_out;

    // 1) QKV = x @ qkv_w^T + qkv_b
    qkv_gemm_kernel<<<dim3(QKV_N / BN, ROWS / BM), 256>>>(x, qkv_w, qkv_b);

    // 2) RoPE cos/sin table
    rope_table_kernel<<<(TSEQ * 32 + 255) / 256, 256>>>();

    // 3) RoPE apply + layout to [B,H,T,Dh]
    rope_apply_kernel<<<(BATCH * TSEQ * NHEADS * 32) / 256, 256>>>();

    // 4) causal flash attention v5 (tf32 mma.sync)
    flash_mma_kernel<<<dim3(TSEQ / FBQ, NHEADS, BATCH), 256>>>();

    // 5) out = attn @ proj_w^T + proj_b
    proj_gemm_kernel<<<dim3(DMODEL / BN, ROWS / BM), 256>>>(proj_w, proj_b, out);
}

// round 8
// speedup vs baseline: 3.1551x; 1.9721x over previous
#include <cuda_runtime.h>
#include <math.h>
#include <cstdint>

// Problem constants
#define BATCH 2
#define TSEQ  2048
#define DMODEL 1024
#define NHEADS 16
#define HDIM  64
#define ROWS (BATCH * TSEQ)          // 4096
#define QKV_N (3 * DMODEL)           // 3072

// ---------------- scratch (no allocation allowed) ----------------
__device__ float g_qkv[ROWS * QKV_N];               // [B*T, 3*D]
__device__ float g_q[BATCH * NHEADS * TSEQ * HDIM]; // [B,H,T,Dh]
__device__ float g_k[BATCH * NHEADS * TSEQ * HDIM];
__device__ float g_v[BATCH * NHEADS * TSEQ * HDIM];
__device__ float g_attn[ROWS * DMODEL];             // [B*T, D]
__device__ float g_cs[TSEQ * 32 * 2];               // cos,sin per (t, freq)
// tf32 column-permuted operands for the GEMMs
__device__ uint32_t g_xt[ROWS * DMODEL];
__device__ uint32_t g_wqkvt[QKV_N * DMODEL];
__device__ uint32_t g_wprojt[DMODEL * DMODEL];
__device__ uint32_t g_attnt[ROWS * DMODEL];

// ================= helpers =================
__device__ __forceinline__ uint32_t s2u(const void* p) {
    uint32_t a;
    asm("{ .reg .u64 t; cvta.to.shared.u64 t, %1; cvt.u32.u64 %0, t; }"
        : "=r"(a) : "l"(p));
    return a;
}
__device__ __forceinline__ uint32_t f2tf32(float f) {
    uint32_t r;
    asm("cvt.rna.tf32.f32 %0, %1;" : "=r"(r) : "f"(f));
    return r;
}
__device__ __forceinline__ float ex2(float x) {
    float y;
    asm("ex2.approx.ftz.f32 %0, %1;" : "=f"(y) : "f"(x));
    return y;
}
__device__ __forceinline__ void cp16(uint32_t dst, const void* src) {
    asm volatile("cp.async.cg.shared.global [%0], [%1], 16;" :: "r"(dst), "l"(src));
}
__device__ __forceinline__ void mma8(float* d, const uint32_t* a, uint32_t b0, uint32_t b1) {
    asm volatile(
        "mma.sync.aligned.m16n8k8.row.col.f32.tf32.tf32.f32 "
        "{%0,%1,%2,%3}, {%4,%5,%6,%7}, {%8,%9}, {%0,%1,%2,%3};"
        : "+f"(d[0]), "+f"(d[1]), "+f"(d[2]), "+f"(d[3])
        : "r"(a[0]), "r"(a[1]), "r"(a[2]), "r"(a[3]), "r"(b0), "r"(b1));
}

// ---------------- convert f32 -> tf32 with per-32-block column permutation -----------
// dst position p within each 32-block holds orig col c = (p&7)*4 + (p>>3)
__global__ void convert_permute_kernel(const float* __restrict__ src,
                                       uint32_t* __restrict__ dst, int n)
{
    int idx = blockIdx.x * blockDim.x + threadIdx.x;
    if (idx >= n) return;
    int p = idx & 31;
    int c = (p & 7) * 4 + (p >> 3);
    int base = idx & ~31;
    dst[idx] = f2tf32(src[base + c]);
}

// ================= tf32 mma GEMM: C[M,NCOLS] = A[M,1024] @ W[NCOLS,1024]^T + bias ======
// Inputs pre-converted tf32 + column-permuted. CTA 128x128, 8 warps (4m x 2n),
// warp tile 32x64, K-chunk 32 double-buffered via cp.async.
// smem: row stride 36 words, 16B chunks XOR-swizzled by q ^= 2*(row&3).
#define GSTR 36
#define GTILEW (128 * GSTR)
#define GEMM_SMEM_B (2 * 2 * GTILEW * 4)   // 73728 bytes

template<int NCOLS>
__global__ __launch_bounds__(256) void tf32_gemm_kernel(
    const uint32_t* __restrict__ A,
    const uint32_t* __restrict__ W,
    const float* __restrict__ bias,
    float* __restrict__ C)
{
    extern __shared__ uint32_t smw[];
    const int tid = threadIdx.x;
    const int wid = tid >> 5, lane = tid & 31;
    const int g = lane >> 2, tg = lane & 3;
    const int wm = wid & 3, wn = wid >> 2;
    const int bm = blockIdx.y * 128, bn = blockIdx.x * 128;

    float acc[2][8][4];
    #pragma unroll
    for (int t = 0; t < 2; t++)
        #pragma unroll
        for (int nt = 0; nt < 8; nt++)
            #pragma unroll
            for (int j = 0; j < 4; j++) acc[t][nt][j] = 0.f;

    // fragment float4 base offset within a row (swizzle uses row&3 == g&3)
    const int fo = 8 * (tg ^ (g & 3));

    // ---- tile loader: chunk c (32 cols) into stage s ----
    #define LOAD_CHUNK(c, s) do {                                                  \
        uint32_t* as_ = smw + (s) * 2 * GTILEW;                                    \
        uint32_t* bs_ = as_ + GTILEW;                                              \
        _Pragma("unroll")                                                          \
        for (int i_ = 0; i_ < 4; i_++) {                                           \
            int idx_ = i_ * 256 + tid;                                             \
            int row_ = idx_ >> 3, q_ = idx_ & 7;                                   \
            int sq_ = q_ ^ ((row_ & 3) << 1);                                      \
            cp16(s2u(as_ + row_ * GSTR + sq_ * 4),                                 \
                 A + (size_t)(bm + row_) * DMODEL + (c) * 32 + q_ * 4);            \
            cp16(s2u(bs_ + row_ * GSTR + sq_ * 4),                                 \
                 W + (size_t)(bn + row_) * DMODEL + (c) * 32 + q_ * 4);            \
        }                                                                          \
        asm volatile("cp.async.commit_group;" ::: "memory");                       \
    } while (0)

    LOAD_CHUNK(0, 0);

    for (int c = 0; c < DMODEL / 32; c++) {
        const int st = c & 1;
        if (c + 1 < DMODEL / 32) {
            LOAD_CHUNK(c + 1, (c + 1) & 1);
            asm volatile("cp.async.wait_group 1;" ::: "memory");
        } else {
            asm volatile("cp.async.wait_group 0;" ::: "memory");
        }
        __syncthreads();

        const uint32_t* as = smw + st * 2 * GTILEW;
        const uint32_t* bs = as + GTILEW;

        // A fragments: 2 m16-tiles x 4 kc x 4 regs (8 LDS.128)
        uint32_t a[2][4][4];
        #pragma unroll
        for (int t = 0; t < 2; t++) {
            const int r0 = wm * 32 + t * 16 + g;
            const int r1 = r0 + 8;
            uint4 x0 = *(const uint4*)(as + r0 * GSTR + fo);
            uint4 x1 = *(const uint4*)(as + r0 * GSTR + fo + 4);
            uint4 y0 = *(const uint4*)(as + r1 * GSTR + fo);
            uint4 y1 = *(const uint4*)(as + r1 * GSTR + fo + 4);
            a[t][0][0]=x0.x; a[t][0][1]=y0.x; a[t][0][2]=x0.y; a[t][0][3]=y0.y;
            a[t][1][0]=x0.z; a[t][1][1]=y0.z; a[t][1][2]=x0.w; a[t][1][3]=y0.w;
            a[t][2][0]=x1.x; a[t][2][1]=y1.x; a[t][2][2]=x1.y; a[t][2][3]=y1.y;
            a[t][3][0]=x1.z; a[t][3][1]=y1.z; a[t][3][2]=x1.w; a[t][3][3]=y1.w;
        }

        // B fragments + MMAs per n-tile (16 LDS.128, 64 HMMA)
        #pragma unroll
        for (int nt = 0; nt < 8; nt++) {
            const int rn = wn * 64 + nt * 8 + g;
            uint4 b0 = *(const uint4*)(bs + rn * GSTR + fo);
            uint4 b1 = *(const uint4*)(bs + rn * GSTR + fo + 4);
            #pragma unroll
            for (int t = 0; t < 2; t++) {
                mma8(acc[t][nt], a[t][0], b0.x, b0.y);
                mma8(acc[t][nt], a[t][1], b0.z, b0.w);
                mma8(acc[t][nt], a[t][2], b1.x, b1.y);
                mma8(acc[t][nt], a[t][3], b1.z, b1.w);
            }
        }
        __syncthreads();
    }
    #undef LOAD_CHUNK

    // epilogue: + bias, write float2 pairs
    #pragma unroll
    for (int t = 0; t < 2; t++) {
        const int r0 = bm + wm * 32 + t * 16 + g;
        #pragma unroll
        for (int nt = 0; nt < 8; nt++) {
            const int cc = bn + wn * 64 + nt * 8 + 2 * tg;
            const float b0 = bias[cc], b1 = bias[cc + 1];
            *(float2*)(C + (size_t)r0 * NCOLS + cc) =
                make_float2(acc[t][nt][0] + b0, acc[t][nt][1] + b1);
            *(float2*)(C + (size_t)(r0 + 8) * NCOLS + cc) =
                make_float2(acc[t][nt][2] + b0, acc[t][nt][3] + b1);
        }
    }
}

// ---------------- RoPE table ----------------
__global__ void rope_table_kernel()
{
    int idx = blockIdx.x * blockDim.x + threadIdx.x;
    if (idx >= TSEQ * 32) return;
    int t = idx >> 5;
    int j = idx & 31;
    float invf = powf(10000.0f, -((float)(2 * j) / 64.0f));
    float angle = (float)t * invf;
    double a = (double)angle;
    double s, c;
    sincos(a, &s, &c);
    g_cs[idx * 2 + 0] = (float)c;
    g_cs[idx * 2 + 1] = (float)s;
}

// ---------------- RoPE apply + transpose to [B,H,T,Dh] ----------------
__global__ void rope_apply_kernel()
{
    int idx = blockIdx.x * blockDim.x + threadIdx.x;
    if (idx >= BATCH * TSEQ * NHEADS * 32) return;
    int j = idx & 31;
    int h = (idx >> 5) & (NHEADS - 1);
    int t = (idx >> 9) & (TSEQ - 1);
    int b = idx >> 20;

    int row = b * TSEQ + t;
    const float* base = g_qkv + (size_t)row * QKV_N + h * HDIM;

    float c  = g_cs[(t * 32 + j) * 2 + 0];
    float sn = g_cs[(t * 32 + j) * 2 + 1];

    float q1 = base[j],          q2 = base[j + 32];
    float k1 = base[DMODEL + j], k2 = base[DMODEL + j + 32];

    size_t od = (((size_t)b * NHEADS + h) * TSEQ + t) * HDIM;
    g_q[od + j]      = q1 * c - q2 * sn;
    g_q[od + j + 32] = q2 * c + q1 * sn;
    g_k[od + j]      = k1 * c - k2 * sn;
    g_k[od + j + 32] = k2 * c + k1 * sn;
    g_v[od + j]      = base[2 * DMODEL + j];
    g_v[od + j + 32] = base[2 * DMODEL + j + 32];
}

// ================= flash attention v5: tf32 mma.sync (FA-2 style) =================
#define FBQ 128
#define FBKV 32
#define KSTR 68
#define VSTR 72

__global__ __launch_bounds__(256, 2) void flash_mma_kernel()
{
    const int tid  = threadIdx.x;
    const int w    = tid >> 5;
    const int lane = tid & 31;
    const int g    = lane >> 2;
    const int tg   = lane & 3;
    const int qt = (gridDim.x - 1) - blockIdx.x;
    const int h  = blockIdx.y;
    const int b  = blockIdx.z;
    const int qb = qt * FBQ;
    const int wb = qb + w * 16;
    const int rA = wb + g;
    const int rB = rA + 8;

    const size_t bh = ((size_t)b * NHEADS + h) * TSEQ * HDIM;
    const float NEG = __int_as_float(0xff800000);

    __shared__ float Ks[FBKV * KSTR];
    __shared__ float Vs[FBKV * VSTR];

    const float pre = 0.125f * 1.4426950408889634f;
    uint32_t qf[8][4];
    {
        const float* q0 = g_q + bh + (size_t)rA * HDIM;
        const float* q1 = g_q + bh + (size_t)rB * HDIM;
        #pragma unroll
        for (int kc = 0; kc < 8; kc++) {
            qf[kc][0] = f2tf32(q0[kc * 8 + tg]     * pre);
            qf[kc][1] = f2tf32(q1[kc * 8 + tg]     * pre);
            qf[kc][2] = f2tf32(q0[kc * 8 + tg + 4] * pre);
            qf[kc][3] = f2tf32(q1[kc * 8 + tg + 4] * pre);
        }
    }

    float o[8][4];
    #pragma unroll
    for (int n = 0; n < 8; n++)
        #pragma unroll
        for (int j = 0; j < 4; j++) o[n][j] = 0.f;
    float mA = NEG, mB = NEG, lA = 0.f, lB = 0.f;

    const int ntiles = qb / FBKV + 4;
    for (int t0 = 0; t0 < ntiles; t0++) {
        const int j0 = t0 * FBKV;

        {
            const float4* ksrc = (const float4*)(g_k + bh + (size_t)j0 * HDIM);
            const float4* vsrc = (const float4*)(g_v + bh + (size_t)j0 * HDIM);
            #pragma unroll
            for (int i = 0; i < 2; i++) {
                const int idx = i * 256 + tid;
                const int key = idx >> 4;
                const int c   = idx & 15;
                float4 kv = ksrc[idx];
                uint4 kt;
                kt.x = f2tf32(kv.x); kt.y = f2tf32(kv.y);
                kt.z = f2tf32(kv.z); kt.w = f2tf32(kv.w);
                *(uint4*)&Ks[key * KSTR + c * 4] = kt;
                kv = vsrc[idx];
                kt.x = f2tf32(kv.x); kt.y = f2tf32(kv.y);
                kt.z = f2tf32(kv.z); kt.w = f2tf32(kv.w);
                *(uint4*)&Vs[key * VSTR + c * 4] = kt;
            }
        }
        __syncthreads();

        if (j0 <= wb) {
            float s[4][4];
            #pragma unroll
            for (int nt = 0; nt < 4; nt++) {
                s[nt][0] = 0.f; s[nt][1] = 0.f; s[nt][2] = 0.f; s[nt][3] = 0.f;
                #pragma unroll
                for (int kc = 0; kc < 8; kc++) {
                    uint32_t b0 = *(const uint32_t*)&Ks[(nt * 8 + g) * KSTR + kc * 8 + tg];
                    uint32_t b1 = *(const uint32_t*)&Ks[(nt * 8 + g) * KSTR + kc * 8 + tg + 4];
                    mma8(s[nt], qf[kc], b0, b1);
                }
            }

            float mtA = mA, mtB = mB;
            #pragma unroll
            for (int nt = 0; nt < 4; nt++) {
                const int jc = j0 + nt * 8 + 2 * tg;
                s[nt][0] = (jc     <= rA) ? s[nt][0] : NEG;
                s[nt][1] = (jc + 1 <= rA) ? s[nt][1] : NEG;
                s[nt][2] = (jc     <= rB) ? s[nt][2] : NEG;
                s[nt][3] = (jc + 1 <= rB) ? s[nt][3] : NEG;
                mtA = fmaxf(mtA, fmaxf(s[nt][0], s[nt][1]));
                mtB = fmaxf(mtB, fmaxf(s[nt][2], s[nt][3]));
            }
            mtA = fmaxf(mtA, __shfl_xor_sync(0xffffffffu, mtA, 1));
            mtA = fmaxf(mtA, __shfl_xor_sync(0xffffffffu, mtA, 2));
            mtB = fmaxf(mtB, __shfl_xor_sync(0xffffffffu, mtB, 1));
            mtB = fmaxf(mtB, __shfl_xor_sync(0xffffffffu, mtB, 2));

            const float corrA = ex2(mA - mtA);
            const float corrB = ex2(mB - mtB);
            mA = mtA; mB = mtB;

            uint32_t pf[4][4];
            float sumA = 0.f, sumB = 0.f;
            #pragma unroll
            for (int nt = 0; nt < 4; nt++) {
                pf[nt][0] = f2tf32(ex2(s[nt][0] - mtA));
                pf[nt][1] = f2tf32(ex2(s[nt][1] - mtA));
                pf[nt][2] = f2tf32(ex2(s[nt][2] - mtB));
                pf[nt][3] = f2tf32(ex2(s[nt][3] - mtB));
                sumA += __uint_as_float(pf[nt][0]) + __uint_as_float(pf[nt][1]);
                sumB += __uint_as_float(pf[nt][2]) + __uint_as_float(pf[nt][3]);
            }
            sumA += __shfl_xor_sync(0xffffffffu, sumA, 1);
            sumA += __shfl_xor_sync(0xffffffffu, sumA, 2);
            sumB += __shfl_xor_sync(0xffffffffu, sumB, 1);
            sumB += __shfl_xor_sync(0xffffffffu, sumB, 2);
            lA = lA * corrA + sumA;
            lB = lB * corrB + sumB;

            #pragma unroll
            for (int n = 0; n < 8; n++) {
                o[n][0] *= corrA; o[n][1] *= corrA;
                o[n][2] *= corrB; o[n][3] *= corrB;
            }

            const int srcL = tg >> 1;
            #pragma unroll
            for (int kc = 0; kc < 4; kc++) {
                uint32_t v0 = __shfl_sync(0xffffffffu, pf[kc][0], srcL, 4);
                uint32_t v1 = __shfl_sync(0xffffffffu, pf[kc][1], srcL, 4);
                uint32_t v2 = __shfl_sync(0xffffffffu, pf[kc][0], srcL + 2, 4);
                uint32_t v3 = __shfl_sync(0xffffffffu, pf[kc][1], srcL + 2, 4);
                uint32_t u0 = __shfl_sync(0xffffffffu, pf[kc][2], srcL, 4);
                uint32_t u1 = __shfl_sync(0xffffffffu, pf[kc][3], srcL, 4);
                uint32_t u2 = __shfl_sync(0xffffffffu, pf[kc][2], srcL + 2, 4);
                uint32_t u3 = __shfl_sync(0xffffffffu, pf[kc][3], srcL + 2, 4);
                uint32_t af[4];
                af[0] = (tg & 1) ? v1 : v0;
                af[1] = (tg & 1) ? u1 : u0;
                af[2] = (tg & 1) ? v3 : v2;
                af[3] = (tg & 1) ? u3 : u2;
                #pragma unroll
                for (int nt2 = 0; nt2 < 8; nt2++) {
                    uint32_t b0 = *(const uint32_t*)&Vs[(kc * 8 + tg) * VSTR + nt2 * 8 + g];
                    uint32_t b1 = *(const uint32_t*)&Vs[(kc * 8 + tg + 4) * VSTR + nt2 * 8 + g];
                    mma8(o[nt2], af, b0, b1);
                }
            }
        }
        __syncthreads();
    }

    const float iA = 1.f / lA;
    const float iB = 1.f / lB;
    float* opA = g_attn + (((size_t)b * TSEQ + rA) * NHEADS + h) * HDIM;
    float* opB = g_attn + (((size_t)b * TSEQ + rB) * NHEADS + h) * HDIM;
    #pragma unroll
    for (int nt2 = 0; nt2 < 8; nt2++) {
        const int cc = nt2 * 8 + 2 * tg;
        *(float2*)(opA + cc) = make_float2(o[nt2][0] * iA, o[nt2][1] * iA);
        *(float2*)(opB + cc) = make_float2(o[nt2][2] * iB, o[nt2][3] * iB);
    }
}

// ---------------- launch ----------------
extern "C" void kernel_launch(void* const* d_in, const int* in_sizes, int n_in,
                              void* d_out, int out_size)
{
    const float* x      = (const float*)d_in[0];
    const float* qkv_w  = (const float*)d_in[1];
    const float* qkv_b  = (const float*)d_in[2];
    const float* proj_w = (const float*)d_in[3];
    const float* proj_b = (const float*)d_in[4];
    float* out = (float*)d_out;

    cudaFuncSetAttribute(tf32_gemm_kernel<QKV_N>,
                         cudaFuncAttributeMaxDynamicSharedMemorySize, GEMM_SMEM_B);
    cudaFuncSetAttribute(tf32_gemm_kernel<DMODEL>,
                         cudaFuncAttributeMaxDynamicSharedMemorySize, GEMM_SMEM_B);

    uint32_t *d_xt, *d_wqkvt, *d_wprojt, *d_attnt;
    float *d_qkv, *d_attn;
    cudaGetSymbolAddress((void**)&d_xt, g_xt);
    cudaGetSymbolAddress((void**)&d_wqkvt, g_wqkvt);
    cudaGetSymbolAddress((void**)&d_wprojt, g_wprojt);
    cudaGetSymbolAddress((void**)&d_attnt, g_attnt);
    cudaGetSymbolAddress((void**)&d_qkv, g_qkv);
    cudaGetSymbolAddress((void**)&d_attn, g_attn);

    // 0) convert+permute GEMM operands to tf32
    convert_permute_kernel<<<(ROWS * DMODEL) / 256, 256>>>(x, d_xt, ROWS * DMODEL);
    convert_permute_kernel<<<(QKV_N * DMODEL) / 256, 256>>>(qkv_w, d_wqkvt, QKV_N * DMODEL);
    convert_permute_kernel<<<(DMODEL * DMODEL) / 256, 256>>>(proj_w, d_wprojt, DMODEL * DMODEL);

    // 1) QKV = x @ qkv_w^T + qkv_b  (tf32 mma)
    tf32_gemm_kernel<QKV_N><<<dim3(QKV_N / 128, ROWS / 128), 256, GEMM_SMEM_B>>>(
        d_xt, d_wqkvt, qkv_b, d_qkv);

    // 2) RoPE cos/sin table
    rope_table_kernel<<<(TSEQ * 32 + 255) / 256, 256>>>();

    // 3) RoPE apply + layout to [B,H,T,Dh]
    rope_apply_kernel<<<(BATCH * TSEQ * NHEADS * 32) / 256, 256>>>();

    // 4) causal flash attention (tf32 mma)
    flash_mma_kernel<<<dim3(TSEQ / FBQ, NHEADS, BATCH), 256>>>();

    // 5) convert attention output, then out = attn @ proj_w^T + proj_b (tf32 mma)
    convert_permute_kernel<<<(ROWS * DMODEL) / 256, 256>>>(d_attn, d_attnt, ROWS * DMODEL);
    tf32_gemm_kernel<DMODEL><<<dim3(DMODEL / 128, ROWS / 128), 256, GEMM_SMEM_B>>>(
        d_attnt, d_wprojt, proj_b, out);
}

// round 9
// speedup vs baseline: 3.3454x; 1.0603x over previous
#include <cuda_runtime.h>
#include <math.h>
#include <cstdint>

// Problem constants
#define BATCH 2
#define TSEQ  2048
#define DMODEL 1024
#define NHEADS 16
#define HDIM  64
#define ROWS (BATCH * TSEQ)          // 4096
#define QKV_N (3 * DMODEL)           // 3072

// ---------------- scratch (no allocation allowed) ----------------
__device__ float g_qkv[ROWS * QKV_N];               // [B*T, 3*D]
__device__ float g_q[BATCH * NHEADS * TSEQ * HDIM]; // [B,H,T,Dh]
__device__ float g_k[BATCH * NHEADS * TSEQ * HDIM];
__device__ float g_v[BATCH * NHEADS * TSEQ * HDIM];
__device__ float g_cs[TSEQ * 32 * 2];               // cos,sin per (t, freq)
// tf32 column-permuted operands for the GEMMs
__device__ uint32_t g_xt[ROWS * DMODEL];
__device__ uint32_t g_wqkvt[QKV_N * DMODEL];
__device__ uint32_t g_wprojt[DMODEL * DMODEL];
__device__ uint32_t g_attnt[ROWS * DMODEL];         // flash writes tf32-permuted O here

// ================= helpers =================
__device__ __forceinline__ uint32_t s2u(const void* p) {
    uint32_t a;
    asm("{ .reg .u64 t; cvta.to.shared.u64 t, %1; cvt.u32.u64 %0, t; }"
        : "=r"(a) : "l"(p));
    return a;
}
__device__ __forceinline__ uint32_t f2tf32(float f) {
    uint32_t r;
    asm("cvt.rna.tf32.f32 %0, %1;" : "=r"(r) : "f"(f));
    return r;
}
__device__ __forceinline__ float ex2(float x) {
    float y;
    asm("ex2.approx.ftz.f32 %0, %1;" : "=f"(y) : "f"(x));
    return y;
}
__device__ __forceinline__ void cp16(uint32_t dst, const void* src) {
    asm volatile("cp.async.cg.shared.global [%0], [%1], 16;" :: "r"(dst), "l"(src));
}
__device__ __forceinline__ void mma8(float* d, const uint32_t* a, uint32_t b0, uint32_t b1) {
    asm volatile(
        "mma.sync.aligned.m16n8k8.row.col.f32.tf32.tf32.f32 "
        "{%0,%1,%2,%3}, {%4,%5,%6,%7}, {%8,%9}, {%0,%1,%2,%3};"
        : "+f"(d[0]), "+f"(d[1]), "+f"(d[2]), "+f"(d[3])
        : "r"(a[0]), "r"(a[1]), "r"(a[2]), "r"(a[3]), "r"(b0), "r"(b1));
}

// ---------------- convert f32 -> tf32 with per-32-block column permutation -----------
// dst position p within each 32-block holds orig col c = (p&7)*4 + (p>>3)
__global__ void convert_permute_kernel(const float* __restrict__ src,
                                       uint32_t* __restrict__ dst, int n)
{
    int idx = blockIdx.x * blockDim.x + threadIdx.x;
    if (idx >= n) return;
    int p = idx & 31;
    int c = (p & 7) * 4 + (p >> 3);
    int base = idx & ~31;
    dst[idx] = f2tf32(src[base + c]);
}

// ================= tf32 mma GEMM: C[M,NCOLS] = A[M,1024] @ W[NCOLS,1024]^T + bias ======
// Inputs pre-converted tf32 + column-permuted. CTA 128x128, 8 warps (4m x 2n),
// warp tile 32x64, K-chunk 32 double-buffered via cp.async. 2 CTAs/SM.
#define GSTR 36
#define GTILEW (128 * GSTR)
#define GEMM_SMEM_B (2 * 2 * GTILEW * 4)   // 73728 bytes

template<int NCOLS>
__global__ __launch_bounds__(256, 2) void tf32_gemm_kernel(
    const uint32_t* __restrict__ A,
    const uint32_t* __restrict__ W,
    const float* __restrict__ bias,
    float* __restrict__ C)
{
    extern __shared__ uint32_t smw[];
    const int tid = threadIdx.x;
    const int wid = tid >> 5, lane = tid & 31;
    const int g = lane >> 2, tg = lane & 3;
    const int wm = wid & 3, wn = wid >> 2;
    const int bm = blockIdx.y * 128, bn = blockIdx.x * 128;

    float acc[2][8][4];
    #pragma unroll
    for (int t = 0; t < 2; t++)
        #pragma unroll
        for (int nt = 0; nt < 8; nt++)
            #pragma unroll
            for (int j = 0; j < 4; j++) acc[t][nt][j] = 0.f;

    // fragment float4 base offset within a row (swizzle uses row&3 == g&3)
    const int fo = 8 * (tg ^ (g & 3));

    #define LOAD_CHUNK(c, s) do {                                                  \
        uint32_t* as_ = smw + (s) * 2 * GTILEW;                                    \
        uint32_t* bs_ = as_ + GTILEW;                                              \
        _Pragma("unroll")                                                          \
        for (int i_ = 0; i_ < 4; i_++) {                                           \
            int idx_ = i_ * 256 + tid;                                             \
            int row_ = idx_ >> 3, q_ = idx_ & 7;                                   \
            int sq_ = q_ ^ ((row_ & 3) << 1);                                      \
            cp16(s2u(as_ + row_ * GSTR + sq_ * 4),                                 \
                 A + (size_t)(bm + row_) * DMODEL + (c) * 32 + q_ * 4);            \
            cp16(s2u(bs_ + row_ * GSTR + sq_ * 4),                                 \
                 W + (size_t)(bn + row_) * DMODEL + (c) * 32 + q_ * 4);            \
        }                                                                          \
        asm volatile("cp.async.commit_group;" ::: "memory");                       \
    } while (0)

    LOAD_CHUNK(0, 0);

    for (int c = 0; c < DMODEL / 32; c++) {
        const int st = c & 1;
        if (c + 1 < DMODEL / 32) {
            LOAD_CHUNK(c + 1, (c + 1) & 1);
            asm volatile("cp.async.wait_group 1;" ::: "memory");
        } else {
            asm volatile("cp.async.wait_group 0;" ::: "memory");
        }
        __syncthreads();

        const uint32_t* as = smw + st * 2 * GTILEW;
        const uint32_t* bs = as + GTILEW;

        // A fragments: 2 m16-tiles x 4 kc x 4 regs (8 LDS.128)
        uint32_t a[2][4][4];
        #pragma unroll
        for (int t = 0; t < 2; t++) {
            const int r0 = wm * 32 + t * 16 + g;
            const int r1 = r0 + 8;
            uint4 x0 = *(const uint4*)(as + r0 * GSTR + fo);
            uint4 x1 = *(const uint4*)(as + r0 * GSTR + fo + 4);
            uint4 y0 = *(const uint4*)(as + r1 * GSTR + fo);
            uint4 y1 = *(const uint4*)(as + r1 * GSTR + fo + 4);
            a[t][0][0]=x0.x; a[t][0][1]=y0.x; a[t][0][2]=x0.y; a[t][0][3]=y0.y;
            a[t][1][0]=x0.z; a[t][1][1]=y0.z; a[t][1][2]=x0.w; a[t][1][3]=y0.w;
            a[t][2][0]=x1.x; a[t][2][1]=y1.x; a[t][2][2]=x1.y; a[t][2][3]=y1.y;
            a[t][3][0]=x1.z; a[t][3][1]=y1.z; a[t][3][2]=x1.w; a[t][3][3]=y1.w;
        }

        #pragma unroll
        for (int nt = 0; nt < 8; nt++) {
            const int rn = wn * 64 + nt * 8 + g;
            uint4 b0 = *(const uint4*)(bs + rn * GSTR + fo);
            uint4 b1 = *(const uint4*)(bs + rn * GSTR + fo + 4);
            #pragma unroll
            for (int t = 0; t < 2; t++) {
                mma8(acc[t][nt], a[t][0], b0.x, b0.y);
                mma8(acc[t][nt], a[t][1], b0.z, b0.w);
                mma8(acc[t][nt], a[t][2], b1.x, b1.y);
                mma8(acc[t][nt], a[t][3], b1.z, b1.w);
            }
        }
        __syncthreads();
    }
    #undef LOAD_CHUNK

    // epilogue: + bias, write float2 pairs
    #pragma unroll
    for (int t = 0; t < 2; t++) {
        const int r0 = bm + wm * 32 + t * 16 + g;
        #pragma unroll
        for (int nt = 0; nt < 8; nt++) {
            const int cc = bn + wn * 64 + nt * 8 + 2 * tg;
            const float b0 = bias[cc], b1 = bias[cc + 1];
            *(float2*)(C + (size_t)r0 * NCOLS + cc) =
                make_float2(acc[t][nt][0] + b0, acc[t][nt][1] + b1);
            *(float2*)(C + (size_t)(r0 + 8) * NCOLS + cc) =
                make_float2(acc[t][nt][2] + b0, acc[t][nt][3] + b1);
        }
    }
}

// ---------------- RoPE table ----------------
__global__ void rope_table_kernel()
{
    int idx = blockIdx.x * blockDim.x + threadIdx.x;
    if (idx >= TSEQ * 32) return;
    int t = idx >> 5;
    int j = idx & 31;
    float invf = powf(10000.0f, -((float)(2 * j) / 64.0f));
    float angle = (float)t * invf;
    double a = (double)angle;
    double s, c;
    sincos(a, &s, &c);
    g_cs[idx * 2 + 0] = (float)c;
    g_cs[idx * 2 + 1] = (float)s;
}

// ---------------- RoPE apply + transpose to [B,H,T,Dh] ----------------
__global__ void rope_apply_kernel()
{
    int idx = blockIdx.x * blockDim.x + threadIdx.x;
    if (idx >= BATCH * TSEQ * NHEADS * 32) return;
    int j = idx & 31;
    int h = (idx >> 5) & (NHEADS - 1);
    int t = (idx >> 9) & (TSEQ - 1);
    int b = idx >> 20;

    int row = b * TSEQ + t;
    const float* base = g_qkv + (size_t)row * QKV_N + h * HDIM;

    float c  = g_cs[(t * 32 + j) * 2 + 0];
    float sn = g_cs[(t * 32 + j) * 2 + 1];

    float q1 = base[j],          q2 = base[j + 32];
    float k1 = base[DMODEL + j], k2 = base[DMODEL + j + 32];

    size_t od = (((size_t)b * NHEADS + h) * TSEQ + t) * HDIM;
    g_q[od + j]      = q1 * c - q2 * sn;
    g_q[od + j + 32] = q2 * c + q1 * sn;
    g_k[od + j]      = k1 * c - k2 * sn;
    g_k[od + j + 32] = k2 * c + k1 * sn;
    g_v[od + j]      = base[2 * DMODEL + j];
    g_v[od + j + 32] = base[2 * DMODEL + j + 32];
}

// ================= flash attention: tf32 mma.sync (FA-2 style) =================
// Epilogue writes O directly as tf32 column-permuted uint32 into g_attnt.
#define FBQ 128
#define FBKV 32
#define KSTR 68
#define VSTR 72

__global__ __launch_bounds__(256, 2) void flash_mma_kernel()
{
    const int tid  = threadIdx.x;
    const int w    = tid >> 5;
    const int lane = tid & 31;
    const int g    = lane >> 2;
    const int tg   = lane & 3;
    const int qt = (gridDim.x - 1) - blockIdx.x;
    const int h  = blockIdx.y;
    const int b  = blockIdx.z;
    const int qb = qt * FBQ;
    const int wb = qb + w * 16;
    const int rA = wb + g;
    const int rB = rA + 8;

    const size_t bh = ((size_t)b * NHEADS + h) * TSEQ * HDIM;
    const float NEG = __int_as_float(0xff800000);

    __shared__ float Ks[FBKV * KSTR];
    __shared__ float Vs[FBKV * VSTR];

    const float pre = 0.125f * 1.4426950408889634f;
    uint32_t qf[8][4];
    {
        const float* q0 = g_q + bh + (size_t)rA * HDIM;
        const float* q1 = g_q + bh + (size_t)rB * HDIM;
        #pragma unroll
        for (int kc = 0; kc < 8; kc++) {
            qf[kc][0] = f2tf32(q0[kc * 8 + tg]     * pre);
            qf[kc][1] = f2tf32(q1[kc * 8 + tg]     * pre);
            qf[kc][2] = f2tf32(q0[kc * 8 + tg + 4] * pre);
            qf[kc][3] = f2tf32(q1[kc * 8 + tg + 4] * pre);
        }
    }

    float o[8][4];
    #pragma unroll
    for (int n = 0; n < 8; n++)
        #pragma unroll
        for (int j = 0; j < 4; j++) o[n][j] = 0.f;
    float mA = NEG, mB = NEG, lA = 0.f, lB = 0.f;

    const int ntiles = qb / FBKV + 4;
    for (int t0 = 0; t0 < ntiles; t0++) {
        const int j0 = t0 * FBKV;

        {
            const float4* ksrc = (const float4*)(g_k + bh + (size_t)j0 * HDIM);
            const float4* vsrc = (const float4*)(g_v + bh + (size_t)j0 * HDIM);
            #pragma unroll
            for (int i = 0; i < 2; i++) {
                const int idx = i * 256 + tid;
                const int key = idx >> 4;
                const int c   = idx & 15;
                float4 kv = ksrc[idx];
                uint4 kt;
                kt.x = f2tf32(kv.x); kt.y = f2tf32(kv.y);
                kt.z = f2tf32(kv.z); kt.w = f2tf32(kv.w);
                *(uint4*)&Ks[key * KSTR + c * 4] = kt;
                kv = vsrc[idx];
                kt.x = f2tf32(kv.x); kt.y = f2tf32(kv.y);
                kt.z = f2tf32(kv.z); kt.w = f2tf32(kv.w);
                *(uint4*)&Vs[key * VSTR + c * 4] = kt;
            }
        }
        __syncthreads();

        if (j0 <= wb) {
            float s[4][4];
            #pragma unroll
            for (int nt = 0; nt < 4; nt++) {
                s[nt][0] = 0.f; s[nt][1] = 0.f; s[nt][2] = 0.f; s[nt][3] = 0.f;
                #pragma unroll
                for (int kc = 0; kc < 8; kc++) {
                    uint32_t b0 = *(const uint32_t*)&Ks[(nt * 8 + g) * KSTR + kc * 8 + tg];
                    uint32_t b1 = *(const uint32_t*)&Ks[(nt * 8 + g) * KSTR + kc * 8 + tg + 4];
                    mma8(s[nt], qf[kc], b0, b1);
                }
            }

            float mtA = mA, mtB = mB;
            #pragma unroll
            for (int nt = 0; nt < 4; nt++) {
                const int jc = j0 + nt * 8 + 2 * tg;
                s[nt][0] = (jc     <= rA) ? s[nt][0] : NEG;
                s[nt][1] = (jc + 1 <= rA) ? s[nt][1] : NEG;
                s[nt][2] = (jc     <= rB) ? s[nt][2] : NEG;
                s[nt][3] = (jc + 1 <= rB) ? s[nt][3] : NEG;
                mtA = fmaxf(mtA, fmaxf(s[nt][0], s[nt][1]));
                mtB = fmaxf(mtB, fmaxf(s[nt][2], s[nt][3]));
            }
            mtA = fmaxf(mtA, __shfl_xor_sync(0xffffffffu, mtA, 1));
            mtA = fmaxf(mtA, __shfl_xor_sync(0xffffffffu, mtA, 2));
            mtB = fmaxf(mtB, __shfl_xor_sync(0xffffffffu, mtB, 1));
            mtB = fmaxf(mtB, __shfl_xor_sync(0xffffffffu, mtB, 2));

            const float corrA = ex2(mA - mtA);
            const float corrB = ex2(mB - mtB);
            mA = mtA; mB = mtB;

            uint32_t pf[4][4];
            float sumA = 0.f, sumB = 0.f;
            #pragma unroll
            for (int nt = 0; nt < 4; nt++) {
                pf[nt][0] = f2tf32(ex2(s[nt][0] - mtA));
                pf[nt][1] = f2tf32(ex2(s[nt][1] - mtA));
                pf[nt][2] = f2tf32(ex2(s[nt][2] - mtB));
                pf[nt][3] = f2tf32(ex2(s[nt][3] - mtB));
                sumA += __uint_as_float(pf[nt][0]) + __uint_as_float(pf[nt][1]);
                sumB += __uint_as_float(pf[nt][2]) + __uint_as_float(pf[nt][3]);
            }
            sumA += __shfl_xor_sync(0xffffffffu, sumA, 1);
            sumA += __shfl_xor_sync(0xffffffffu, sumA, 2);
            sumB += __shfl_xor_sync(0xffffffffu, sumB, 1);
            sumB += __shfl_xor_sync(0xffffffffu, sumB, 2);
            lA = lA * corrA + sumA;
            lB = lB * corrB + sumB;

            #pragma unroll
            for (int n = 0; n < 8; n++) {
                o[n][0] *= corrA; o[n][1] *= corrA;
                o[n][2] *= corrB; o[n][3] *= corrB;
            }

            const int srcL = tg >> 1;
            #pragma unroll
            for (int kc = 0; kc < 4; kc++) {
                uint32_t v0 = __shfl_sync(0xffffffffu, pf[kc][0], srcL, 4);
                uint32_t v1 = __shfl_sync(0xffffffffu, pf[kc][1], srcL, 4);
                uint32_t v2 = __shfl_sync(0xffffffffu, pf[kc][0], srcL + 2, 4);
                uint32_t v3 = __shfl_sync(0xffffffffu, pf[kc][1], srcL + 2, 4);
                uint32_t u0 = __shfl_sync(0xffffffffu, pf[kc][2], srcL, 4);
                uint32_t u1 = __shfl_sync(0xffffffffu, pf[kc][3], srcL, 4);
                uint32_t u2 = __shfl_sync(0xffffffffu, pf[kc][2], srcL + 2, 4);
                uint32_t u3 = __shfl_sync(0xffffffffu, pf[kc][3], srcL + 2, 4);
                uint32_t af[4];
                af[0] = (tg & 1) ? v1 : v0;
                af[1] = (tg & 1) ? u1 : u0;
                af[2] = (tg & 1) ? v3 : v2;
                af[3] = (tg & 1) ? u3 : u2;
                #pragma unroll
                for (int nt2 = 0; nt2 < 8; nt2++) {
                    uint32_t b0 = *(const uint32_t*)&Vs[(kc * 8 + tg) * VSTR + nt2 * 8 + g];
                    uint32_t b1 = *(const uint32_t*)&Vs[(kc * 8 + tg + 4) * VSTR + nt2 * 8 + g];
                    mma8(o[nt2], af, b0, b1);
                }
            }
        }
        __syncthreads();
    }

    // ---- epilogue: O/l -> tf32 column-permuted rows of g_attnt [B*T, 1024] ----
    // global col = h*64 + nt2*8 + 2*tg (+1); within 32-block: p = (c&3)*8 + (c>>2)
    const float iA = 1.f / lA;
    const float iB = 1.f / lB;
    uint32_t* opA = g_attnt + ((size_t)b * TSEQ + rA) * DMODEL + h * HDIM;
    uint32_t* opB = g_attnt + ((size_t)b * TSEQ + rB) * DMODEL + h * HDIM;
    #pragma unroll
    for (int nt2 = 0; nt2 < 8; nt2++) {
        const int cc = nt2 * 8 + 2 * tg;        // 0..63 within head
        const int blk = (cc >> 5) << 5;         // 0 or 32
        const int c0 = cc & 31, c1 = (cc + 1) & 31;
        const int p0 = (c0 & 3) * 8 + (c0 >> 2);
        const int p1 = (c1 & 3) * 8 + (c1 >> 2);
        opA[blk + p0] = f2tf32(o[nt2][0] * iA);
        opA[blk + p1] = f2tf32(o[nt2][1] * iA);
        opB[blk + p0] = f2tf32(o[nt2][2] * iB);
        opB[blk + p1] = f2tf32(o[nt2][3] * iB);
    }
}

// ---------------- launch ----------------
extern "C" void kernel_launch(void* const* d_in, const int* in_sizes, int n_in,
                              void* d_out, int out_size)
{
    const float* x      = (const float*)d_in[0];
    const float* qkv_w  = (const float*)d_in[1];
    const float* qkv_b  = (const float*)d_in[2];
    const float* proj_w = (const float*)d_in[3];
    const float* proj_b = (const float*)d_in[4];
    float* out = (float*)d_out;

    cudaFuncSetAttribute(tf32_gemm_kernel<QKV_N>,
                         cudaFuncAttributeMaxDynamicSharedMemorySize, GEMM_SMEM_B);
    cudaFuncSetAttribute(tf32_gemm_kernel<DMODEL>,
                         cudaFuncAttributeMaxDynamicSharedMemorySize, GEMM_SMEM_B);

    uint32_t *d_xt, *d_wqkvt, *d_wprojt, *d_attnt;
    float *d_qkv;
    cudaGetSymbolAddress((void**)&d_xt, g_xt);
    cudaGetSymbolAddress((void**)&d_wqkvt, g_wqkvt);
    cudaGetSymbolAddress((void**)&d_wprojt, g_wprojt);
    cudaGetSymbolAddress((void**)&d_attnt, g_attnt);
    cudaGetSymbolAddress((void**)&d_qkv, g_qkv);

    // 0) convert+permute GEMM operands to tf32
    convert_permute_kernel<<<(ROWS * DMODEL) / 256, 256>>>(x, d_xt, ROWS * DMODEL);
    convert_permute_kernel<<<(QKV_N * DMODEL) / 256, 256>>>(qkv_w, d_wqkvt, QKV_N * DMODEL);
    convert_permute_kernel<<<(DMODEL * DMODEL) / 256, 256>>>(proj_w, d_wprojt, DMODEL * DMODEL);

    // 1) QKV = x @ qkv_w^T + qkv_b  (tf32 mma)
    tf32_gemm_kernel<QKV_N><<<dim3(QKV_N / 128, ROWS / 128), 256, GEMM_SMEM_B>>>(
        d_xt, d_wqkvt, qkv_b, d_qkv);

    // 2) RoPE cos/sin table
    rope_table_kernel<<<(TSEQ * 32 + 255) / 256, 256>>>();

    // 3) RoPE apply + layout to [B,H,T,Dh]
    rope_apply_kernel<<<(BATCH * TSEQ * NHEADS * 32) / 256, 256>>>();

    // 4) causal flash attention (tf32 mma) -> writes tf32-permuted O into g_attnt
    flash_mma_kernel<<<dim3(TSEQ / FBQ, NHEADS, BATCH), 256>>>();

    // 5) out = attn @ proj_w^T + proj_b (tf32 mma)
    tf32_gemm_kernel<DMODEL><<<dim3(DMODEL / 128, ROWS / 128), 256, GEMM_SMEM_B>>>(
        d_attnt, d_wprojt, proj_b, out);
}

// round 10
// speedup vs baseline: 3.4614x; 1.0347x over previous
#include <cuda_runtime.h>
#include <math.h>
#include <cstdint>

// Problem constants
#define BATCH 2
#define TSEQ  2048
#define DMODEL 1024
#define NHEADS 16
#define HDIM  64
#define ROWS (BATCH * TSEQ)          // 4096
#define QKV_N (3 * DMODEL)           // 3072

// ---------------- scratch (no allocation allowed) ----------------
__device__ float g_qkv[ROWS * QKV_N];               // [B*T, 3*D]
__device__ float g_q[BATCH * NHEADS * TSEQ * HDIM]; // [B,H,T,Dh] fp32
__device__ uint32_t g_kt[BATCH * NHEADS * TSEQ * HDIM]; // [B,H,T,Dh] tf32
__device__ uint32_t g_vt[BATCH * NHEADS * TSEQ * HDIM]; // [B,H,T,Dh] tf32
__device__ float g_cs[TSEQ * 32 * 2];               // cos,sin per (t, freq)
// tf32 column-permuted operands for the GEMMs
__device__ uint32_t g_xt[ROWS * DMODEL];
__device__ uint32_t g_wqkvt[QKV_N * DMODEL];
__device__ uint32_t g_wprojt[DMODEL * DMODEL];
__device__ uint32_t g_attnt[ROWS * DMODEL];         // flash writes tf32-permuted O here

// ================= helpers =================
__device__ __forceinline__ uint32_t s2u(const void* p) {
    uint32_t a;
    asm("{ .reg .u64 t; cvta.to.shared.u64 t, %1; cvt.u32.u64 %0, t; }"
        : "=r"(a) : "l"(p));
    return a;
}
__device__ __forceinline__ uint32_t f2tf32(float f) {
    uint32_t r;
    asm("cvt.rna.tf32.f32 %0, %1;" : "=r"(r) : "f"(f));
    return r;
}
__device__ __forceinline__ float ex2(float x) {
    float y;
    asm("ex2.approx.ftz.f32 %0, %1;" : "=f"(y) : "f"(x));
    return y;
}
__device__ __forceinline__ void cp16(uint32_t dst, const void* src) {
    asm volatile("cp.async.cg.shared.global [%0], [%1], 16;" :: "r"(dst), "l"(src));
}
__device__ __forceinline__ void mma8(float* d, const uint32_t* a, uint32_t b0, uint32_t b1) {
    asm volatile(
        "mma.sync.aligned.m16n8k8.row.col.f32.tf32.tf32.f32 "
        "{%0,%1,%2,%3}, {%4,%5,%6,%7}, {%8,%9}, {%0,%1,%2,%3};"
        : "+f"(d[0]), "+f"(d[1]), "+f"(d[2]), "+f"(d[3])
        : "r"(a[0]), "r"(a[1]), "r"(a[2]), "r"(a[3]), "r"(b0), "r"(b1));
}

// ---------------- convert f32 -> tf32 with per-32-block column permutation -----------
// dst position p within each 32-block holds orig col c = (p&7)*4 + (p>>3)
__global__ void convert_permute_kernel(const float* __restrict__ src,
                                       uint32_t* __restrict__ dst, int n)
{
    int idx = blockIdx.x * blockDim.x + threadIdx.x;
    if (idx >= n) return;
    int p = idx & 31;
    int c = (p & 7) * 4 + (p >> 3);
    int base = idx & ~31;
    dst[idx] = f2tf32(src[base + c]);
}

// ================= tf32 mma GEMM: C[M,NCOLS] = A[M,1024] @ W[NCOLS,1024]^T + bias ======
// Inputs pre-converted tf32 + column-permuted. CTA 128x128, 8 warps (4m x 2n),
// warp tile 32x64, K-chunk 32 double-buffered via cp.async, ONE sync per chunk.
#define GSTR 36
#define GTILEW (128 * GSTR)
#define GEMM_SMEM_B (2 * 2 * GTILEW * 4)   // 73728 bytes

template<int NCOLS>
__global__ __launch_bounds__(256, 2) void tf32_gemm_kernel(
    const uint32_t* __restrict__ A,
    const uint32_t* __restrict__ W,
    const float* __restrict__ bias,
    float* __restrict__ C)
{
    extern __shared__ uint32_t smw[];
    const int tid = threadIdx.x;
    const int wid = tid >> 5, lane = tid & 31;
    const int g = lane >> 2, tg = lane & 3;
    const int wm = wid & 3, wn = wid >> 2;
    const int bm = blockIdx.y * 128, bn = blockIdx.x * 128;

    float acc[2][8][4];
    #pragma unroll
    for (int t = 0; t < 2; t++)
        #pragma unroll
        for (int nt = 0; nt < 8; nt++)
            #pragma unroll
            for (int j = 0; j < 4; j++) acc[t][nt][j] = 0.f;

    // fragment float4 base offset within a row (swizzle uses row&3 == g&3)
    const int fo = 8 * (tg ^ (g & 3));

    #define LOAD_CHUNK(c, s) do {                                                  \
        uint32_t* as_ = smw + (s) * 2 * GTILEW;                                    \
        uint32_t* bs_ = as_ + GTILEW;                                              \
        _Pragma("unroll")                                                          \
        for (int i_ = 0; i_ < 4; i_++) {                                           \
            int idx_ = i_ * 256 + tid;                                             \
            int row_ = idx_ >> 3, q_ = idx_ & 7;                                   \
            int sq_ = q_ ^ ((row_ & 3) << 1);                                      \
            cp16(s2u(as_ + row_ * GSTR + sq_ * 4),                                 \
                 A + (size_t)(bm + row_) * DMODEL + (c) * 32 + q_ * 4);            \
            cp16(s2u(bs_ + row_ * GSTR + sq_ * 4),                                 \
                 W + (size_t)(bn + row_) * DMODEL + (c) * 32 + q_ * 4);            \
        }                                                                          \
        asm volatile("cp.async.commit_group;" ::: "memory");                       \
    } while (0)

    #define CONSUME(s) do {                                                        \
        const uint32_t* as = smw + (s) * 2 * GTILEW;                               \
        const uint32_t* bs = as + GTILEW;                                          \
        uint32_t a[2][4][4];                                                       \
        _Pragma("unroll")                                                          \
        for (int t = 0; t < 2; t++) {                                              \
            const int r0 = wm * 32 + t * 16 + g;                                   \
            const int r1 = r0 + 8;                                                 \
            uint4 x0 = *(const uint4*)(as + r0 * GSTR + fo);                       \
            uint4 x1 = *(const uint4*)(as + r0 * GSTR + fo + 4);                   \
            uint4 y0 = *(const uint4*)(as + r1 * GSTR + fo);                       \
            uint4 y1 = *(const uint4*)(as + r1 * GSTR + fo + 4);                   \
            a[t][0][0]=x0.x; a[t][0][1]=y0.x; a[t][0][2]=x0.y; a[t][0][3]=y0.y;    \
            a[t][1][0]=x0.z; a[t][1][1]=y0.z; a[t][1][2]=x0.w; a[t][1][3]=y0.w;    \
            a[t][2][0]=x1.x; a[t][2][1]=y1.x; a[t][2][2]=x1.y; a[t][2][3]=y1.y;    \
            a[t][3][0]=x1.z; a[t][3][1]=y1.z; a[t][3][2]=x1.w; a[t][3][3]=y1.w;    \
        }                                                                          \
        _Pragma("unroll")                                                          \
        for (int nt = 0; nt < 8; nt++) {                                           \
            const int rn = wn * 64 + nt * 8 + g;                                   \
            uint4 b0 = *(const uint4*)(bs + rn * GSTR + fo);                       \
            uint4 b1 = *(const uint4*)(bs + rn * GSTR + fo + 4);                   \
            _Pragma("unroll")                                                      \
            for (int t = 0; t < 2; t++) {                                          \
                mma8(acc[t][nt], a[t][0], b0.x, b0.y);                             \
                mma8(acc[t][nt], a[t][1], b0.z, b0.w);                             \
                mma8(acc[t][nt], a[t][2], b1.x, b1.y);                             \
                mma8(acc[t][nt], a[t][3], b1.z, b1.w);                             \
            }                                                                      \
        }                                                                          \
    } while (0)

    LOAD_CHUNK(0, 0);

    #pragma unroll 1
    for (int c = 0; c < DMODEL / 32; c += 2) {
        // chunk c in stage 0
        asm volatile("cp.async.wait_group 0;" ::: "memory");
        __syncthreads();
        LOAD_CHUNK(c + 1, 1);          // c <= 30 so c+1 <= 31 always valid
        CONSUME(0);
        // chunk c+1 in stage 1
        asm volatile("cp.async.wait_group 0;" ::: "memory");
        __syncthreads();
        if (c + 2 < DMODEL / 32) LOAD_CHUNK(c + 2, 0);
        CONSUME(1);
    }
    #undef LOAD_CHUNK
    #undef CONSUME

    // epilogue: + bias, write float2 pairs
    #pragma unroll
    for (int t = 0; t < 2; t++) {
        const int r0 = bm + wm * 32 + t * 16 + g;
        #pragma unroll
        for (int nt = 0; nt < 8; nt++) {
            const int cc = bn + wn * 64 + nt * 8 + 2 * tg;
            const float b0 = bias[cc], b1 = bias[cc + 1];
            *(float2*)(C + (size_t)r0 * NCOLS + cc) =
                make_float2(acc[t][nt][0] + b0, acc[t][nt][1] + b1);
            *(float2*)(C + (size_t)(r0 + 8) * NCOLS + cc) =
                make_float2(acc[t][nt][2] + b0, acc[t][nt][3] + b1);
        }
    }
}

// ---------------- RoPE table ----------------
__global__ void rope_table_kernel()
{
    int idx = blockIdx.x * blockDim.x + threadIdx.x;
    if (idx >= TSEQ * 32) return;
    int t = idx >> 5;
    int j = idx & 31;
    float invf = powf(10000.0f, -((float)(2 * j) / 64.0f));
    float angle = (float)t * invf;
    double a = (double)angle;
    double s, c;
    sincos(a, &s, &c);
    g_cs[idx * 2 + 0] = (float)c;
    g_cs[idx * 2 + 1] = (float)s;
}

// ---------------- RoPE apply + transpose; K,V stored as tf32 ----------------
__global__ void rope_apply_kernel()
{
    int idx = blockIdx.x * blockDim.x + threadIdx.x;
    if (idx >= BATCH * TSEQ * NHEADS * 32) return;
    int j = idx & 31;
    int h = (idx >> 5) & (NHEADS - 1);
    int t = (idx >> 9) & (TSEQ - 1);
    int b = idx >> 20;

    int row = b * TSEQ + t;
    const float* base = g_qkv + (size_t)row * QKV_N + h * HDIM;

    float c  = g_cs[(t * 32 + j) * 2 + 0];
    float sn = g_cs[(t * 32 + j) * 2 + 1];

    float q1 = base[j],          q2 = base[j + 32];
    float k1 = base[DMODEL + j], k2 = base[DMODEL + j + 32];

    size_t od = (((size_t)b * NHEADS + h) * TSEQ + t) * HDIM;
    g_q[od + j]      = q1 * c - q2 * sn;
    g_q[od + j + 32] = q2 * c + q1 * sn;
    g_kt[od + j]      = f2tf32(k1 * c - k2 * sn);
    g_kt[od + j + 32] = f2tf32(k2 * c + k1 * sn);
    g_vt[od + j]      = f2tf32(base[2 * DMODEL + j]);
    g_vt[od + j + 32] = f2tf32(base[2 * DMODEL + j + 32]);
}

// ================= flash attention: tf32 mma.sync, cp.async K/V pipeline ==========
#define FBQ 128
#define FBKV 32
#define KSTR 68
#define VSTR 72

__global__ __launch_bounds__(256, 2) void flash_mma_kernel()
{
    const int tid  = threadIdx.x;
    const int w    = tid >> 5;
    const int lane = tid & 31;
    const int g    = lane >> 2;
    const int tg   = lane & 3;
    const int qt = (gridDim.x - 1) - blockIdx.x;
    const int h  = blockIdx.y;
    const int b  = blockIdx.z;
    const int qb = qt * FBQ;
    const int wb = qb + w * 16;
    const int rA = wb + g;
    const int rB = rA + 8;

    const size_t bh = ((size_t)b * NHEADS + h) * TSEQ * HDIM;
    const float NEG = __int_as_float(0xff800000);

    __shared__ uint32_t Ks[2][FBKV * KSTR];
    __shared__ uint32_t Vs[2][FBKV * VSTR];

    const float pre = 0.125f * 1.4426950408889634f;
    uint32_t qf[8][4];
    {
        const float* q0 = g_q + bh + (size_t)rA * HDIM;
        const float* q1 = g_q + bh + (size_t)rB * HDIM;
        #pragma unroll
        for (int kc = 0; kc < 8; kc++) {
            qf[kc][0] = f2tf32(q0[kc * 8 + tg]     * pre);
            qf[kc][1] = f2tf32(q1[kc * 8 + tg]     * pre);
            qf[kc][2] = f2tf32(q0[kc * 8 + tg + 4] * pre);
            qf[kc][3] = f2tf32(q1[kc * 8 + tg + 4] * pre);
        }
    }

    float o[8][4];
    #pragma unroll
    for (int n = 0; n < 8; n++)
        #pragma unroll
        for (int j = 0; j < 4; j++) o[n][j] = 0.f;
    float mA = NEG, mB = NEG, lA = 0.f, lB = 0.f;

    const int ntiles = qb / FBKV + 4;

    // K/V tile loader via cp.async (tiles are pre-converted tf32 in gmem)
    #define FLOAD(t0_, s_) do {                                                    \
        const uint32_t* ks_ = g_kt + bh + (size_t)(t0_) * FBKV * HDIM;             \
        const uint32_t* vs_ = g_vt + bh + (size_t)(t0_) * FBKV * HDIM;             \
        _Pragma("unroll")                                                          \
        for (int i_ = 0; i_ < 2; i_++) {                                           \
            int idx_ = i_ * 256 + tid;                                             \
            int key_ = idx_ >> 4, c_ = idx_ & 15;                                  \
            cp16(s2u(&Ks[s_][key_ * KSTR + c_ * 4]), ks_ + idx_ * 4);              \
            cp16(s2u(&Vs[s_][key_ * VSTR + c_ * 4]), vs_ + idx_ * 4);              \
        }                                                                          \
        asm volatile("cp.async.commit_group;" ::: "memory");                       \
    } while (0)

    FLOAD(0, 0);

    #pragma unroll 1
    for (int t0 = 0; t0 < ntiles; t0++) {
        const int j0 = t0 * FBKV;
        const int st = t0 & 1;

        asm volatile("cp.async.wait_group 0;" ::: "memory");
        __syncthreads();
        if (t0 + 1 < ntiles) FLOAD(t0 + 1, (t0 + 1) & 1);

        if (j0 <= wb) {
            const uint32_t* ksm = Ks[st];
            const uint32_t* vsm = Vs[st];

            float s[4][4];
            #pragma unroll
            for (int nt = 0; nt < 4; nt++) {
                s[nt][0] = 0.f; s[nt][1] = 0.f; s[nt][2] = 0.f; s[nt][3] = 0.f;
                #pragma unroll
                for (int kc = 0; kc < 8; kc++) {
                    uint32_t b0 = ksm[(nt * 8 + g) * KSTR + kc * 8 + tg];
                    uint32_t b1 = ksm[(nt * 8 + g) * KSTR + kc * 8 + tg + 4];
                    mma8(s[nt], qf[kc], b0, b1);
                }
            }

            float mtA = mA, mtB = mB;
            #pragma unroll
            for (int nt = 0; nt < 4; nt++) {
                const int jc = j0 + nt * 8 + 2 * tg;
                s[nt][0] = (jc     <= rA) ? s[nt][0] : NEG;
                s[nt][1] = (jc + 1 <= rA) ? s[nt][1] : NEG;
                s[nt][2] = (jc     <= rB) ? s[nt][2] : NEG;
                s[nt][3] = (jc + 1 <= rB) ? s[nt][3] : NEG;
                mtA = fmaxf(mtA, fmaxf(s[nt][0], s[nt][1]));
                mtB = fmaxf(mtB, fmaxf(s[nt][2], s[nt][3]));
            }
            mtA = fmaxf(mtA, __shfl_xor_sync(0xffffffffu, mtA, 1));
            mtA = fmaxf(mtA, __shfl_xor_sync(0xffffffffu, mtA, 2));
            mtB = fmaxf(mtB, __shfl_xor_sync(0xffffffffu, mtB, 1));
            mtB = fmaxf(mtB, __shfl_xor_sync(0xffffffffu, mtB, 2));

            const float corrA = ex2(mA - mtA);
            const float corrB = ex2(mB - mtB);
            mA = mtA; mB = mtB;

            uint32_t pf[4][4];
            float sumA = 0.f, sumB = 0.f;
            #pragma unroll
            for (int nt = 0; nt < 4; nt++) {
                pf[nt][0] = f2tf32(ex2(s[nt][0] - mtA));
                pf[nt][1] = f2tf32(ex2(s[nt][1] - mtA));
                pf[nt][2] = f2tf32(ex2(s[nt][2] - mtB));
                pf[nt][3] = f2tf32(ex2(s[nt][3] - mtB));
                sumA += __uint_as_float(pf[nt][0]) + __uint_as_float(pf[nt][1]);
                sumB += __uint_as_float(pf[nt][2]) + __uint_as_float(pf[nt][3]);
            }
            sumA += __shfl_xor_sync(0xffffffffu, sumA, 1);
            sumA += __shfl_xor_sync(0xffffffffu, sumA, 2);
            sumB += __shfl_xor_sync(0xffffffffu, sumB, 1);
            sumB += __shfl_xor_sync(0xffffffffu, sumB, 2);
            lA = lA * corrA + sumA;
            lB = lB * corrB + sumB;

            #pragma unroll
            for (int n = 0; n < 8; n++) {
                o[n][0] *= corrA; o[n][1] *= corrA;
                o[n][2] *= corrB; o[n][3] *= corrB;
            }

            const int srcL = tg >> 1;
            #pragma unroll
            for (int kc = 0; kc < 4; kc++) {
                uint32_t v0 = __shfl_sync(0xffffffffu, pf[kc][0], srcL, 4);
                uint32_t v1 = __shfl_sync(0xffffffffu, pf[kc][1], srcL, 4);
                uint32_t v2 = __shfl_sync(0xffffffffu, pf[kc][0], srcL + 2, 4);
                uint32_t v3 = __shfl_sync(0xffffffffu, pf[kc][1], srcL + 2, 4);
                uint32_t u0 = __shfl_sync(0xffffffffu, pf[kc][2], srcL, 4);
                uint32_t u1 = __shfl_sync(0xffffffffu, pf[kc][3], srcL, 4);
                uint32_t u2 = __shfl_sync(0xffffffffu, pf[kc][2], srcL + 2, 4);
                uint32_t u3 = __shfl_sync(0xffffffffu, pf[kc][3], srcL + 2, 4);
                uint32_t af[4];
                af[0] = (tg & 1) ? v1 : v0;
                af[1] = (tg & 1) ? u1 : u0;
                af[2] = (tg & 1) ? v3 : v2;
                af[3] = (tg & 1) ? u3 : u2;
                #pragma unroll
                for (int nt2 = 0; nt2 < 8; nt2++) {
                    uint32_t b0 = vsm[(kc * 8 + tg) * VSTR + nt2 * 8 + g];
                    uint32_t b1 = vsm[(kc * 8 + tg + 4) * VSTR + nt2 * 8 + g];
                    mma8(o[nt2], af, b0, b1);
                }
            }
        }
    }
    #undef FLOAD

    // ---- epilogue: O/l -> tf32 column-permuted rows of g_attnt [B*T, 1024] ----
    const float iA = 1.f / lA;
    const float iB = 1.f / lB;
    uint32_t* opA = g_attnt + ((size_t)b * TSEQ + rA) * DMODEL + h * HDIM;
    uint32_t* opB = g_attnt + ((size_t)b * TSEQ + rB) * DMODEL + h * HDIM;
    #pragma unroll
    for (int nt2 = 0; nt2 < 8; nt2++) {
        const int cc = nt2 * 8 + 2 * tg;        // 0..63 within head
        const int blk = (cc >> 5) << 5;         // 0 or 32
        const int c0 = cc & 31, c1 = (cc + 1) & 31;
        const int p0 = (c0 & 3) * 8 + (c0 >> 2);
        const int p1 = (c1 & 3) * 8 + (c1 >> 2);
        opA[blk + p0] = f2tf32(o[nt2][0] * iA);
        opA[blk + p1] = f2tf32(o[nt2][1] * iA);
        opB[blk + p0] = f2tf32(o[nt2][2] * iB);
        opB[blk + p1] = f2tf32(o[nt2][3] * iB);
    }
}

// ---------------- launch ----------------
extern "C" void kernel_launch(void* const* d_in, const int* in_sizes, int n_in,
                              void* d_out, int out_size)
{
    const float* x      = (const float*)d_in[0];
    const float* qkv_w  = (const float*)d_in[1];
    const float* qkv_b  = (const float*)d_in[2];
    const float* proj_w = (const float*)d_in[3];
    const float* proj_b = (const float*)d_in[4];
    float* out = (float*)d_out;

    cudaFuncSetAttribute(tf32_gemm_kernel<QKV_N>,
                         cudaFuncAttributeMaxDynamicSharedMemorySize, GEMM_SMEM_B);
    cudaFuncSetAttribute(tf32_gemm_kernel<DMODEL>,
                         cudaFuncAttributeMaxDynamicSharedMemorySize, GEMM_SMEM_B);

    uint32_t *d_xt, *d_wqkvt, *d_wprojt, *d_attnt;
    float *d_qkv;
    cudaGetSymbolAddress((void**)&d_xt, g_xt);
    cudaGetSymbolAddress((void**)&d_wqkvt, g_wqkvt);
    cudaGetSymbolAddress((void**)&d_wprojt, g_wprojt);
    cudaGetSymbolAddress((void**)&d_attnt, g_attnt);
    cudaGetSymbolAddress((void**)&d_qkv, g_qkv);

    // 0) convert+permute GEMM operands to tf32
    convert_permute_kernel<<<(ROWS * DMODEL) / 256, 256>>>(x, d_xt, ROWS * DMODEL);
    convert_permute_kernel<<<(QKV_N * DMODEL) / 256, 256>>>(qkv_w, d_wqkvt, QKV_N * DMODEL);
    convert_permute_kernel<<<(DMODEL * DMODEL) / 256, 256>>>(proj_w, d_wprojt, DMODEL * DMODEL);

    // 1) QKV = x @ qkv_w^T + qkv_b  (tf32 mma)
    tf32_gemm_kernel<QKV_N><<<dim3(QKV_N / 128, ROWS / 128), 256, GEMM_SMEM_B>>>(
        d_xt, d_wqkvt, qkv_b, d_qkv);

    // 2) RoPE cos/sin table
    rope_table_kernel<<<(TSEQ * 32 + 255) / 256, 256>>>();

    // 3) RoPE apply + layout; K,V stored tf32
    rope_apply_kernel<<<(BATCH * TSEQ * NHEADS * 32) / 256, 256>>>();

    // 4) causal flash attention (tf32 mma) -> writes tf32-permuted O into g_attnt
    flash_mma_kernel<<<dim3(TSEQ / FBQ, NHEADS, BATCH), 256>>>();

    // 5) out = attn @ proj_w^T + proj_b (tf32 mma)
    tf32_gemm_kernel<DMODEL><<<dim3(DMODEL / 128, ROWS / 128), 256, GEMM_SMEM_B>>>(
        d_attnt, d_wprojt, proj_b, out);
}

// round 11
// speedup vs baseline: 3.4987x; 1.0108x over previous
#include <cuda_runtime.h>
#include <math.h>
#include <cstdint>

// Problem constants
#define BATCH 2
#define TSEQ  2048
#define DMODEL 1024
#define NHEADS 16
#define HDIM  64
#define ROWS (BATCH * TSEQ)          // 4096
#define QKV_N (3 * DMODEL)           // 3072

// ---------------- scratch (no allocation allowed) ----------------
__device__ float g_qkv[ROWS * QKV_N];               // [B*T, 3*D]
__device__ float g_q[BATCH * NHEADS * TSEQ * HDIM]; // [B,H,T,Dh] fp32
__device__ uint32_t g_kt[BATCH * NHEADS * TSEQ * HDIM]; // tf32
__device__ uint32_t g_vt[BATCH * NHEADS * TSEQ * HDIM]; // tf32
__device__ float g_cs[TSEQ * 32 * 2];               // cos,sin per (t, freq)
// tf32 column-permuted operands for the GEMMs
__device__ uint32_t g_xt[ROWS * DMODEL];
__device__ uint32_t g_wqkvt[QKV_N * DMODEL];
__device__ uint32_t g_wprojt[DMODEL * DMODEL];
__device__ uint32_t g_attnt[ROWS * DMODEL];         // flash writes tf32-permuted O here

// ================= helpers =================
__device__ __forceinline__ uint32_t s2u(const void* p) {
    uint32_t a;
    asm("{ .reg .u64 t; cvta.to.shared.u64 t, %1; cvt.u32.u64 %0, t; }"
        : "=r"(a) : "l"(p));
    return a;
}
__device__ __forceinline__ uint32_t f2tf32(float f) {
    uint32_t r;
    asm("cvt.rna.tf32.f32 %0, %1;" : "=r"(r) : "f"(f));
    return r;
}
__device__ __forceinline__ float ex2(float x) {
    float y;
    asm("ex2.approx.ftz.f32 %0, %1;" : "=f"(y) : "f"(x));
    return y;
}
__device__ __forceinline__ void cp16(uint32_t dst, const void* src) {
    asm volatile("cp.async.cg.shared.global [%0], [%1], 16;" :: "r"(dst), "l"(src));
}
__device__ __forceinline__ void mma8(float* d, const uint32_t* a, uint32_t b0, uint32_t b1) {
    asm volatile(
        "mma.sync.aligned.m16n8k8.row.col.f32.tf32.tf32.f32 "
        "{%0,%1,%2,%3}, {%4,%5,%6,%7}, {%8,%9}, {%0,%1,%2,%3};"
        : "+f"(d[0]), "+f"(d[1]), "+f"(d[2]), "+f"(d[3])
        : "r"(a[0]), "r"(a[1]), "r"(a[2]), "r"(a[3]), "r"(b0), "r"(b1));
}

// ---------------- convert f32 -> tf32 with per-32-block column permutation -----------
__global__ void convert_permute_kernel(const float* __restrict__ src,
                                       uint32_t* __restrict__ dst, int n)
{
    int idx = blockIdx.x * blockDim.x + threadIdx.x;
    if (idx >= n) return;
    int p = idx & 31;
    int c = (p & 7) * 4 + (p >> 3);
    int base = idx & ~31;
    dst[idx] = f2tf32(src[base + c]);
}

// ================= tf32 mma GEMM: C[M,NCOLS] = A[M,1024] @ W[NCOLS,1024]^T + bias ======
// 3-stage cp.async pipeline (wait_group 1), MMA reordered for RAW spacing.
#define GSTR 36
#define GTILEW (128 * GSTR)
#define GSTAGES 3
#define GEMM_SMEM_B (GSTAGES * 2 * GTILEW * 4)   // 110592 bytes

template<int NCOLS>
__global__ __launch_bounds__(256, 2) void tf32_gemm_kernel(
    const uint32_t* __restrict__ A,
    const uint32_t* __restrict__ W,
    const float* __restrict__ bias,
    float* __restrict__ C)
{
    extern __shared__ uint32_t smw[];
    const int tid = threadIdx.x;
    const int wid = tid >> 5, lane = tid & 31;
    const int g = lane >> 2, tg = lane & 3;
    const int wm = wid & 3, wn = wid >> 2;
    const int bm = blockIdx.y * 128, bn = blockIdx.x * 128;

    float acc[2][8][4];
    #pragma unroll
    for (int t = 0; t < 2; t++)
        #pragma unroll
        for (int nt = 0; nt < 8; nt++)
            #pragma unroll
            for (int j = 0; j < 4; j++) acc[t][nt][j] = 0.f;

    const int fo = 8 * (tg ^ (g & 3));

    #define LOAD_CHUNK(c, s) do {                                                  \
        uint32_t* as_ = smw + (s) * 2 * GTILEW;                                    \
        uint32_t* bs_ = as_ + GTILEW;                                              \
        _Pragma("unroll")                                                          \
        for (int i_ = 0; i_ < 4; i_++) {                                           \
            int idx_ = i_ * 256 + tid;                                             \
            int row_ = idx_ >> 3, q_ = idx_ & 7;                                   \
            int sq_ = q_ ^ ((row_ & 3) << 1);                                      \
            cp16(s2u(as_ + row_ * GSTR + sq_ * 4),                                 \
                 A + (size_t)(bm + row_) * DMODEL + (c) * 32 + q_ * 4);            \
            cp16(s2u(bs_ + row_ * GSTR + sq_ * 4),                                 \
                 W + (size_t)(bn + row_) * DMODEL + (c) * 32 + q_ * 4);            \
        }                                                                          \
        asm volatile("cp.async.commit_group;" ::: "memory");                       \
    } while (0)

    // prologue: 2 chunks in flight
    LOAD_CHUNK(0, 0);
    LOAD_CHUNK(1, 1);

    int s = 0, sp = 2;     // consume stage / prefetch stage
    #pragma unroll 1
    for (int c = 0; c < DMODEL / 32; c++) {
        asm volatile("cp.async.wait_group 1;" ::: "memory");
        __syncthreads();
        if (c + 2 < DMODEL / 32) {
            LOAD_CHUNK(c + 2, sp);
        } else {
            asm volatile("cp.async.commit_group;" ::: "memory");  // empty group keeps count
        }

        const uint32_t* as = smw + s * 2 * GTILEW;
        const uint32_t* bs = as + GTILEW;

        // A fragments: 2 m16-tiles x 4 kc x 4 regs
        uint32_t a[2][4][4];
        #pragma unroll
        for (int t = 0; t < 2; t++) {
            const int r0 = wm * 32 + t * 16 + g;
            const int r1 = r0 + 8;
            uint4 x0 = *(const uint4*)(as + r0 * GSTR + fo);
            uint4 x1 = *(const uint4*)(as + r0 * GSTR + fo + 4);
            uint4 y0 = *(const uint4*)(as + r1 * GSTR + fo);
            uint4 y1 = *(const uint4*)(as + r1 * GSTR + fo + 4);
            a[t][0][0]=x0.x; a[t][0][1]=y0.x; a[t][0][2]=x0.y; a[t][0][3]=y0.y;
            a[t][1][0]=x0.z; a[t][1][1]=y0.z; a[t][1][2]=x0.w; a[t][1][3]=y0.w;
            a[t][2][0]=x1.x; a[t][2][1]=y1.x; a[t][2][2]=x1.y; a[t][2][3]=y1.y;
            a[t][3][0]=x1.z; a[t][3][1]=y1.z; a[t][3][2]=x1.w; a[t][3][3]=y1.w;
        }

        // B fragments + MMAs; kc-outer/t-inner => same-acc RAW distance 2
        #pragma unroll
        for (int nt = 0; nt < 8; nt++) {
            const int rn = wn * 64 + nt * 8 + g;
            uint4 b0 = *(const uint4*)(bs + rn * GSTR + fo);
            uint4 b1 = *(const uint4*)(bs + rn * GSTR + fo + 4);
            mma8(acc[0][nt], a[0][0], b0.x, b0.y);
            mma8(acc[1][nt], a[1][0], b0.x, b0.y);
            mma8(acc[0][nt], a[0][1], b0.z, b0.w);
            mma8(acc[1][nt], a[1][1], b0.z, b0.w);
            mma8(acc[0][nt], a[0][2], b1.x, b1.y);
            mma8(acc[1][nt], a[1][2], b1.x, b1.y);
            mma8(acc[0][nt], a[0][3], b1.z, b1.w);
            mma8(acc[1][nt], a[1][3], b1.z, b1.w);
        }

        s  = (s  == GSTAGES - 1) ? 0 : s + 1;
        sp = (sp == GSTAGES - 1) ? 0 : sp + 1;
    }
    #undef LOAD_CHUNK

    // epilogue: + bias, write float2 pairs
    #pragma unroll
    for (int t = 0; t < 2; t++) {
        const int r0 = bm + wm * 32 + t * 16 + g;
        #pragma unroll
        for (int nt = 0; nt < 8; nt++) {
            const int cc = bn + wn * 64 + nt * 8 + 2 * tg;
            const float b0 = bias[cc], b1 = bias[cc + 1];
            *(float2*)(C + (size_t)r0 * NCOLS + cc) =
                make_float2(acc[0][nt][0] + b0, acc[0][nt][1] + b1);
            *(float2*)(C + (size_t)(r0 + 8) * NCOLS + cc) =
                make_float2(acc[0][nt][2] + b0, acc[0][nt][3] + b1);
            const int r2 = r0 + 16;
            *(float2*)(C + (size_t)r2 * NCOLS + cc) =
                make_float2(acc[1][nt][0] + b0, acc[1][nt][1] + b1);
            *(float2*)(C + (size_t)(r2 + 8) * NCOLS + cc) =
                make_float2(acc[1][nt][2] + b0, acc[1][nt][3] + b1);
        }
        break;   // both t handled above via acc[0]/acc[1]
    }

    // NOTE: loop above collapsed: t=0 rows wm*32+{0..15}, t=1 rows wm*32+{16..31}
}

// ---------------- RoPE table ----------------
__global__ void rope_table_kernel()
{
    int idx = blockIdx.x * blockDim.x + threadIdx.x;
    if (idx >= TSEQ * 32) return;
    int t = idx >> 5;
    int j = idx & 31;
    float invf = powf(10000.0f, -((float)(2 * j) / 64.0f));
    float angle = (float)t * invf;
    double a = (double)angle;
    double s, c;
    sincos(a, &s, &c);
    g_cs[idx * 2 + 0] = (float)c;
    g_cs[idx * 2 + 1] = (float)s;
}

// ---------------- RoPE apply + transpose; K,V stored as tf32 ----------------
__global__ void rope_apply_kernel()
{
    int idx = blockIdx.x * blockDim.x + threadIdx.x;
    if (idx >= BATCH * TSEQ * NHEADS * 32) return;
    int j = idx & 31;
    int h = (idx >> 5) & (NHEADS - 1);
    int t = (idx >> 9) & (TSEQ - 1);
    int b = idx >> 20;

    int row = b * TSEQ + t;
    const float* base = g_qkv + (size_t)row * QKV_N + h * HDIM;

    float c  = g_cs[(t * 32 + j) * 2 + 0];
    float sn = g_cs[(t * 32 + j) * 2 + 1];

    float q1 = base[j],          q2 = base[j + 32];
    float k1 = base[DMODEL + j], k2 = base[DMODEL + j + 32];

    size_t od = (((size_t)b * NHEADS + h) * TSEQ + t) * HDIM;
    g_q[od + j]      = q1 * c - q2 * sn;
    g_q[od + j + 32] = q2 * c + q1 * sn;
    g_kt[od + j]      = f2tf32(k1 * c - k2 * sn);
    g_kt[od + j + 32] = f2tf32(k2 * c + k1 * sn);
    g_vt[od + j]      = f2tf32(base[2 * DMODEL + j]);
    g_vt[od + j + 32] = f2tf32(base[2 * DMODEL + j + 32]);
}

// ================= flash attention: tf32 mma.sync, cp.async K/V pipeline ==========
#define FBQ 128
#define FBKV 32
#define KSTR 68
#define VSTR 72

__global__ __launch_bounds__(256, 2) void flash_mma_kernel()
{
    const int tid  = threadIdx.x;
    const int w    = tid >> 5;
    const int lane = tid & 31;
    const int g    = lane >> 2;
    const int tg   = lane & 3;
    const int qt = (gridDim.x - 1) - blockIdx.x;
    const int h  = blockIdx.y;
    const int b  = blockIdx.z;
    const int qb = qt * FBQ;
    const int wb = qb + w * 16;
    const int rA = wb + g;
    const int rB = rA + 8;

    const size_t bh = ((size_t)b * NHEADS + h) * TSEQ * HDIM;
    const float NEG = __int_as_float(0xff800000);

    __shared__ uint32_t Ks[2][FBKV * KSTR];
    __shared__ uint32_t Vs[2][FBKV * VSTR];

    const float pre = 0.125f * 1.4426950408889634f;
    uint32_t qf[8][4];
    {
        const float* q0 = g_q + bh + (size_t)rA * HDIM;
        const float* q1 = g_q + bh + (size_t)rB * HDIM;
        #pragma unroll
        for (int kc = 0; kc < 8; kc++) {
            qf[kc][0] = f2tf32(q0[kc * 8 + tg]     * pre);
            qf[kc][1] = f2tf32(q1[kc * 8 + tg]     * pre);
            qf[kc][2] = f2tf32(q0[kc * 8 + tg + 4] * pre);
            qf[kc][3] = f2tf32(q1[kc * 8 + tg + 4] * pre);
        }
    }

    float o[8][4];
    #pragma unroll
    for (int n = 0; n < 8; n++)
        #pragma unroll
        for (int j = 0; j < 4; j++) o[n][j] = 0.f;
    float mA = NEG, mB = NEG, lA = 0.f, lB = 0.f;

    const int ntiles = qb / FBKV + 4;

    #define FLOAD(t0_, s_) do {                                                    \
        const uint32_t* ks_ = g_kt + bh + (size_t)(t0_) * FBKV * HDIM;             \
        const uint32_t* vs_ = g_vt + bh + (size_t)(t0_) * FBKV * HDIM;             \
        _Pragma("unroll")                                                          \
        for (int i_ = 0; i_ < 2; i_++) {                                           \
            int idx_ = i_ * 256 + tid;                                             \
            int key_ = idx_ >> 4, c_ = idx_ & 15;                                  \
            cp16(s2u(&Ks[s_][key_ * KSTR + c_ * 4]), ks_ + idx_ * 4);              \
            cp16(s2u(&Vs[s_][key_ * VSTR + c_ * 4]), vs_ + idx_ * 4);              \
        }                                                                          \
        asm volatile("cp.async.commit_group;" ::: "memory");                       \
    } while (0)

    FLOAD(0, 0);

    #pragma unroll 1
    for (int t0 = 0; t0 < ntiles; t0++) {
        const int j0 = t0 * FBKV;
        const int st = t0 & 1;

        asm volatile("cp.async.wait_group 0;" ::: "memory");
        __syncthreads();
        if (t0 + 1 < ntiles) FLOAD(t0 + 1, (t0 + 1) & 1);

        if (j0 <= wb) {
            const uint32_t* ksm = Ks[st];
            const uint32_t* vsm = Vs[st];

            // S = Q@K^T: kc-outer / nt-inner => same-acc RAW distance 4
            float s[4][4];
            #pragma unroll
            for (int nt = 0; nt < 4; nt++) {
                s[nt][0] = 0.f; s[nt][1] = 0.f; s[nt][2] = 0.f; s[nt][3] = 0.f;
            }
            #pragma unroll
            for (int kc = 0; kc < 8; kc++) {
                #pragma unroll
                for (int nt = 0; nt < 4; nt++) {
                    uint32_t b0 = ksm[(nt * 8 + g) * KSTR + kc * 8 + tg];
                    uint32_t b1 = ksm[(nt * 8 + g) * KSTR + kc * 8 + tg + 4];
                    mma8(s[nt], qf[kc], b0, b1);
                }
            }

            float mtA = mA, mtB = mB;
            #pragma unroll
            for (int nt = 0; nt < 4; nt++) {
                const int jc = j0 + nt * 8 + 2 * tg;
                s[nt][0] = (jc     <= rA) ? s[nt][0] : NEG;
                s[nt][1] = (jc + 1 <= rA) ? s[nt][1] : NEG;
                s[nt][2] = (jc     <= rB) ? s[nt][2] : NEG;
                s[nt][3] = (jc + 1 <= rB) ? s[nt][3] : NEG;
                mtA = fmaxf(mtA, fmaxf(s[nt][0], s[nt][1]));
                mtB = fmaxf(mtB, fmaxf(s[nt][2], s[nt][3]));
            }
            mtA = fmaxf(mtA, __shfl_xor_sync(0xffffffffu, mtA, 1));
            mtA = fmaxf(mtA, __shfl_xor_sync(0xffffffffu, mtA, 2));
            mtB = fmaxf(mtB, __shfl_xor_sync(0xffffffffu, mtB, 1));
            mtB = fmaxf(mtB, __shfl_xor_sync(0xffffffffu, mtB, 2));

            const float corrA = ex2(mA - mtA);
            const float corrB = ex2(mB - mtB);
            mA = mtA; mB = mtB;

            uint32_t pf[4][4];
            float sumA = 0.f, sumB = 0.f;
            #pragma unroll
            for (int nt = 0; nt < 4; nt++) {
                pf[nt][0] = f2tf32(ex2(s[nt][0] - mtA));
                pf[nt][1] = f2tf32(ex2(s[nt][1] - mtA));
                pf[nt][2] = f2tf32(ex2(s[nt][2] - mtB));
                pf[nt][3] = f2tf32(ex2(s[nt][3] - mtB));
                sumA += __uint_as_float(pf[nt][0]) + __uint_as_float(pf[nt][1]);
                sumB += __uint_as_float(pf[nt][2]) + __uint_as_float(pf[nt][3]);
            }
            sumA += __shfl_xor_sync(0xffffffffu, sumA, 1);
            sumA += __shfl_xor_sync(0xffffffffu, sumA, 2);
            sumB += __shfl_xor_sync(0xffffffffu, sumB, 1);
            sumB += __shfl_xor_sync(0xffffffffu, sumB, 2);
            lA = lA * corrA + sumA;
            lB = lB * corrB + sumB;

            #pragma unroll
            for (int n = 0; n < 8; n++) {
                o[n][0] *= corrA; o[n][1] *= corrA;
                o[n][2] *= corrB; o[n][3] *= corrB;
            }

            const int srcL = tg >> 1;
            #pragma unroll
            for (int kc = 0; kc < 4; kc++) {
                uint32_t v0 = __shfl_sync(0xffffffffu, pf[kc][0], srcL, 4);
                uint32_t v1 = __shfl_sync(0xffffffffu, pf[kc][1], srcL, 4);
                uint32_t v2 = __shfl_sync(0xffffffffu, pf[kc][0], srcL + 2, 4);
                uint32_t v3 = __shfl_sync(0xffffffffu, pf[kc][1], srcL + 2, 4);
                uint32_t u0 = __shfl_sync(0xffffffffu, pf[kc][2], srcL, 4);
                uint32_t u1 = __shfl_sync(0xffffffffu, pf[kc][3], srcL, 4);
                uint32_t u2 = __shfl_sync(0xffffffffu, pf[kc][2], srcL + 2, 4);
                uint32_t u3 = __shfl_sync(0xffffffffu, pf[kc][3], srcL + 2, 4);
                uint32_t af[4];
                af[0] = (tg & 1) ? v1 : v0;
                af[1] = (tg & 1) ? u1 : u0;
                af[2] = (tg & 1) ? v3 : v2;
                af[3] = (tg & 1) ? u3 : u2;
                #pragma unroll
                for (int nt2 = 0; nt2 < 8; nt2++) {
                    uint32_t b0 = vsm[(kc * 8 + tg) * VSTR + nt2 * 8 + g];
                    uint32_t b1 = vsm[(kc * 8 + tg + 4) * VSTR + nt2 * 8 + g];
                    mma8(o[nt2], af, b0, b1);
                }
            }
        }
    }
    #undef FLOAD

    // ---- epilogue: O/l -> tf32 column-permuted rows of g_attnt [B*T, 1024] ----
    const float iA = 1.f / lA;
    const float iB = 1.f / lB;
    uint32_t* opA = g_attnt + ((size_t)b * TSEQ + rA) * DMODEL + h * HDIM;
    uint32_t* opB = g_attnt + ((size_t)b * TSEQ + rB) * DMODEL + h * HDIM;
    #pragma unroll
    for (int nt2 = 0; nt2 < 8; nt2++) {
        const int cc = nt2 * 8 + 2 * tg;
        const int blk = (cc >> 5) << 5;
        const int c0 = cc & 31, c1 = (cc + 1) & 31;
        const int p0 = (c0 & 3) * 8 + (c0 >> 2);
        const int p1 = (c1 & 3) * 8 + (c1 >> 2);
        opA[blk + p0] = f2tf32(o[nt2][0] * iA);
        opA[blk + p1] = f2tf32(o[nt2][1] * iA);
        opB[blk + p0] = f2tf32(o[nt2][2] * iB);
        opB[blk + p1] = f2tf32(o[nt2][3] * iB);
    }
}

// ---------------- launch ----------------
extern "C" void kernel_launch(void* const* d_in, const int* in_sizes, int n_in,
                              void* d_out, int out_size)
{
    const float* x      = (const float*)d_in[0];
    const float* qkv_w  = (const float*)d_in[1];
    const float* qkv_b  = (const float*)d_in[2];
    const float* proj_w = (const float*)d_in[3];
    const float* proj_b = (const float*)d_in[4];
    float* out = (float*)d_out;

    cudaFuncSetAttribute(tf32_gemm_kernel<QKV_N>,
                         cudaFuncAttributeMaxDynamicSharedMemorySize, GEMM_SMEM_B);
    cudaFuncSetAttribute(tf32_gemm_kernel<DMODEL>,
                         cudaFuncAttributeMaxDynamicSharedMemorySize, GEMM_SMEM_B);

    uint32_t *d_xt, *d_wqkvt, *d_wprojt, *d_attnt;
    float *d_qkv;
    cudaGetSymbolAddress((void**)&d_xt, g_xt);
    cudaGetSymbolAddress((void**)&d_wqkvt, g_wqkvt);
    cudaGetSymbolAddress((void**)&d_wprojt, g_wprojt);
    cudaGetSymbolAddress((void**)&d_attnt, g_attnt);
    cudaGetSymbolAddress((void**)&d_qkv, g_qkv);

    // 0) convert+permute GEMM operands to tf32
    convert_permute_kernel<<<(ROWS * DMODEL) / 256, 256>>>(x, d_xt, ROWS * DMODEL);
    convert_permute_kernel<<<(QKV_N * DMODEL) / 256, 256>>>(qkv_w, d_wqkvt, QKV_N * DMODEL);
    convert_permute_kernel<<<(DMODEL * DMODEL) / 256, 256>>>(proj_w, d_wprojt, DMODEL * DMODEL);

    // 1) QKV = x @ qkv_w^T + qkv_b  (tf32 mma)
    tf32_gemm_kernel<QKV_N><<<dim3(QKV_N / 128, ROWS / 128), 256, GEMM_SMEM_B>>>(
        d_xt, d_wqkvt, qkv_b, d_qkv);

    // 2) RoPE cos/sin table
    rope_table_kernel<<<(TSEQ * 32 + 255) / 256, 256>>>();

    // 3) RoPE apply + layout; K,V stored tf32
    rope_apply_kernel<<<(BATCH * TSEQ * NHEADS * 32) / 256, 256>>>();

    // 4) causal flash attention (tf32 mma) -> writes tf32-permuted O into g_attnt
    flash_mma_kernel<<<dim3(TSEQ / FBQ, NHEADS, BATCH), 256>>>();

    // 5) out = attn @ proj_w^T + proj_b (tf32 mma)
    tf32_gemm_kernel<DMODEL><<<dim3(DMODEL / 128, ROWS / 128), 256, GEMM_SMEM_B>>>(
        d_attnt, d_wprojt, proj_b, out);
}

// round 12
// speedup vs baseline: 3.5420x; 1.0124x over previous
#include <cuda_runtime.h>
#include <math.h>
#include <cstdint>

// Problem constants
#define BATCH 2
#define TSEQ  2048
#define DMODEL 1024
#define NHEADS 16
#define HDIM  64
#define ROWS (BATCH * TSEQ)          // 4096
#define QKV_N (3 * DMODEL)           // 3072

// ---------------- scratch (no allocation allowed) ----------------
__device__ float g_qkv[ROWS * QKV_N];               // [B*T, 3*D]
__device__ float g_q[BATCH * NHEADS * TSEQ * HDIM]; // [B,H,T,Dh] fp32
__device__ uint32_t g_kt[BATCH * NHEADS * TSEQ * HDIM]; // tf32
__device__ uint32_t g_vt[BATCH * NHEADS * TSEQ * HDIM]; // tf32
__device__ float g_cs[TSEQ * 32 * 2];               // cos,sin per (t, freq)
// tf32 column-permuted operands for the GEMMs
__device__ uint32_t g_xt[ROWS * DMODEL];
__device__ uint32_t g_wqkvt[QKV_N * DMODEL];
__device__ uint32_t g_wprojt[DMODEL * DMODEL];
__device__ uint32_t g_attnt[ROWS * DMODEL];         // flash writes tf32-permuted O here

// ================= helpers =================
__device__ __forceinline__ uint32_t s2u(const void* p) {
    uint32_t a;
    asm("{ .reg .u64 t; cvta.to.shared.u64 t, %1; cvt.u32.u64 %0, t; }"
        : "=r"(a) : "l"(p));
    return a;
}
__device__ __forceinline__ uint32_t f2tf32(float f) {
    uint32_t r;
    asm("cvt.rna.tf32.f32 %0, %1;" : "=r"(r) : "f"(f));
    return r;
}
__device__ __forceinline__ float ex2(float x) {
    float y;
    asm("ex2.approx.ftz.f32 %0, %1;" : "=f"(y) : "f"(x));
    return y;
}
__device__ __forceinline__ void cp16(uint32_t dst, const void* src) {
    asm volatile("cp.async.cg.shared.global [%0], [%1], 16;" :: "r"(dst), "l"(src));
}
__device__ __forceinline__ void mma8(float* d, const uint32_t* a, uint32_t b0, uint32_t b1) {
    asm volatile(
        "mma.sync.aligned.m16n8k8.row.col.f32.tf32.tf32.f32 "
        "{%0,%1,%2,%3}, {%4,%5,%6,%7}, {%8,%9}, {%0,%1,%2,%3};"
        : "+f"(d[0]), "+f"(d[1]), "+f"(d[2]), "+f"(d[3])
        : "r"(a[0]), "r"(a[1]), "r"(a[2]), "r"(a[3]), "r"(b0), "r"(b1));
}

// ---------------- convert f32 -> tf32 with per-32-block column permutation -----------
__global__ void convert_permute_kernel(const float* __restrict__ src,
                                       uint32_t* __restrict__ dst, int n)
{
    int idx = blockIdx.x * blockDim.x + threadIdx.x;
    if (idx >= n) return;
    int p = idx & 31;
    int c = (p & 7) * 4 + (p >> 3);
    int base = idx & ~31;
    dst[idx] = f2tf32(src[base + c]);
}

// ================= tf32 mma GEMM: C[M,NCOLS] = A[M,1024] @ W[NCOLS,1024]^T + bias ======
// 3-stage cp.async pipeline, COMPILE-TIME stage indices (all smem addrs = base+imm).
#define GSTR 36
#define GTILEW (128 * GSTR)                      // words per tile
#define GSTAGEW (2 * GTILEW)                     // words per stage (A+B)
#define GSTAGES 3
#define GEMM_SMEM_B (GSTAGES * GSTAGEW * 4)      // 110592 bytes

template<int NCOLS>
__global__ __launch_bounds__(256, 2) void tf32_gemm_kernel(
    const uint32_t* __restrict__ A,
    const uint32_t* __restrict__ W,
    const float* __restrict__ bias,
    float* __restrict__ C)
{
    extern __shared__ uint32_t smw[];
    const int tid = threadIdx.x;
    const int wid = tid >> 5, lane = tid & 31;
    const int g = lane >> 2, tg = lane & 3;
    const int wm = wid & 3, wn = wid >> 2;
    const int bm = blockIdx.y * 128, bn = blockIdx.x * 128;

    float acc[2][8][4];
    #pragma unroll
    for (int t = 0; t < 2; t++)
        #pragma unroll
        for (int nt = 0; nt < 8; nt++)
            #pragma unroll
            for (int j = 0; j < 4; j++) acc[t][nt][j] = 0.f;

    const int fo = 8 * (tg ^ (g & 3));

    // -------- hoisted cp.async destination addresses (stage 0; stage adds imm) -------
    uint32_t aDst[4], bDst[4];
    const uint32_t* aSrcB[4];
    const uint32_t* bSrcB[4];
    #pragma unroll
    for (int i = 0; i < 4; i++) {
        const int idx = i * 256 + tid;
        const int row = idx >> 3, q = idx & 7;
        const int sq = q ^ ((row & 3) << 1);
        aDst[i] = s2u(smw + row * GSTR + sq * 4);
        bDst[i] = aDst[i] + GTILEW * 4;
        aSrcB[i] = A + (size_t)(bm + row) * DMODEL + q * 4;
        bSrcB[i] = W + (size_t)(bn + row) * DMODEL + q * 4;
    }
    // -------- hoisted fragment base pointers (stage 0) --------
    const uint32_t* aF = smw + (wm * 32 + g) * GSTR + fo;
    const uint32_t* bF = smw + GTILEW + (wn * 64 + g) * GSTR + fo;

    #define LOAD_CHUNK(c_, S_) do {                                                \
        _Pragma("unroll")                                                          \
        for (int i_ = 0; i_ < 4; i_++) {                                           \
            cp16(aDst[i_] + (S_) * GSTAGEW * 4, aSrcB[i_] + (c_) * 32);            \
            cp16(bDst[i_] + (S_) * GSTAGEW * 4, bSrcB[i_] + (c_) * 32);            \
        }                                                                          \
        asm volatile("cp.async.commit_group;" ::: "memory");                       \
    } while (0)

    #define GBODY(c_, S_, PF_) do {                                                \
        asm volatile("cp.async.wait_group 1;" ::: "memory");                       \
        __syncthreads();                                                           \
        if (PF_) { LOAD_CHUNK((c_) + 2, ((S_) + 2) % GSTAGES); }                   \
        else { asm volatile("cp.async.commit_group;" ::: "memory"); }              \
        const uint32_t* as_ = aF + (S_) * GSTAGEW;                                 \
        const uint32_t* bs_ = bF + (S_) * GSTAGEW;                                 \
        uint32_t a_[2][4][4];                                                      \
        _Pragma("unroll")                                                          \
        for (int t_ = 0; t_ < 2; t_++) {                                           \
            uint4 x0 = *(const uint4*)(as_ + t_ * 16 * GSTR);                      \
            uint4 x1 = *(const uint4*)(as_ + t_ * 16 * GSTR + 4);                  \
            uint4 y0 = *(const uint4*)(as_ + (t_ * 16 + 8) * GSTR);                \
            uint4 y1 = *(const uint4*)(as_ + (t_ * 16 + 8) * GSTR + 4);            \
            a_[t_][0][0]=x0.x; a_[t_][0][1]=y0.x; a_[t_][0][2]=x0.y; a_[t_][0][3]=y0.y; \
            a_[t_][1][0]=x0.z; a_[t_][1][1]=y0.z; a_[t_][1][2]=x0.w; a_[t_][1][3]=y0.w; \
            a_[t_][2][0]=x1.x; a_[t_][2][1]=y1.x; a_[t_][2][2]=x1.y; a_[t_][2][3]=y1.y; \
            a_[t_][3][0]=x1.z; a_[t_][3][1]=y1.z; a_[t_][3][2]=x1.w; a_[t_][3][3]=y1.w; \
        }                                                                          \
        _Pragma("unroll")                                                          \
        for (int nt_ = 0; nt_ < 8; nt_++) {                                        \
            uint4 b0 = *(const uint4*)(bs_ + nt_ * 8 * GSTR);                      \
            uint4 b1 = *(const uint4*)(bs_ + nt_ * 8 * GSTR + 4);                  \
            mma8(acc[0][nt_], a_[0][0], b0.x, b0.y);                               \
            mma8(acc[1][nt_], a_[1][0], b0.x, b0.y);                               \
            mma8(acc[0][nt_], a_[0][1], b0.z, b0.w);                               \
            mma8(acc[1][nt_], a_[1][1], b0.z, b0.w);                               \
            mma8(acc[0][nt_], a_[0][2], b1.x, b1.y);                               \
            mma8(acc[1][nt_], a_[1][2], b1.x, b1.y);                               \
            mma8(acc[0][nt_], a_[0][3], b1.z, b1.w);                               \
            mma8(acc[1][nt_], a_[1][3], b1.z, b1.w);                               \
        }                                                                          \
    } while (0)

    // prologue: 2 chunks in flight
    LOAD_CHUNK(0, 0);
    LOAD_CHUNK(1, 1);

    #pragma unroll 1
    for (int cb = 0; cb < 30; cb += 3) {
        GBODY(cb + 0, 0, 1);
        GBODY(cb + 1, 1, 1);
        GBODY(cb + 2, 2, 1);
    }
    GBODY(30, 0, 0);
    GBODY(31, 1, 0);
    #undef LOAD_CHUNK
    #undef GBODY

    // epilogue: + bias, write float2 pairs
    #pragma unroll
    for (int t = 0; t < 2; t++) {
        const int r0 = bm + wm * 32 + t * 16 + g;
        #pragma unroll
        for (int nt = 0; nt < 8; nt++) {
            const int cc = bn + wn * 64 + nt * 8 + 2 * tg;
            const float b0 = bias[cc], b1 = bias[cc + 1];
            *(float2*)(C + (size_t)r0 * NCOLS + cc) =
                make_float2(acc[t][nt][0] + b0, acc[t][nt][1] + b1);
            *(float2*)(C + (size_t)(r0 + 8) * NCOLS + cc) =
                make_float2(acc[t][nt][2] + b0, acc[t][nt][3] + b1);
        }
    }
}

// ---------------- RoPE table ----------------
__global__ void rope_table_kernel()
{
    int idx = blockIdx.x * blockDim.x + threadIdx.x;
    if (idx >= TSEQ * 32) return;
    int t = idx >> 5;
    int j = idx & 31;
    float invf = powf(10000.0f, -((float)(2 * j) / 64.0f));
    float angle = (float)t * invf;
    double a = (double)angle;
    double s, c;
    sincos(a, &s, &c);
    g_cs[idx * 2 + 0] = (float)c;
    g_cs[idx * 2 + 1] = (float)s;
}

// ---------------- RoPE apply + transpose; K,V stored as tf32 ----------------
__global__ void rope_apply_kernel()
{
    int idx = blockIdx.x * blockDim.x + threadIdx.x;
    if (idx >= BATCH * TSEQ * NHEADS * 32) return;
    int j = idx & 31;
    int h = (idx >> 5) & (NHEADS - 1);
    int t = (idx >> 9) & (TSEQ - 1);
    int b = idx >> 20;

    int row = b * TSEQ + t;
    const float* base = g_qkv + (size_t)row * QKV_N + h * HDIM;

    float c  = g_cs[(t * 32 + j) * 2 + 0];
    float sn = g_cs[(t * 32 + j) * 2 + 1];

    float q1 = base[j],          q2 = base[j + 32];
    float k1 = base[DMODEL + j], k2 = base[DMODEL + j + 32];

    size_t od = (((size_t)b * NHEADS + h) * TSEQ + t) * HDIM;
    g_q[od + j]      = q1 * c - q2 * sn;
    g_q[od + j + 32] = q2 * c + q1 * sn;
    g_kt[od + j]      = f2tf32(k1 * c - k2 * sn);
    g_kt[od + j + 32] = f2tf32(k2 * c + k1 * sn);
    g_vt[od + j]      = f2tf32(base[2 * DMODEL + j]);
    g_vt[od + j + 32] = f2tf32(base[2 * DMODEL + j + 32]);
}

// ================= flash attention: tf32 mma.sync, compile-time stages ==========
#define FBQ 128
#define FBKV 32
#define KSTR 68
#define VSTR 72

__global__ __launch_bounds__(256, 2) void flash_mma_kernel()
{
    const int tid  = threadIdx.x;
    const int w    = tid >> 5;
    const int lane = tid & 31;
    const int g    = lane >> 2;
    const int tg   = lane & 3;
    const int qt = (gridDim.x - 1) - blockIdx.x;
    const int h  = blockIdx.y;
    const int b  = blockIdx.z;
    const int qb = qt * FBQ;
    const int wb = qb + w * 16;
    const int rA = wb + g;
    const int rB = rA + 8;

    const size_t bh = ((size_t)b * NHEADS + h) * TSEQ * HDIM;
    const float NEG = __int_as_float(0xff800000);

    __shared__ uint32_t Ks[2][FBKV * KSTR];
    __shared__ uint32_t Vs[2][FBKV * VSTR];

    const float pre = 0.125f * 1.4426950408889634f;
    uint32_t qf[8][4];
    {
        const float* q0 = g_q + bh + (size_t)rA * HDIM;
        const float* q1 = g_q + bh + (size_t)rB * HDIM;
        #pragma unroll
        for (int kc = 0; kc < 8; kc++) {
            qf[kc][0] = f2tf32(q0[kc * 8 + tg]     * pre);
            qf[kc][1] = f2tf32(q1[kc * 8 + tg]     * pre);
            qf[kc][2] = f2tf32(q0[kc * 8 + tg + 4] * pre);
            qf[kc][3] = f2tf32(q1[kc * 8 + tg + 4] * pre);
        }
    }

    float o[8][4];
    #pragma unroll
    for (int n = 0; n < 8; n++)
        #pragma unroll
        for (int j = 0; j < 4; j++) o[n][j] = 0.f;
    float mA = NEG, mB = NEG, lA = 0.f, lB = 0.f;

    const int ntiles = qb / FBKV + 4;      // = 4*qt + 4, always even

    // hoisted cp.async destinations (stage 0)
    uint32_t kDst[2], vDst[2];
    const uint32_t* kSrcB[2];
    const uint32_t* vSrcB[2];
    #pragma unroll
    for (int i = 0; i < 2; i++) {
        const int idx = i * 256 + tid;
        const int key = idx >> 4, c = idx & 15;
        kDst[i] = s2u(&Ks[0][key * KSTR + c * 4]);
        vDst[i] = s2u(&Vs[0][key * VSTR + c * 4]);
        kSrcB[i] = g_kt + bh + idx * 4;
        vSrcB[i] = g_vt + bh + idx * 4;
    }

    #define FLOAD(t0_, S_) do {                                                    \
        _Pragma("unroll")                                                          \
        for (int i_ = 0; i_ < 2; i_++) {                                           \
            cp16(kDst[i_] + (S_) * (FBKV * KSTR * 4), kSrcB[i_] + (t0_) * FBKV * HDIM); \
            cp16(vDst[i_] + (S_) * (FBKV * VSTR * 4), vSrcB[i_] + (t0_) * FBKV * HDIM); \
        }                                                                          \
        asm volatile("cp.async.commit_group;" ::: "memory");                       \
    } while (0)

    #define FBODY(t0_, S_) do {                                                    \
        const int j0 = (t0_) * FBKV;                                               \
        asm volatile("cp.async.wait_group 0;" ::: "memory");                       \
        __syncthreads();                                                           \
        if ((t0_) + 1 < ntiles) FLOAD((t0_) + 1, ((S_) + 1) & 1);                  \
        if (j0 <= wb) {                                                            \
            const uint32_t* ksm = Ks[S_];                                          \
            const uint32_t* vsm = Vs[S_];                                          \
            float s[4][4];                                                         \
            _Pragma("unroll")                                                      \
            for (int nt = 0; nt < 4; nt++) {                                       \
                s[nt][0] = 0.f; s[nt][1] = 0.f; s[nt][2] = 0.f; s[nt][3] = 0.f;    \
            }                                                                      \
            _Pragma("unroll")                                                      \
            for (int kc = 0; kc < 8; kc++) {                                       \
                _Pragma("unroll")                                                  \
                for (int nt = 0; nt < 4; nt++) {                                   \
                    uint32_t b0 = ksm[(nt * 8 + g) * KSTR + kc * 8 + tg];          \
                    uint32_t b1 = ksm[(nt * 8 + g) * KSTR + kc * 8 + tg + 4];      \
                    mma8(s[nt], qf[kc], b0, b1);                                   \
                }                                                                  \
            }                                                                      \
            float mtA = mA, mtB = mB;                                              \
            _Pragma("unroll")                                                      \
            for (int nt = 0; nt < 4; nt++) {                                       \
                const int jc = j0 + nt * 8 + 2 * tg;                               \
                s[nt][0] = (jc     <= rA) ? s[nt][0] : NEG;                        \
                s[nt][1] = (jc + 1 <= rA) ? s[nt][1] : NEG;                        \
                s[nt][2] = (jc     <= rB) ? s[nt][2] : NEG;                        \
                s[nt][3] = (jc + 1 <= rB) ? s[nt][3] : NEG;                        \
                mtA = fmaxf(mtA, fmaxf(s[nt][0], s[nt][1]));                       \
                mtB = fmaxf(mtB, fmaxf(s[nt][2], s[nt][3]));                       \
            }                                                                      \
            mtA = fmaxf(mtA, __shfl_xor_sync(0xffffffffu, mtA, 1));                \
            mtA = fmaxf(mtA, __shfl_xor_sync(0xffffffffu, mtA, 2));                \
            mtB = fmaxf(mtB, __shfl_xor_sync(0xffffffffu, mtB, 1));                \
            mtB = fmaxf(mtB, __shfl_xor_sync(0xffffffffu, mtB, 2));                \
            const float corrA = ex2(mA - mtA);                                     \
            const float corrB = ex2(mB - mtB);                                     \
            mA = mtA; mB = mtB;                                                    \
            uint32_t pf[4][4];                                                     \
            float sumA = 0.f, sumB = 0.f;                                          \
            _Pragma("unroll")                                                      \
            for (int nt = 0; nt < 4; nt++) {                                       \
                pf[nt][0] = f2tf32(ex2(s[nt][0] - mtA));                           \
                pf[nt][1] = f2tf32(ex2(s[nt][1] - mtA));                           \
                pf[nt][2] = f2tf32(ex2(s[nt][2] - mtB));                           \
                pf[nt][3] = f2tf32(ex2(s[nt][3] - mtB));                           \
                sumA += __uint_as_float(pf[nt][0]) + __uint_as_float(pf[nt][1]);   \
                sumB += __uint_as_float(pf[nt][2]) + __uint_as_float(pf[nt][3]);   \
            }                                                                      \
            sumA += __shfl_xor_sync(0xffffffffu, sumA, 1);                         \
            sumA += __shfl_xor_sync(0xffffffffu, sumA, 2);                         \
            sumB += __shfl_xor_sync(0xffffffffu, sumB, 1);                         \
            sumB += __shfl_xor_sync(0xffffffffu, sumB, 2);                         \
            lA = lA * corrA + sumA;                                                \
            lB = lB * corrB + sumB;                                                \
            _Pragma("unroll")                                                      \
            for (int n = 0; n < 8; n++) {                                          \
                o[n][0] *= corrA; o[n][1] *= corrA;                                \
                o[n][2] *= corrB; o[n][3] *= corrB;                                \
            }                                                                      \
            const int srcL = tg >> 1;                                              \
            _Pragma("unroll")                                                      \
            for (int kc = 0; kc < 4; kc++) {                                       \
                uint32_t v0 = __shfl_sync(0xffffffffu, pf[kc][0], srcL, 4);        \
                uint32_t v1 = __shfl_sync(0xffffffffu, pf[kc][1], srcL, 4);        \
                uint32_t v2 = __shfl_sync(0xffffffffu, pf[kc][0], srcL + 2, 4);    \
                uint32_t v3 = __shfl_sync(0xffffffffu, pf[kc][1], srcL + 2, 4);    \
                uint32_t u0 = __shfl_sync(0xffffffffu, pf[kc][2], srcL, 4);        \
                uint32_t u1 = __shfl_sync(0xffffffffu, pf[kc][3], srcL, 4);        \
                uint32_t u2 = __shfl_sync(0xffffffffu, pf[kc][2], srcL + 2, 4);    \
                uint32_t u3 = __shfl_sync(0xffffffffu, pf[kc][3], srcL + 2, 4);    \
                uint32_t af[4];                                                    \
                af[0] = (tg & 1) ? v1 : v0;                                        \
                af[1] = (tg & 1) ? u1 : u0;                                        \
                af[2] = (tg & 1) ? v3 : v2;                                        \
                af[3] = (tg & 1) ? u3 : u2;                                        \
                _Pragma("unroll")                                                  \
                for (int nt2 = 0; nt2 < 8; nt2++) {                                \
                    uint32_t b0 = vsm[(kc * 8 + tg) * VSTR + nt2 * 8 + g];         \
                    uint32_t b1 = vsm[(kc * 8 + tg + 4) * VSTR + nt2 * 8 + g];     \
                    mma8(o[nt2], af, b0, b1);                                      \
                }                                                                  \
            }                                                                      \
        }                                                                          \
    } while (0)

    FLOAD(0, 0);

    #pragma unroll 1
    for (int t0 = 0; t0 < ntiles; t0 += 2) {
        FBODY(t0, 0);
        FBODY(t0 + 1, 1);
    }
    #undef FLOAD
    #undef FBODY

    // ---- epilogue: O/l -> tf32 column-permuted rows of g_attnt [B*T, 1024] ----
    const float iA = 1.f / lA;
    const float iB = 1.f / lB;
    uint32_t* opA = g_attnt + ((size_t)b * TSEQ + rA) * DMODEL + h * HDIM;
    uint32_t* opB = g_attnt + ((size_t)b * TSEQ + rB) * DMODEL + h * HDIM;
    #pragma unroll
    for (int nt2 = 0; nt2 < 8; nt2++) {
        const int cc = nt2 * 8 + 2 * tg;
        const int blk = (cc >> 5) << 5;
        const int c0 = cc & 31, c1 = (cc + 1) & 31;
        const int p0 = (c0 & 3) * 8 + (c0 >> 2);
        const int p1 = (c1 & 3) * 8 + (c1 >> 2);
        opA[blk + p0] = f2tf32(o[nt2][0] * iA);
        opA[blk + p1] = f2tf32(o[nt2][1] * iA);
        opB[blk + p0] = f2tf32(o[nt2][2] * iB);
        opB[blk + p1] = f2tf32(o[nt2][3] * iB);
    }
}

// ---------------- launch ----------------
extern "C" void kernel_launch(void* const* d_in, const int* in_sizes, int n_in,
                              void* d_out, int out_size)
{
    const float* x      = (const float*)d_in[0];
    const float* qkv_w  = (const float*)d_in[1];
    const float* qkv_b  = (const float*)d_in[2];
    const float* proj_w = (const float*)d_in[3];
    const float* proj_b = (const float*)d_in[4];
    float* out = (float*)d_out;

    cudaFuncSetAttribute(tf32_gemm_kernel<QKV_N>,
                         cudaFuncAttributeMaxDynamicSharedMemorySize, GEMM_SMEM_B);
    cudaFuncSetAttribute(tf32_gemm_kernel<DMODEL>,
                         cudaFuncAttributeMaxDynamicSharedMemorySize, GEMM_SMEM_B);

    uint32_t *d_xt, *d_wqkvt, *d_wprojt, *d_attnt;
    float *d_qkv;
    cudaGetSymbolAddress((void**)&d_xt, g_xt);
    cudaGetSymbolAddress((void**)&d_wqkvt, g_wqkvt);
    cudaGetSymbolAddress((void**)&d_wprojt, g_wprojt);
    cudaGetSymbolAddress((void**)&d_attnt, g_attnt);
    cudaGetSymbolAddress((void**)&d_qkv, g_qkv);

    // 0) convert+permute GEMM operands to tf32
    convert_permute_kernel<<<(ROWS * DMODEL) / 256, 256>>>(x, d_xt, ROWS * DMODEL);
    convert_permute_kernel<<<(QKV_N * DMODEL) / 256, 256>>>(qkv_w, d_wqkvt, QKV_N * DMODEL);
    convert_permute_kernel<<<(DMODEL * DMODEL) / 256, 256>>>(proj_w, d_wprojt, DMODEL * DMODEL);

    // 1) QKV = x @ qkv_w^T + qkv_b  (tf32 mma)
    tf32_gemm_kernel<QKV_N><<<dim3(QKV_N / 128, ROWS / 128), 256, GEMM_SMEM_B>>>(
        d_xt, d_wqkvt, qkv_b, d_qkv);

    // 2) RoPE cos/sin table
    rope_table_kernel<<<(TSEQ * 32 + 255) / 256, 256>>>();

    // 3) RoPE apply + layout; K,V stored tf32
    rope_apply_kernel<<<(BATCH * TSEQ * NHEADS * 32) / 256, 256>>>();

    // 4) causal flash attention (tf32 mma) -> writes tf32-permuted O into g_attnt
    flash_mma_kernel<<<dim3(TSEQ / FBQ, NHEADS, BATCH), 256>>>();

    // 5) out = attn @ proj_w^T + proj_b (tf32 mma)
    tf32_gemm_kernel<DMODEL><<<dim3(DMODEL / 128, ROWS / 128), 256, GEMM_SMEM_B>>>(
        d_attnt, d_wprojt, proj_b, out);
}

// round 13
// speedup vs baseline: 3.6284x; 1.0244x over previous
#include <cuda_runtime.h>
#include <math.h>
#include <cstdint>

// Problem constants
#define BATCH 2
#define TSEQ  2048
#define DMODEL 1024
#define NHEADS 16
#define HDIM  64
#define ROWS (BATCH * TSEQ)          // 4096
#define QKV_N (3 * DMODEL)           // 3072

// ---------------- scratch (no allocation allowed) ----------------
__device__ uint32_t g_qt[BATCH * NHEADS * TSEQ * HDIM]; // tf32, pre-scaled by 1/8*log2e
__device__ uint32_t g_kt[BATCH * NHEADS * TSEQ * HDIM]; // tf32
__device__ uint32_t g_vt[BATCH * NHEADS * TSEQ * HDIM]; // tf32
__device__ float g_cs[TSEQ * 32 * 2];               // cos,sin per (t, freq)
// tf32 column-permuted operands for the GEMMs
__device__ uint32_t g_xt[ROWS * DMODEL];
__device__ uint32_t g_wqkvt[QKV_N * DMODEL];
__device__ uint32_t g_wprojt[DMODEL * DMODEL];
__device__ uint32_t g_attnt[ROWS * DMODEL];         // flash writes tf32-permuted O here

// ================= helpers =================
__device__ __forceinline__ uint32_t s2u(const void* p) {
    uint32_t a;
    asm("{ .reg .u64 t; cvta.to.shared.u64 t, %1; cvt.u32.u64 %0, t; }"
        : "=r"(a) : "l"(p));
    return a;
}
__device__ __forceinline__ uint32_t f2tf32(float f) {
    uint32_t r;
    asm("cvt.rna.tf32.f32 %0, %1;" : "=r"(r) : "f"(f));
    return r;
}
__device__ __forceinline__ float ex2(float x) {
    float y;
    asm("ex2.approx.ftz.f32 %0, %1;" : "=f"(y) : "f"(x));
    return y;
}
__device__ __forceinline__ void cp16(uint32_t dst, const void* src) {
    asm volatile("cp.async.cg.shared.global [%0], [%1], 16;" :: "r"(dst), "l"(src));
}
__device__ __forceinline__ void mma8(float* d, const uint32_t* a, uint32_t b0, uint32_t b1) {
    asm volatile(
        "mma.sync.aligned.m16n8k8.row.col.f32.tf32.tf32.f32 "
        "{%0,%1,%2,%3}, {%4,%5,%6,%7}, {%8,%9}, {%0,%1,%2,%3};"
        : "+f"(d[0]), "+f"(d[1]), "+f"(d[2]), "+f"(d[3])
        : "r"(a[0]), "r"(a[1]), "r"(a[2]), "r"(a[3]), "r"(b0), "r"(b1));
}

// ---------------- convert f32 -> tf32 with per-32-block column permutation -----------
__global__ void convert_permute_kernel(const float* __restrict__ src,
                                       uint32_t* __restrict__ dst, int n)
{
    int idx = blockIdx.x * blockDim.x + threadIdx.x;
    if (idx >= n) return;
    int p = idx & 31;
    int c = (p & 7) * 4 + (p >> 3);
    int base = idx & ~31;
    dst[idx] = f2tf32(src[base + c]);
}

// ================= tf32 mma GEMM =================
// MODE 0: C = A @ W^T + bias (fp32 out)
// MODE 1: QKV with fused RoPE epilogue -> g_qt/g_kt/g_vt in [B,H,T,Dh] (tf32)
#define GSTR 36
#define GTILEW (128 * GSTR)
#define GSTAGEW (2 * GTILEW)
#define GSTAGES 3
#define GEMM_SMEM_B (GSTAGES * GSTAGEW * 4)      // 110592 bytes

template<int NCOLS, int MODE>
__global__ __launch_bounds__(256, 2) void tf32_gemm_kernel(
    const uint32_t* __restrict__ A,
    const uint32_t* __restrict__ W,
    const float* __restrict__ bias,
    float* __restrict__ C)
{
    extern __shared__ uint32_t smw[];
    const int tid = threadIdx.x;
    const int wid = tid >> 5, lane = tid & 31;
    const int g = lane >> 2, tg = lane & 3;
    const int wm = wid & 3, wn = wid >> 2;
    const int bm = blockIdx.y * 128, bn = blockIdx.x * 128;

    float acc[2][8][4];
    #pragma unroll
    for (int t = 0; t < 2; t++)
        #pragma unroll
        for (int nt = 0; nt < 8; nt++)
            #pragma unroll
            for (int j = 0; j < 4; j++) acc[t][nt][j] = 0.f;

    const int fo = 8 * (tg ^ (g & 3));

    uint32_t aDst[4], bDst[4];
    const uint32_t* aSrcB[4];
    const uint32_t* bSrcB[4];
    #pragma unroll
    for (int i = 0; i < 4; i++) {
        const int idx = i * 256 + tid;
        const int row = idx >> 3, q = idx & 7;
        const int sq = q ^ ((row & 3) << 1);
        aDst[i] = s2u(smw + row * GSTR + sq * 4);
        bDst[i] = aDst[i] + GTILEW * 4;
        aSrcB[i] = A + (size_t)(bm + row) * DMODEL + q * 4;
        bSrcB[i] = W + (size_t)(bn + row) * DMODEL + q * 4;
    }
    const uint32_t* aF = smw + (wm * 32 + g) * GSTR + fo;
    const uint32_t* bF = smw + GTILEW + (wn * 64 + g) * GSTR + fo;

    #define LOAD_CHUNK(c_, S_) do {                                                \
        _Pragma("unroll")                                                          \
        for (int i_ = 0; i_ < 4; i_++) {                                           \
            cp16(aDst[i_] + (S_) * GSTAGEW * 4, aSrcB[i_] + (c_) * 32);            \
            cp16(bDst[i_] + (S_) * GSTAGEW * 4, bSrcB[i_] + (c_) * 32);            \
        }                                                                          \
        asm volatile("cp.async.commit_group;" ::: "memory");                       \
    } while (0)

    #define GBODY(c_, S_, PF_) do {                                                \
        asm volatile("cp.async.wait_group 1;" ::: "memory");                       \
        __syncthreads();                                                           \
        if (PF_) { LOAD_CHUNK((c_) + 2, ((S_) + 2) % GSTAGES); }                   \
        else { asm volatile("cp.async.commit_group;" ::: "memory"); }              \
        const uint32_t* as_ = aF + (S_) * GSTAGEW;                                 \
        const uint32_t* bs_ = bF + (S_) * GSTAGEW;                                 \
        uint32_t a_[2][4][4];                                                      \
        _Pragma("unroll")                                                          \
        for (int t_ = 0; t_ < 2; t_++) {                                           \
            uint4 x0 = *(const uint4*)(as_ + t_ * 16 * GSTR);                      \
            uint4 x1 = *(const uint4*)(as_ + t_ * 16 * GSTR + 4);                  \
            uint4 y0 = *(const uint4*)(as_ + (t_ * 16 + 8) * GSTR);                \
            uint4 y1 = *(const uint4*)(as_ + (t_ * 16 + 8) * GSTR + 4);            \
            a_[t_][0][0]=x0.x; a_[t_][0][1]=y0.x; a_[t_][0][2]=x0.y; a_[t_][0][3]=y0.y; \
            a_[t_][1][0]=x0.z; a_[t_][1][1]=y0.z; a_[t_][1][2]=x0.w; a_[t_][1][3]=y0.w; \
            a_[t_][2][0]=x1.x; a_[t_][2][1]=y1.x; a_[t_][2][2]=x1.y; a_[t_][2][3]=y1.y; \
            a_[t_][3][0]=x1.z; a_[t_][3][1]=y1.z; a_[t_][3][2]=x1.w; a_[t_][3][3]=y1.w; \
        }                                                                          \
        _Pragma("unroll")                                                          \
        for (int nt_ = 0; nt_ < 8; nt_++) {                                        \
            uint4 b0 = *(const uint4*)(bs_ + nt_ * 8 * GSTR);                      \
            uint4 b1 = *(const uint4*)(bs_ + nt_ * 8 * GSTR + 4);                  \
            mma8(acc[0][nt_], a_[0][0], b0.x, b0.y);                               \
            mma8(acc[1][nt_], a_[1][0], b0.x, b0.y);                               \
            mma8(acc[0][nt_], a_[0][1], b0.z, b0.w);                               \
            mma8(acc[1][nt_], a_[1][1], b0.z, b0.w);                               \
            mma8(acc[0][nt_], a_[0][2], b1.x, b1.y);                               \
            mma8(acc[1][nt_], a_[1][2], b1.x, b1.y);                               \
            mma8(acc[0][nt_], a_[0][3], b1.z, b1.w);                               \
            mma8(acc[1][nt_], a_[1][3], b1.z, b1.w);                               \
        }                                                                          \
    } while (0)

    LOAD_CHUNK(0, 0);
    LOAD_CHUNK(1, 1);

    #pragma unroll 1
    for (int cb = 0; cb < 30; cb += 3) {
        GBODY(cb + 0, 0, 1);
        GBODY(cb + 1, 1, 1);
        GBODY(cb + 2, 2, 1);
    }
    GBODY(30, 0, 0);
    GBODY(31, 1, 0);
    #undef LOAD_CHUNK
    #undef GBODY

    if (MODE == 0) {
        // plain epilogue: + bias, fp32 out
        #pragma unroll
        for (int t = 0; t < 2; t++) {
            const int r0 = bm + wm * 32 + t * 16 + g;
            #pragma unroll
            for (int nt = 0; nt < 8; nt++) {
                const int cc = bn + wn * 64 + nt * 8 + 2 * tg;
                const float b0 = bias[cc], b1 = bias[cc + 1];
                *(float2*)(C + (size_t)r0 * NCOLS + cc) =
                    make_float2(acc[t][nt][0] + b0, acc[t][nt][1] + b1);
                *(float2*)(C + (size_t)(r0 + 8) * NCOLS + cc) =
                    make_float2(acc[t][nt][2] + b0, acc[t][nt][3] + b1);
            }
        }
    } else {
        // fused RoPE epilogue. Warp n-tile (64 wide) = one head; pair c <-> c+32
        // lives in acc[nt] / acc[nt+4] of the SAME thread.
        const int gcb = bn + wn * 64;           // warp col base
        const int region = gcb >> 10;           // 0=Q 1=K 2=V
        const int h = (gcb & 1023) >> 6;
        const int bb = bm >> 11;                // batch
        const float pre = 0.125f * 1.4426950408889634f;
        const float2* cs2 = (const float2*)g_cs;

        #pragma unroll
        for (int t = 0; t < 2; t++) {
            const int ta = (bm & 2047) + wm * 32 + t * 16 + g;
            const int tb = ta + 8;
            const size_t odA = (((size_t)bb * NHEADS + h) * TSEQ + ta) * HDIM;
            const size_t odB = odA + 8 * HDIM;
            #pragma unroll
            for (int nt = 0; nt < 4; nt++) {
                const int c0 = nt * 8 + 2 * tg;          // < 32
                const float bl0 = bias[gcb + c0],      bl1 = bias[gcb + c0 + 1];
                const float bh0 = bias[gcb + c0 + 32], bh1 = bias[gcb + c0 + 33];
                // rows A (=ta): acc[..][0..1]; rows B (=tb): acc[..][2..3]
                float xA0 = acc[t][nt][0] + bl0,     xA1 = acc[t][nt][1] + bl1;
                float xB0 = acc[t][nt][2] + bl0,     xB1 = acc[t][nt][3] + bl1;
                float yA0 = acc[t][nt + 4][0] + bh0, yA1 = acc[t][nt + 4][1] + bh1;
                float yB0 = acc[t][nt + 4][2] + bh0, yB1 = acc[t][nt + 4][3] + bh1;

                if (region == 2) {
                    g_vt[odA + c0]      = f2tf32(xA0);
                    g_vt[odA + c0 + 1]  = f2tf32(xA1);
                    g_vt[odA + c0 + 32] = f2tf32(yA0);
                    g_vt[odA + c0 + 33] = f2tf32(yA1);
                    g_vt[odB + c0]      = f2tf32(xB0);
                    g_vt[odB + c0 + 1]  = f2tf32(xB1);
                    g_vt[odB + c0 + 32] = f2tf32(yB0);
                    g_vt[odB + c0 + 33] = f2tf32(yB1);
                } else {
                    float2 ca0 = cs2[ta * 32 + c0];
                    float2 ca1 = cs2[ta * 32 + c0 + 1];
                    float2 cb0 = cs2[tb * 32 + c0];
                    float2 cb1 = cs2[tb * 32 + c0 + 1];
                    // lo = x*cos - y*sin ; hi = y*cos + x*sin
                    float loA0 = xA0 * ca0.x - yA0 * ca0.y, hiA0 = yA0 * ca0.x + xA0 * ca0.y;
                    float loA1 = xA1 * ca1.x - yA1 * ca1.y, hiA1 = yA1 * ca1.x + xA1 * ca1.y;
                    float loB0 = xB0 * cb0.x - yB0 * cb0.y, hiB0 = yB0 * cb0.x + xB0 * cb0.y;
                    float loB1 = xB1 * cb1.x - yB1 * cb1.y, hiB1 = yB1 * cb1.x + xB1 * cb1.y;
                    if (region == 0) {
                        g_qt[odA + c0]      = f2tf32(loA0 * pre);
                        g_qt[odA + c0 + 1]  = f2tf32(loA1 * pre);
                        g_qt[odA + c0 + 32] = f2tf32(hiA0 * pre);
                        g_qt[odA + c0 + 33] = f2tf32(hiA1 * pre);
                        g_qt[odB + c0]      = f2tf32(loB0 * pre);
                        g_qt[odB + c0 + 1]  = f2tf32(loB1 * pre);
                        g_qt[odB + c0 + 32] = f2tf32(hiB0 * pre);
                        g_qt[odB + c0 + 33] = f2tf32(hiB1 * pre);
                    } else {
                        g_kt[odA + c0]      = f2tf32(loA0);
                        g_kt[odA + c0 + 1]  = f2tf32(loA1);
                        g_kt[odA + c0 + 32] = f2tf32(hiA0);
                        g_kt[odA + c0 + 33] = f2tf32(hiA1);
                        g_kt[odB + c0]      = f2tf32(loB0);
                        g_kt[odB + c0 + 1]  = f2tf32(loB1);
                        g_kt[odB + c0 + 32] = f2tf32(hiB0);
                        g_kt[odB + c0 + 33] = f2tf32(hiB1);
                    }
                }
            }
        }
    }
}

// ---------------- RoPE table ----------------
__global__ void rope_table_kernel()
{
    int idx = blockIdx.x * blockDim.x + threadIdx.x;
    if (idx >= TSEQ * 32) return;
    int t = idx >> 5;
    int j = idx & 31;
    float invf = powf(10000.0f, -((float)(2 * j) / 64.0f));
    float angle = (float)t * invf;
    double a = (double)angle;
    double s, c;
    sincos(a, &s, &c);
    g_cs[idx * 2 + 0] = (float)c;
    g_cs[idx * 2 + 1] = (float)s;
}

// ================= flash attention: tf32 mma.sync, compile-time stages ==========
#define FBQ 128
#define FBKV 32
#define KSTR 68
#define VSTR 72

__global__ __launch_bounds__(256, 2) void flash_mma_kernel()
{
    const int tid  = threadIdx.x;
    const int w    = tid >> 5;
    const int lane = tid & 31;
    const int g    = lane >> 2;
    const int tg   = lane & 3;
    const int qt = (gridDim.x - 1) - blockIdx.x;
    const int h  = blockIdx.y;
    const int b  = blockIdx.z;
    const int qb = qt * FBQ;
    const int wb = qb + w * 16;
    const int rA = wb + g;
    const int rB = rA + 8;

    const size_t bh = ((size_t)b * NHEADS + h) * TSEQ * HDIM;
    const float NEG = __int_as_float(0xff800000);

    __shared__ uint32_t Ks[2][FBKV * KSTR];
    __shared__ uint32_t Vs[2][FBKV * VSTR];

    // Q fragments: already tf32 + prescaled in gmem
    uint32_t qf[8][4];
    {
        const uint32_t* q0 = g_qt + bh + (size_t)rA * HDIM;
        const uint32_t* q1 = g_qt + bh + (size_t)rB * HDIM;
        #pragma unroll
        for (int kc = 0; kc < 8; kc++) {
            qf[kc][0] = q0[kc * 8 + tg];
            qf[kc][1] = q1[kc * 8 + tg];
            qf[kc][2] = q0[kc * 8 + tg + 4];
            qf[kc][3] = q1[kc * 8 + tg + 4];
        }
    }

    float o[8][4];
    #pragma unroll
    for (int n = 0; n < 8; n++)
        #pragma unroll
        for (int j = 0; j < 4; j++) o[n][j] = 0.f;
    float mA = NEG, mB = NEG, lA = 0.f, lB = 0.f;

    const int ntiles = qb / FBKV + 4;      // = 4*qt + 4, always even

    uint32_t kDst[2], vDst[2];
    const uint32_t* kSrcB[2];
    const uint32_t* vSrcB[2];
    #pragma unroll
    for (int i = 0; i < 2; i++) {
        const int idx = i * 256 + tid;
        const int key = idx >> 4, c = idx & 15;
        kDst[i] = s2u(&Ks[0][key * KSTR + c * 4]);
        vDst[i] = s2u(&Vs[0][key * VSTR + c * 4]);
        kSrcB[i] = g_kt + bh + idx * 4;
        vSrcB[i] = g_vt + bh + idx * 4;
    }

    #define FLOAD(t0_, S_) do {                                                    \
        _Pragma("unroll")                                                          \
        for (int i_ = 0; i_ < 2; i_++) {                                           \
            cp16(kDst[i_] + (S_) * (FBKV * KSTR * 4), kSrcB[i_] + (t0_) * FBKV * HDIM); \
            cp16(vDst[i_] + (S_) * (FBKV * VSTR * 4), vSrcB[i_] + (t0_) * FBKV * HDIM); \
        }                                                                          \
        asm volatile("cp.async.commit_group;" ::: "memory");                       \
    } while (0)

    #define FBODY(t0_, S_) do {                                                    \
        const int j0 = (t0_) * FBKV;                                               \
        asm volatile("cp.async.wait_group 0;" ::: "memory");                       \
        __syncthreads();                                                           \
        if ((t0_) + 1 < ntiles) FLOAD((t0_) + 1, ((S_) + 1) & 1);                  \
        if (j0 <= wb) {                                                            \
            const uint32_t* ksm = Ks[S_];                                          \
            const uint32_t* vsm = Vs[S_];                                          \
            float s[4][4];                                                         \
            _Pragma("unroll")                                                      \
            for (int nt = 0; nt < 4; nt++) {                                       \
                s[nt][0] = 0.f; s[nt][1] = 0.f; s[nt][2] = 0.f; s[nt][3] = 0.f;    \
            }                                                                      \
            _Pragma("unroll")                                                      \
            for (int kc = 0; kc < 8; kc++) {                                       \
                _Pragma("unroll")                                                  \
                for (int nt = 0; nt < 4; nt++) {                                   \
                    uint32_t b0 = ksm[(nt * 8 + g) * KSTR + kc * 8 + tg];          \
                    uint32_t b1 = ksm[(nt * 8 + g) * KSTR + kc * 8 + tg + 4];      \
                    mma8(s[nt], qf[kc], b0, b1);                                   \
                }                                                                  \
            }                                                                      \
            float mtA = mA, mtB = mB;                                              \
            _Pragma("unroll")                                                      \
            for (int nt = 0; nt < 4; nt++) {                                       \
                const int jc = j0 + nt * 8 + 2 * tg;                               \
                s[nt][0] = (jc     <= rA) ? s[nt][0] : NEG;                        \
                s[nt][1] = (jc + 1 <= rA) ? s[nt][1] : NEG;                        \
                s[nt][2] = (jc     <= rB) ? s[nt][2] : NEG;                        \
                s[nt][3] = (jc + 1 <= rB) ? s[nt][3] : NEG;                        \
                mtA = fmaxf(mtA, fmaxf(s[nt][0], s[nt][1]));                       \
                mtB = fmaxf(mtB, fmaxf(s[nt][2], s[nt][3]));                       \
            }                                                                      \
            mtA = fmaxf(mtA, __shfl_xor_sync(0xffffffffu, mtA, 1));                \
            mtA = fmaxf(mtA, __shfl_xor_sync(0xffffffffu, mtA, 2));                \
            mtB = fmaxf(mtB, __shfl_xor_sync(0xffffffffu, mtB, 1));                \
            mtB = fmaxf(mtB, __shfl_xor_sync(0xffffffffu, mtB, 2));                \
            const float corrA = ex2(mA - mtA);                                     \
            const float corrB = ex2(mB - mtB);                                     \
            mA = mtA; mB = mtB;                                                    \
            uint32_t pf[4][4];                                                     \
            float sumA = 0.f, sumB = 0.f;                                          \
            _Pragma("unroll")                                                      \
            for (int nt = 0; nt < 4; nt++) {                                       \
                pf[nt][0] = f2tf32(ex2(s[nt][0] - mtA));                           \
                pf[nt][1] = f2tf32(ex2(s[nt][1] - mtA));                           \
                pf[nt][2] = f2tf32(ex2(s[nt][2] - mtB));                           \
                pf[nt][3] = f2tf32(ex2(s[nt][3] - mtB));                           \
                sumA += __uint_as_float(pf[nt][0]) + __uint_as_float(pf[nt][1]);   \
                sumB += __uint_as_float(pf[nt][2]) + __uint_as_float(pf[nt][3]);   \
            }                                                                      \
            sumA += __shfl_xor_sync(0xffffffffu, sumA, 1);                         \
            sumA += __shfl_xor_sync(0xffffffffu, sumA, 2);                         \
            sumB += __shfl_xor_sync(0xffffffffu, sumB, 1);                         \
            sumB += __shfl_xor_sync(0xffffffffu, sumB, 2);                         \
            lA = lA * corrA + sumA;                                                \
            lB = lB * corrB + sumB;                                                \
            _Pragma("unroll")                                                      \
            for (int n = 0; n < 8; n++) {                                          \
                o[n][0] *= corrA; o[n][1] *= corrA;                                \
                o[n][2] *= corrB; o[n][3] *= corrB;                                \
            }                                                                      \
            const int srcL = tg >> 1;                                              \
            _Pragma("unroll")                                                      \
            for (int kc = 0; kc < 4; kc++) {                                       \
                uint32_t v0 = __shfl_sync(0xffffffffu, pf[kc][0], srcL, 4);        \
                uint32_t v1 = __shfl_sync(0xffffffffu, pf[kc][1], srcL, 4);        \
                uint32_t v2 = __shfl_sync(0xffffffffu, pf[kc][0], srcL + 2, 4);    \
                uint32_t v3 = __shfl_sync(0xffffffffu, pf[kc][1], srcL + 2, 4);    \
                uint32_t u0 = __shfl_sync(0xffffffffu, pf[kc][2], srcL, 4);        \
                uint32_t u1 = __shfl_sync(0xffffffffu, pf[kc][3], srcL, 4);        \
                uint32_t u2 = __shfl_sync(0xffffffffu, pf[kc][2], srcL + 2, 4);    \
                uint32_t u3 = __shfl_sync(0xffffffffu, pf[kc][3], srcL + 2, 4);    \
                uint32_t af[4];                                                    \
                af[0] = (tg & 1) ? v1 : v0;                                        \
                af[1] = (tg & 1) ? u1 : u0;                                        \
                af[2] = (tg & 1) ? v3 : v2;                                        \
                af[3] = (tg & 1) ? u3 : u2;                                        \
                _Pragma("unroll")                                                  \
                for (int nt2 = 0; nt2 < 8; nt2++) {                                \
                    uint32_t b0 = vsm[(kc * 8 + tg) * VSTR + nt2 * 8 + g];         \
                    uint32_t b1 = vsm[(kc * 8 + tg + 4) * VSTR + nt2 * 8 + g];     \
                    mma8(o[nt2], af, b0, b1);                                      \
                }                                                                  \
            }                                                                      \
        }                                                                          \
    } while (0)

    FLOAD(0, 0);

    #pragma unroll 1
    for (int t0 = 0; t0 < ntiles; t0 += 2) {
        FBODY(t0, 0);
        FBODY(t0 + 1, 1);
    }
    #undef FLOAD
    #undef FBODY

    // ---- epilogue: O/l -> tf32 column-permuted rows of g_attnt [B*T, 1024] ----
    const float iA = 1.f / lA;
    const float iB = 1.f / lB;
    uint32_t* opA = g_attnt + ((size_t)b * TSEQ + rA) * DMODEL + h * HDIM;
    uint32_t* opB = g_attnt + ((size_t)b * TSEQ + rB) * DMODEL + h * HDIM;
    #pragma unroll
    for (int nt2 = 0; nt2 < 8; nt2++) {
        const int cc = nt2 * 8 + 2 * tg;
        const int blk = (cc >> 5) << 5;
        const int c0 = cc & 31, c1 = (cc + 1) & 31;
        const int p0 = (c0 & 3) * 8 + (c0 >> 2);
        const int p1 = (c1 & 3) * 8 + (c1 >> 2);
        opA[blk + p0] = f2tf32(o[nt2][0] * iA);
        opA[blk + p1] = f2tf32(o[nt2][1] * iA);
        opB[blk + p0] = f2tf32(o[nt2][2] * iB);
        opB[blk + p1] = f2tf32(o[nt2][3] * iB);
    }
}

// ---------------- launch ----------------
extern "C" void kernel_launch(void* const* d_in, const int* in_sizes, int n_in,
                              void* d_out, int out_size)
{
    const float* x      = (const float*)d_in[0];
    const float* qkv_w  = (const float*)d_in[1];
    const float* qkv_b  = (const float*)d_in[2];
    const float* proj_w = (const float*)d_in[3];
    const float* proj_b = (const float*)d_in[4];
    float* out = (float*)d_out;

    cudaFuncSetAttribute(tf32_gemm_kernel<QKV_N, 1>,
                         cudaFuncAttributeMaxDynamicSharedMemorySize, GEMM_SMEM_B);
    cudaFuncSetAttribute(tf32_gemm_kernel<DMODEL, 0>,
                         cudaFuncAttributeMaxDynamicSharedMemorySize, GEMM_SMEM_B);

    uint32_t *d_xt, *d_wqkvt, *d_wprojt, *d_attnt;
    cudaGetSymbolAddress((void**)&d_xt, g_xt);
    cudaGetSymbolAddress((void**)&d_wqkvt, g_wqkvt);
    cudaGetSymbolAddress((void**)&d_wprojt, g_wprojt);
    cudaGetSymbolAddress((void**)&d_attnt, g_attnt);

    // 0) convert+permute GEMM operands to tf32
    convert_permute_kernel<<<(ROWS * DMODEL) / 256, 256>>>(x, d_xt, ROWS * DMODEL);
    convert_permute_kernel<<<(QKV_N * DMODEL) / 256, 256>>>(qkv_w, d_wqkvt, QKV_N * DMODEL);
    convert_permute_kernel<<<(DMODEL * DMODEL) / 256, 256>>>(proj_w, d_wprojt, DMODEL * DMODEL);

    // 1) RoPE cos/sin table (needed by QKV epilogue)
    rope_table_kernel<<<(TSEQ * 32 + 255) / 256, 256>>>();

    // 2) QKV GEMM with fused RoPE epilogue -> g_qt/g_kt/g_vt
    tf32_gemm_kernel<QKV_N, 1><<<dim3(QKV_N / 128, ROWS / 128), 256, GEMM_SMEM_B>>>(
        d_xt, d_wqkvt, qkv_b, nullptr);

    // 3) causal flash attention (tf32 mma) -> tf32-permuted O into g_attnt
    flash_mma_kernel<<<dim3(TSEQ / FBQ, NHEADS, BATCH), 256>>>();

    // 4) out = attn @ proj_w^T + proj_b
    tf32_gemm_kernel<DMODEL, 0><<<dim3(DMODEL / 128, ROWS / 128), 256, GEMM_SMEM_B>>>(
        d_attnt, d_wprojt, proj_b, out);
}

// round 14
// speedup vs baseline: 6.6390x; 1.8297x over previous
#include <cuda_runtime.h>
#include <cuda_fp16.h>
#include <math.h>
#include <cstdint>

// Problem constants
#define BATCH 2
#define TSEQ  2048
#define DMODEL 1024
#define NHEADS 16
#define HDIM  64
#define ROWS (BATCH * TSEQ)          // 4096
#define QKV_N (3 * DMODEL)           // 3072
#define RWORDS (DMODEL / 2)          // 512 half2 words per row

// ---------------- scratch (no allocation allowed) ----------------
__device__ uint32_t g_qt[BATCH * NHEADS * TSEQ * HDIM / 2];  // half2, prescaled
__device__ uint32_t g_kt[BATCH * NHEADS * TSEQ * HDIM / 2];  // half2
__device__ __half   g_vtr[BATCH * NHEADS * HDIM * TSEQ];     // V transposed [b,h,d,t]
__device__ float    g_cs[TSEQ * 32 * 2];                     // cos,sin per (t, freq)
// half2 column-pair-permuted operands for the GEMMs
__device__ uint32_t g_xt[ROWS * RWORDS];
__device__ uint32_t g_wqkvt[QKV_N * RWORDS];
__device__ uint32_t g_wprojt[DMODEL * RWORDS];
__device__ uint32_t g_attnt[ROWS * RWORDS];                  // flash writes permuted O

// ================= helpers =================
__device__ __forceinline__ uint32_t s2u(const void* p) {
    uint32_t a;
    asm("{ .reg .u64 t; cvta.to.shared.u64 t, %1; cvt.u32.u64 %0, t; }"
        : "=r"(a) : "l"(p));
    return a;
}
__device__ __forceinline__ float ex2(float x) {
    float y;
    asm("ex2.approx.ftz.f32 %0, %1;" : "=f"(y) : "f"(x));
    return y;
}
__device__ __forceinline__ void cp16(uint32_t dst, const void* src) {
    asm volatile("cp.async.cg.shared.global [%0], [%1], 16;" :: "r"(dst), "l"(src));
}
__device__ __forceinline__ uint32_t h2bits(float lo, float hi) {
    __half2 h = __floats2half2_rn(lo, hi);
    return *(uint32_t*)&h;
}
__device__ __forceinline__ void mma16(float* d, const uint32_t* a, uint32_t b0, uint32_t b1) {
    asm volatile(
        "mma.sync.aligned.m16n8k16.row.col.f32.f16.f16.f32 "
        "{%0,%1,%2,%3}, {%4,%5,%6,%7}, {%8,%9}, {%0,%1,%2,%3};"
        : "+f"(d[0]), "+f"(d[1]), "+f"(d[2]), "+f"(d[3])
        : "r"(a[0]), "r"(a[1]), "r"(a[2]), "r"(a[3]), "r"(b0), "r"(b1));
}

// ------- convert f32 -> half2 words with per-32-word-block permutation -------
// dst word position p holds source word c = (p&7)*4 + (p>>3) (word = k-pair)
__global__ void convert_permute_kernel(const float* __restrict__ src,
                                       uint32_t* __restrict__ dst, int nw)
{
    int idx = blockIdx.x * blockDim.x + threadIdx.x;
    if (idx >= nw) return;
    int p = idx & 31;
    int c = (p & 7) * 4 + (p >> 3);
    int base = idx & ~31;
    float2 v = *(const float2*)(src + 2 * (size_t)(base + c));
    dst[idx] = h2bits(v.x, v.y);
}

// ================= fp16 mma GEMM: C[M,NCOLS] = A[M,1024] @ W[NCOLS,1024]^T + bias ======
// MODE 0: fp32 out. MODE 1: QKV fused RoPE epilogue -> g_qt/g_kt(half2)/g_vtr(transposed)
#define GSTR 36
#define GTILEW (128 * GSTR)
#define GSTAGEW (2 * GTILEW)
#define GSTAGES 3
#define GEMM_SMEM_B (GSTAGES * GSTAGEW * 4)      // 110592 bytes

template<int NCOLS, int MODE>
__global__ __launch_bounds__(256, 2) void f16_gemm_kernel(
    const uint32_t* __restrict__ A,
    const uint32_t* __restrict__ W,
    const float* __restrict__ bias,
    float* __restrict__ C)
{
    extern __shared__ uint32_t smw[];
    const int tid = threadIdx.x;
    const int wid = tid >> 5, lane = tid & 31;
    const int g = lane >> 2, tg = lane & 3;
    const int wm = wid & 3, wn = wid >> 2;
    const int bm = blockIdx.y * 128, bn = blockIdx.x * 128;

    float acc[2][8][4];
    #pragma unroll
    for (int t = 0; t < 2; t++)
        #pragma unroll
        for (int nt = 0; nt < 8; nt++)
            #pragma unroll
            for (int j = 0; j < 4; j++) acc[t][nt][j] = 0.f;

    const int fo = 8 * (tg ^ (g & 3));

    uint32_t aDst[4], bDst[4];
    const uint32_t* aSrcB[4];
    const uint32_t* bSrcB[4];
    #pragma unroll
    for (int i = 0; i < 4; i++) {
        const int idx = i * 256 + tid;
        const int row = idx >> 3, q = idx & 7;
        const int sq = q ^ ((row & 3) << 1);
        aDst[i] = s2u(smw + row * GSTR + sq * 4);
        bDst[i] = aDst[i] + GTILEW * 4;
        aSrcB[i] = A + (size_t)(bm + row) * RWORDS + q * 4;
        bSrcB[i] = W + (size_t)(bn + row) * RWORDS + q * 4;
    }
    const uint32_t* aF = smw + (wm * 32 + g) * GSTR + fo;
    const uint32_t* bF = smw + GTILEW + (wn * 64 + g) * GSTR + fo;

    #define LOAD_CHUNK(c_, S_) do {                                                \
        _Pragma("unroll")                                                          \
        for (int i_ = 0; i_ < 4; i_++) {                                           \
            cp16(aDst[i_] + (S_) * GSTAGEW * 4, aSrcB[i_] + (c_) * 32);            \
            cp16(bDst[i_] + (S_) * GSTAGEW * 4, bSrcB[i_] + (c_) * 32);            \
        }                                                                          \
        asm volatile("cp.async.commit_group;" ::: "memory");                       \
    } while (0)

    // body: chunk c_ (64 k) in stage S_; PF_ -> prefetch c_+2
    #define GBODY(c_, S_, PF_) do {                                                \
        asm volatile("cp.async.wait_group 1;" ::: "memory");                       \
        __syncthreads();                                                           \
        if (PF_) { LOAD_CHUNK((c_) + 2, ((S_) + 2) % GSTAGES); }                   \
        else { asm volatile("cp.async.commit_group;" ::: "memory"); }              \
        const uint32_t* as_ = aF + (S_) * GSTAGEW;                                 \
        const uint32_t* bs_ = bF + (S_) * GSTAGEW;                                 \
        uint32_t a_[2][4][4];                                                      \
        _Pragma("unroll")                                                          \
        for (int t_ = 0; t_ < 2; t_++) {                                           \
            uint4 x0 = *(const uint4*)(as_ + t_ * 16 * GSTR);                      \
            uint4 x1 = *(const uint4*)(as_ + t_ * 16 * GSTR + 4);                  \
            uint4 y0 = *(const uint4*)(as_ + (t_ * 16 + 8) * GSTR);                \
            uint4 y1 = *(const uint4*)(as_ + (t_ * 16 + 8) * GSTR + 4);            \
            a_[t_][0][0]=x0.x; a_[t_][0][1]=y0.x; a_[t_][0][2]=x0.y; a_[t_][0][3]=y0.y; \
            a_[t_][1][0]=x0.z; a_[t_][1][1]=y0.z; a_[t_][1][2]=x0.w; a_[t_][1][3]=y0.w; \
            a_[t_][2][0]=x1.x; a_[t_][2][1]=y1.x; a_[t_][2][2]=x1.y; a_[t_][2][3]=y1.y; \
            a_[t_][3][0]=x1.z; a_[t_][3][1]=y1.z; a_[t_][3][2]=x1.w; a_[t_][3][3]=y1.w; \
        }                                                                          \
        _Pragma("unroll")                                                          \
        for (int nt_ = 0; nt_ < 8; nt_++) {                                        \
            uint4 b0 = *(const uint4*)(bs_ + nt_ * 8 * GSTR);                      \
            uint4 b1 = *(const uint4*)(bs_ + nt_ * 8 * GSTR + 4);                  \
            mma16(acc[0][nt_], a_[0][0], b0.x, b0.y);                              \
            mma16(acc[1][nt_], a_[1][0], b0.x, b0.y);                              \
            mma16(acc[0][nt_], a_[0][1], b0.z, b0.w);                              \
            mma16(acc[1][nt_], a_[1][1], b0.z, b0.w);                              \
            mma16(acc[0][nt_], a_[0][2], b1.x, b1.y);                              \
            mma16(acc[1][nt_], a_[1][2], b1.x, b1.y);                              \
            mma16(acc[0][nt_], a_[0][3], b1.z, b1.w);                              \
            mma16(acc[1][nt_], a_[1][3], b1.z, b1.w);                              \
        }                                                                          \
    } while (0)

    LOAD_CHUNK(0, 0);
    LOAD_CHUNK(1, 1);

    #pragma unroll 1
    for (int cb = 0; cb < 12; cb += 3) {
        GBODY(cb + 0, 0, 1);
        GBODY(cb + 1, 1, 1);
        GBODY(cb + 2, 2, 1);
    }
    GBODY(12, 0, 1);
    GBODY(13, 1, 1);
    GBODY(14, 2, 0);
    GBODY(15, 0, 0);
    #undef LOAD_CHUNK
    #undef GBODY

    if (MODE == 0) {
        #pragma unroll
        for (int t = 0; t < 2; t++) {
            const int r0 = bm + wm * 32 + t * 16 + g;
            #pragma unroll
            for (int nt = 0; nt < 8; nt++) {
                const int cc = bn + wn * 64 + nt * 8 + 2 * tg;
                const float b0 = bias[cc], b1 = bias[cc + 1];
                *(float2*)(C + (size_t)r0 * NCOLS + cc) =
                    make_float2(acc[t][nt][0] + b0, acc[t][nt][1] + b1);
                *(float2*)(C + (size_t)(r0 + 8) * NCOLS + cc) =
                    make_float2(acc[t][nt][2] + b0, acc[t][nt][3] + b1);
            }
        }
    } else {
        // fused RoPE epilogue; warp n-tile (64) = one head; pair c <-> c+32 in-thread.
        const int gcb = bn + wn * 64;
        const int region = gcb >> 10;           // 0=Q 1=K 2=V
        const int h = (gcb & 1023) >> 6;
        const int bb = bm >> 11;
        const float pre = 0.125f * 1.4426950408889634f;
        const float2* cs2 = (const float2*)g_cs;

        #pragma unroll
        for (int t = 0; t < 2; t++) {
            const int ta = (bm & 2047) + wm * 32 + t * 16 + g;
            const int tb = ta + 8;
            const size_t rowA = ((size_t)bb * NHEADS + h) * TSEQ + ta;
            const size_t wA = rowA * 32;            // 32 half2 words per row
            const size_t wB = wA + 8 * 32;
            #pragma unroll
            for (int nt = 0; nt < 4; nt++) {
                const int c0 = nt * 8 + 2 * tg;          // < 32
                const int wlo = nt * 4 + tg;             // half2 word index
                const float bl0 = bias[gcb + c0],      bl1 = bias[gcb + c0 + 1];
                const float bh0 = bias[gcb + c0 + 32], bh1 = bias[gcb + c0 + 33];
                float xA0 = acc[t][nt][0] + bl0,     xA1 = acc[t][nt][1] + bl1;
                float xB0 = acc[t][nt][2] + bl0,     xB1 = acc[t][nt][3] + bl1;
                float yA0 = acc[t][nt + 4][0] + bh0, yA1 = acc[t][nt + 4][1] + bh1;
                float yB0 = acc[t][nt + 4][2] + bh0, yB1 = acc[t][nt + 4][3] + bh1;

                if (region == 2) {
                    // V transposed [b,h,d,t]
                    const size_t vb = ((size_t)bb * NHEADS + h) * HDIM;
                    g_vtr[(vb + c0)      * TSEQ + ta] = __float2half_rn(xA0);
                    g_vtr[(vb + c0 + 1)  * TSEQ + ta] = __float2half_rn(xA1);
                    g_vtr[(vb + c0 + 32) * TSEQ + ta] = __float2half_rn(yA0);
                    g_vtr[(vb + c0 + 33) * TSEQ + ta] = __float2half_rn(yA1);
                    g_vtr[(vb + c0)      * TSEQ + tb] = __float2half_rn(xB0);
                    g_vtr[(vb + c0 + 1)  * TSEQ + tb] = __float2half_rn(xB1);
                    g_vtr[(vb + c0 + 32) * TSEQ + tb] = __float2half_rn(yB0);
                    g_vtr[(vb + c0 + 33) * TSEQ + tb] = __float2half_rn(yB1);
                } else {
                    float2 ca0 = cs2[ta * 32 + c0];
                    float2 ca1 = cs2[ta * 32 + c0 + 1];
                    float2 cb0 = cs2[tb * 32 + c0];
                    float2 cb1 = cs2[tb * 32 + c0 + 1];
                    float loA0 = xA0 * ca0.x - yA0 * ca0.y, hiA0 = yA0 * ca0.x + xA0 * ca0.y;
                    float loA1 = xA1 * ca1.x - yA1 * ca1.y, hiA1 = yA1 * ca1.x + xA1 * ca1.y;
                    float loB0 = xB0 * cb0.x - yB0 * cb0.y, hiB0 = yB0 * cb0.x + xB0 * cb0.y;
                    float loB1 = xB1 * cb1.x - yB1 * cb1.y, hiB1 = yB1 * cb1.x + xB1 * cb1.y;
                    if (region == 0) {
                        g_qt[wA + wlo]      = h2bits(loA0 * pre, loA1 * pre);
                        g_qt[wA + wlo + 16] = h2bits(hiA0 * pre, hiA1 * pre);
                        g_qt[wB + wlo]      = h2bits(loB0 * pre, loB1 * pre);
                        g_qt[wB + wlo + 16] = h2bits(hiB0 * pre, hiB1 * pre);
                    } else {
                        g_kt[wA + wlo]      = h2bits(loA0, loA1);
                        g_kt[wA + wlo + 16] = h2bits(hiA0, hiA1);
                        g_kt[wB + wlo]      = h2bits(loB0, loB1);
                        g_kt[wB + wlo + 16] = h2bits(hiB0, hiB1);
                    }
                }
            }
        }
    }
}

// ---------------- RoPE table ----------------
__global__ void rope_table_kernel()
{
    int idx = blockIdx.x * blockDim.x + threadIdx.x;
    if (idx >= TSEQ * 32) return;
    int t = idx >> 5;
    int j = idx & 31;
    float invf = powf(10000.0f, -((float)(2 * j) / 64.0f));
    float angle = (float)t * invf;
    double a = (double)angle;
    double s, c;
    sincos(a, &s, &c);
    g_cs[idx * 2 + 0] = (float)c;
    g_cs[idx * 2 + 1] = (float)s;
}

// ================= flash attention: fp16 mma.sync (shuffle-free PV) ==========
#define FBQ 128
#define FBKV 32
#define KSTR 36          // words per K row (32 payload + 4 pad)
#define VSTR 20          // words per V row (16 payload + 4 pad)
#define KTILE_B (FBKV * KSTR * 4)
#define VTILE_B (HDIM * VSTR * 4)

__global__ __launch_bounds__(256, 2) void flash_mma_kernel()
{
    const int tid  = threadIdx.x;
    const int w    = tid >> 5;
    const int lane = tid & 31;
    const int g    = lane >> 2;
    const int tg   = lane & 3;
    const int qt = (gridDim.x - 1) - blockIdx.x;
    const int h  = blockIdx.y;
    const int b  = blockIdx.z;
    const int qb = qt * FBQ;
    const int wb = qb + w * 16;
    const int rA = wb + g;
    const int rB = rA + 8;

    const float NEG = __int_as_float(0xff800000);

    __shared__ uint32_t Ks[2][FBKV * KSTR];
    __shared__ uint32_t Vs[2][HDIM * VSTR];

    // Q fragments: half2 words, prescaled, 4 k16 groups
    uint32_t qf[4][4];
    {
        const size_t base = (((size_t)b * NHEADS + h) * TSEQ) * 32;
        const uint32_t* q0 = g_qt + base + (size_t)rA * 32;
        const uint32_t* q1 = g_qt + base + (size_t)(rB - rA) * 0 + (size_t)rB * 32;
        #pragma unroll
        for (int kc = 0; kc < 4; kc++) {
            qf[kc][0] = q0[kc * 8 + tg];
            qf[kc][1] = q1[kc * 8 + tg];
            qf[kc][2] = q0[kc * 8 + tg + 4];
            qf[kc][3] = q1[kc * 8 + tg + 4];
        }
    }

    float o[8][4];
    #pragma unroll
    for (int n = 0; n < 8; n++)
        #pragma unroll
        for (int j = 0; j < 4; j++) o[n][j] = 0.f;
    float mA = NEG, mB = NEG, lA = 0.f, lB = 0.f;

    const int ntiles = qb / FBKV + 4;      // always even

    // hoisted cp.async addressing (stage 0)
    const uint32_t* kSrc = g_kt + (((size_t)b * NHEADS + h) * TSEQ) * 32 + tid * 4;
    const int vd = tid >> 2, vc = tid & 3;
    const uint32_t* vSrc = (const uint32_t*)g_vtr
        + (((size_t)b * NHEADS + h) * HDIM + vd) * (TSEQ / 2) + vc * 4;
    const uint32_t kDst = s2u(&Ks[0][(tid >> 3) * KSTR + (tid & 7) * 4]);
    const uint32_t vDst = s2u(&Vs[0][vd * VSTR + vc * 4]);

    #define FLOAD(t0_, S_) do {                                                    \
        cp16(kDst + (S_) * KTILE_B, kSrc + (t0_) * 1024);                          \
        cp16(vDst + (S_) * VTILE_B, vSrc + (t0_) * 16);                            \
        asm volatile("cp.async.commit_group;" ::: "memory");                       \
    } while (0)

    #define FBODY(t0_, S_) do {                                                    \
        const int j0 = (t0_) * FBKV;                                               \
        asm volatile("cp.async.wait_group 0;" ::: "memory");                       \
        __syncthreads();                                                           \
        if ((t0_) + 1 < ntiles) FLOAD((t0_) + 1, ((S_) + 1) & 1);                  \
        if (j0 <= wb) {                                                            \
            const uint32_t* ksm = Ks[S_];                                          \
            const uint32_t* vsm = Vs[S_];                                          \
            float s[4][4];                                                         \
            _Pragma("unroll")                                                      \
            for (int nt = 0; nt < 4; nt++) {                                       \
                s[nt][0] = 0.f; s[nt][1] = 0.f; s[nt][2] = 0.f; s[nt][3] = 0.f;    \
            }                                                                      \
            _Pragma("unroll")                                                      \
            for (int kc = 0; kc < 4; kc++) {                                       \
                _Pragma("unroll")                                                  \
                for (int nt = 0; nt < 4; nt++) {                                   \
                    uint32_t b0 = ksm[(nt * 8 + g) * KSTR + kc * 8 + tg];          \
                    uint32_t b1 = ksm[(nt * 8 + g) * KSTR + kc * 8 + tg + 4];      \
                    mma16(s[nt], qf[kc], b0, b1);                                  \
                }                                                                  \
            }                                                                      \
            float mtA = mA, mtB = mB;                                              \
            _Pragma("unroll")                                                      \
            for (int nt = 0; nt < 4; nt++) {                                       \
                const int jc = j0 + nt * 8 + 2 * tg;                               \
                s[nt][0] = (jc     <= rA) ? s[nt][0] : NEG;                        \
                s[nt][1] = (jc + 1 <= rA) ? s[nt][1] : NEG;                        \
                s[nt][2] = (jc     <= rB) ? s[nt][2] : NEG;                        \
                s[nt][3] = (jc + 1 <= rB) ? s[nt][3] : NEG;                        \
                mtA = fmaxf(mtA, fmaxf(s[nt][0], s[nt][1]));                       \
                mtB = fmaxf(mtB, fmaxf(s[nt][2], s[nt][3]));                       \
            }                                                                      \
            mtA = fmaxf(mtA, __shfl_xor_sync(0xffffffffu, mtA, 1));                \
            mtA = fmaxf(mtA, __shfl_xor_sync(0xffffffffu, mtA, 2));                \
            mtB = fmaxf(mtB, __shfl_xor_sync(0xffffffffu, mtB, 1));                \
            mtB = fmaxf(mtB, __shfl_xor_sync(0xffffffffu, mtB, 2));                \
            const float corrA = ex2(mA - mtA);                                     \
            const float corrB = ex2(mB - mtB);                                     \
            mA = mtA; mB = mtB;                                                    \
            uint32_t phA[4], phB[4];                                               \
            float sumA = 0.f, sumB = 0.f;                                          \
            _Pragma("unroll")                                                      \
            for (int nt = 0; nt < 4; nt++) {                                       \
                float pA0 = ex2(s[nt][0] - mtA), pA1 = ex2(s[nt][1] - mtA);        \
                float pB0 = ex2(s[nt][2] - mtB), pB1 = ex2(s[nt][3] - mtB);        \
                sumA += pA0 + pA1; sumB += pB0 + pB1;                              \
                phA[nt] = h2bits(pA0, pA1);                                        \
                phB[nt] = h2bits(pB0, pB1);                                        \
            }                                                                      \
            sumA += __shfl_xor_sync(0xffffffffu, sumA, 1);                         \
            sumA += __shfl_xor_sync(0xffffffffu, sumA, 2);                         \
            sumB += __shfl_xor_sync(0xffffffffu, sumB, 1);                         \
            sumB += __shfl_xor_sync(0xffffffffu, sumB, 2);                         \
            lA = lA * corrA + sumA;                                                \
            lB = lB * corrB + sumB;                                                \
            _Pragma("unroll")                                                      \
            for (int n = 0; n < 8; n++) {                                          \
                o[n][0] *= corrA; o[n][1] *= corrA;                                \
                o[n][2] *= corrB; o[n][3] *= corrB;                                \
            }                                                                      \
            _Pragma("unroll")                                                      \
            for (int kc2 = 0; kc2 < 2; kc2++) {                                    \
                uint32_t af[4];                                                    \
                af[0] = phA[2 * kc2];                                              \
                af[1] = phB[2 * kc2];                                              \
                af[2] = phA[2 * kc2 + 1];                                          \
                af[3] = phB[2 * kc2 + 1];                                          \
                _Pragma("unroll")                                                  \
                for (int nt2 = 0; nt2 < 8; nt2++) {                                \
                    uint32_t b0 = vsm[(nt2 * 8 + g) * VSTR + kc2 * 8 + tg];        \
                    uint32_t b1 = vsm[(nt2 * 8 + g) * VSTR + kc2 * 8 + tg + 4];    \
                    mma16(o[nt2], af, b0, b1);                                     \
                }                                                                  \
            }                                                                      \
        }                                                                          \
    } while (0)

    FLOAD(0, 0);

    #pragma unroll 1
    for (int t0 = 0; t0 < ntiles; t0 += 2) {
        FBODY(t0, 0);
        FBODY(t0 + 1, 1);
    }
    #undef FLOAD
    #undef FBODY

    // ---- epilogue: O/l -> half2 word-permuted rows of g_attnt [B*T, 512 words] ----
    const float iA = 1.f / lA;
    const float iB = 1.f / lB;
    uint32_t* opA = g_attnt + ((size_t)b * TSEQ + rA) * RWORDS + h * 32;
    uint32_t* opB = g_attnt + ((size_t)b * TSEQ + rB) * RWORDS + h * 32;
    #pragma unroll
    for (int nt2 = 0; nt2 < 8; nt2++) {
        const int c = nt2 * 4 + tg;              // word index within head block
        const int p = (c & 3) * 8 + (c >> 2);    // permuted position
        opA[p] = h2bits(o[nt2][0] * iA, o[nt2][1] * iA);
        opB[p] = h2bits(o[nt2][2] * iB, o[nt2][3] * iB);
    }
}

// ---------------- launch ----------------
extern "C" void kernel_launch(void* const* d_in, const int* in_sizes, int n_in,
                              void* d_out, int out_size)
{
    const float* x      = (const float*)d_in[0];
    const float* qkv_w  = (const float*)d_in[1];
    const float* qkv_b  = (const float*)d_in[2];
    const float* proj_w = (const float*)d_in[3];
    const float* proj_b = (const float*)d_in[4];
    float* out = (float*)d_out;

    cudaFuncSetAttribute(f16_gemm_kernel<QKV_N, 1>,
                         cudaFuncAttributeMaxDynamicSharedMemorySize, GEMM_SMEM_B);
    cudaFuncSetAttribute(f16_gemm_kernel<DMODEL, 0>,
                         cudaFuncAttributeMaxDynamicSharedMemorySize, GEMM_SMEM_B);

    uint32_t *d_xt, *d_wqkvt, *d_wprojt, *d_attnt;
    cudaGetSymbolAddress((void**)&d_xt, g_xt);
    cudaGetSymbolAddress((void**)&d_wqkvt, g_wqkvt);
    cudaGetSymbolAddress((void**)&d_wprojt, g_wprojt);
    cudaGetSymbolAddress((void**)&d_attnt, g_attnt);

    // 0) convert+pair-permute operands to half2
    convert_permute_kernel<<<(ROWS * RWORDS) / 256, 256>>>(x, d_xt, ROWS * RWORDS);
    convert_permute_kernel<<<(QKV_N * RWORDS) / 256, 256>>>(qkv_w, d_wqkvt, QKV_N * RWORDS);
    convert_permute_kernel<<<(DMODEL * RWORDS) / 256, 256>>>(proj_w, d_wprojt, DMODEL * RWORDS);

    // 1) RoPE cos/sin table
    rope_table_kernel<<<(TSEQ * 32 + 255) / 256, 256>>>();

    // 2) QKV GEMM with fused RoPE epilogue -> g_qt/g_kt/g_vtr
    f16_gemm_kernel<QKV_N, 1><<<dim3(QKV_N / 128, ROWS / 128), 256, GEMM_SMEM_B>>>(
        d_xt, d_wqkvt, qkv_b, nullptr);

    // 3) causal flash attention (fp16 mma) -> permuted O into g_attnt
    flash_mma_kernel<<<dim3(TSEQ / FBQ, NHEADS, BATCH), 256>>>();

    // 4) out = attn @ proj_w^T + proj_b
    f16_gemm_kernel<DMODEL, 0><<<dim3(DMODEL / 128, ROWS / 128), 256, GEMM_SMEM_B>>>(
        d_attnt, d_wprojt, proj_b, out);
}

// round 15
// speedup vs baseline: 6.8433x; 1.0308x over previous
#include <cuda_runtime.h>
#include <cuda_fp16.h>
#include <math.h>
#include <cstdint>

// Problem constants
#define BATCH 2
#define TSEQ  2048
#define DMODEL 1024
#define NHEADS 16
#define HDIM  64
#define ROWS (BATCH * TSEQ)          // 4096
#define QKV_N (3 * DMODEL)           // 3072
#define RWORDS (DMODEL / 2)          // 512 half2 words per row

// ---------------- scratch (no allocation allowed) ----------------
__device__ uint32_t g_qt[BATCH * NHEADS * TSEQ * HDIM / 2];  // half2, prescaled
__device__ uint32_t g_kt[BATCH * NHEADS * TSEQ * HDIM / 2];  // half2
__device__ __half   g_vtr[BATCH * NHEADS * HDIM * TSEQ];     // V transposed [b,h,d,t]
__device__ float    g_cs[TSEQ * 32 * 2];                     // cos,sin per (t, freq)
// half2 column-pair-permuted operands for the GEMMs
__device__ uint32_t g_xt[ROWS * RWORDS];
__device__ uint32_t g_wqkvt[QKV_N * RWORDS];
__device__ uint32_t g_wprojt[DMODEL * RWORDS];
__device__ uint32_t g_attnt[ROWS * RWORDS];                  // flash writes permuted O

// ================= helpers =================
__device__ __forceinline__ uint32_t s2u(const void* p) {
    uint32_t a;
    asm("{ .reg .u64 t; cvta.to.shared.u64 t, %1; cvt.u32.u64 %0, t; }"
        : "=r"(a) : "l"(p));
    return a;
}
__device__ __forceinline__ float ex2(float x) {
    float y;
    asm("ex2.approx.ftz.f32 %0, %1;" : "=f"(y) : "f"(x));
    return y;
}
__device__ __forceinline__ void cp16(uint32_t dst, const void* src) {
    asm volatile("cp.async.cg.shared.global [%0], [%1], 16;" :: "r"(dst), "l"(src));
}
__device__ __forceinline__ uint32_t h2bits(float lo, float hi) {
    __half2 h = __floats2half2_rn(lo, hi);
    return *(uint32_t*)&h;
}
__device__ __forceinline__ void mma16(float* d, const uint32_t* a, uint32_t b0, uint32_t b1) {
    asm volatile(
        "mma.sync.aligned.m16n8k16.row.col.f32.f16.f16.f32 "
        "{%0,%1,%2,%3}, {%4,%5,%6,%7}, {%8,%9}, {%0,%1,%2,%3};"
        : "+f"(d[0]), "+f"(d[1]), "+f"(d[2]), "+f"(d[3])
        : "r"(a[0]), "r"(a[1]), "r"(a[2]), "r"(a[3]), "r"(b0), "r"(b1));
}

// ------- ONE kernel converts all three operands: f32 -> half2, pair-permuted -------
// dst word position p in each 32-word block holds source word c = (p&7)*4 + (p>>3)
#define NW_X   (ROWS * RWORDS)
#define NW_WQ  (QKV_N * RWORDS)
#define NW_WP  (DMODEL * RWORDS)
__global__ void convert_all_kernel(const float* __restrict__ x,
                                   const float* __restrict__ wqkv,
                                   const float* __restrict__ wproj)
{
    int idx = blockIdx.x * blockDim.x + threadIdx.x;
    const float* src;
    uint32_t* dst;
    int rel;
    if (idx < NW_X)                { src = x;     dst = g_xt;     rel = idx; }
    else if (idx < NW_X + NW_WQ)   { src = wqkv;  dst = g_wqkvt;  rel = idx - NW_X; }
    else                           { src = wproj; dst = g_wprojt; rel = idx - NW_X - NW_WQ; }
    int p = rel & 31;
    int c = (p & 7) * 4 + (p >> 3);
    int base = rel & ~31;
    float2 v = *(const float2*)(src + 2 * (size_t)(base + c));
    dst[rel] = h2bits(v.x, v.y);
}

// ================= fp16 mma GEMM: C[M,NCOLS] = A[M,1024] @ W[NCOLS,1024]^T + bias ======
// MODE 0: fp32 out. MODE 1: QKV fused RoPE epilogue -> g_qt/g_kt(half2)/g_vtr(transposed)
#define GSTR 36
#define GTILEW (128 * GSTR)
#define GSTAGEW (2 * GTILEW)
#define GSTAGES 3
#define GEMM_SMEM_B (GSTAGES * GSTAGEW * 4)      // 110592 bytes

template<int NCOLS, int MODE>
__global__ __launch_bounds__(256, 2) void f16_gemm_kernel(
    const uint32_t* __restrict__ A,
    const uint32_t* __restrict__ W,
    const float* __restrict__ bias,
    float* __restrict__ C)
{
    extern __shared__ uint32_t smw[];
    const int tid = threadIdx.x;
    const int wid = tid >> 5, lane = tid & 31;
    const int g = lane >> 2, tg = lane & 3;
    const int wm = wid & 3, wn = wid >> 2;
    const int bm = blockIdx.y * 128, bn = blockIdx.x * 128;

    float acc[2][8][4];
    #pragma unroll
    for (int t = 0; t < 2; t++)
        #pragma unroll
        for (int nt = 0; nt < 8; nt++)
            #pragma unroll
            for (int j = 0; j < 4; j++) acc[t][nt][j] = 0.f;

    const int fo = 8 * (tg ^ (g & 3));

    uint32_t aDst[4], bDst[4];
    const uint32_t* aSrcB[4];
    const uint32_t* bSrcB[4];
    #pragma unroll
    for (int i = 0; i < 4; i++) {
        const int idx = i * 256 + tid;
        const int row = idx >> 3, q = idx & 7;
        const int sq = q ^ ((row & 3) << 1);
        aDst[i] = s2u(smw + row * GSTR + sq * 4);
        bDst[i] = aDst[i] + GTILEW * 4;
        aSrcB[i] = A + (size_t)(bm + row) * RWORDS + q * 4;
        bSrcB[i] = W + (size_t)(bn + row) * RWORDS + q * 4;
    }
    const uint32_t* aF = smw + (wm * 32 + g) * GSTR + fo;
    const uint32_t* bF = smw + GTILEW + (wn * 64 + g) * GSTR + fo;

    #define LOAD_CHUNK(c_, S_) do {                                                \
        _Pragma("unroll")                                                          \
        for (int i_ = 0; i_ < 4; i_++) {                                           \
            cp16(aDst[i_] + (S_) * GSTAGEW * 4, aSrcB[i_] + (c_) * 32);            \
            cp16(bDst[i_] + (S_) * GSTAGEW * 4, bSrcB[i_] + (c_) * 32);            \
        }                                                                          \
        asm volatile("cp.async.commit_group;" ::: "memory");                       \
    } while (0)

    #define GBODY(c_, S_, PF_) do {                                                \
        asm volatile("cp.async.wait_group 1;" ::: "memory");                       \
        __syncthreads();                                                           \
        if (PF_) { LOAD_CHUNK((c_) + 2, ((S_) + 2) % GSTAGES); }                   \
        else { asm volatile("cp.async.commit_group;" ::: "memory"); }              \
        const uint32_t* as_ = aF + (S_) * GSTAGEW;                                 \
        const uint32_t* bs_ = bF + (S_) * GSTAGEW;                                 \
        uint32_t a_[2][4][4];                                                      \
        _Pragma("unroll")                                                          \
        for (int t_ = 0; t_ < 2; t_++) {                                           \
            uint4 x0 = *(const uint4*)(as_ + t_ * 16 * GSTR);                      \
            uint4 x1 = *(const uint4*)(as_ + t_ * 16 * GSTR + 4);                  \
            uint4 y0 = *(const uint4*)(as_ + (t_ * 16 + 8) * GSTR);                \
            uint4 y1 = *(const uint4*)(as_ + (t_ * 16 + 8) * GSTR + 4);            \
            a_[t_][0][0]=x0.x; a_[t_][0][1]=y0.x; a_[t_][0][2]=x0.y; a_[t_][0][3]=y0.y; \
            a_[t_][1][0]=x0.z; a_[t_][1][1]=y0.z; a_[t_][1][2]=x0.w; a_[t_][1][3]=y0.w; \
            a_[t_][2][0]=x1.x; a_[t_][2][1]=y1.x; a_[t_][2][2]=x1.y; a_[t_][2][3]=y1.y; \
            a_[t_][3][0]=x1.z; a_[t_][3][1]=y1.z; a_[t_][3][2]=x1.w; a_[t_][3][3]=y1.w; \
        }                                                                          \
        _Pragma("unroll")                                                          \
        for (int nt_ = 0; nt_ < 8; nt_++) {                                        \
            uint4 b0 = *(const uint4*)(bs_ + nt_ * 8 * GSTR);                      \
            uint4 b1 = *(const uint4*)(bs_ + nt_ * 8 * GSTR + 4);                  \
            mma16(acc[0][nt_], a_[0][0], b0.x, b0.y);                              \
            mma16(acc[1][nt_], a_[1][0], b0.x, b0.y);                              \
            mma16(acc[0][nt_], a_[0][1], b0.z, b0.w);                              \
            mma16(acc[1][nt_], a_[1][1], b0.z, b0.w);                              \
            mma16(acc[0][nt_], a_[0][2], b1.x, b1.y);                              \
            mma16(acc[1][nt_], a_[1][2], b1.x, b1.y);                              \
            mma16(acc[0][nt_], a_[0][3], b1.z, b1.w);                              \
            mma16(acc[1][nt_], a_[1][3], b1.z, b1.w);                              \
        }                                                                          \
    } while (0)

    LOAD_CHUNK(0, 0);
    LOAD_CHUNK(1, 1);

    #pragma unroll 1
    for (int cb = 0; cb < 12; cb += 3) {
        GBODY(cb + 0, 0, 1);
        GBODY(cb + 1, 1, 1);
        GBODY(cb + 2, 2, 1);
    }
    GBODY(12, 0, 1);
    GBODY(13, 1, 1);
    GBODY(14, 2, 0);
    GBODY(15, 0, 0);
    #undef LOAD_CHUNK
    #undef GBODY

    if (MODE == 0) {
        #pragma unroll
        for (int t = 0; t < 2; t++) {
            const int r0 = bm + wm * 32 + t * 16 + g;
            #pragma unroll
            for (int nt = 0; nt < 8; nt++) {
                const int cc = bn + wn * 64 + nt * 8 + 2 * tg;
                const float b0 = bias[cc], b1 = bias[cc + 1];
                *(float2*)(C + (size_t)r0 * NCOLS + cc) =
                    make_float2(acc[t][nt][0] + b0, acc[t][nt][1] + b1);
                *(float2*)(C + (size_t)(r0 + 8) * NCOLS + cc) =
                    make_float2(acc[t][nt][2] + b0, acc[t][nt][3] + b1);
            }
        }
    } else {
        // fused RoPE epilogue; warp n-tile (64) = one head; pair c <-> c+32 in-thread.
        const int gcb = bn + wn * 64;
        const int region = gcb >> 10;           // 0=Q 1=K 2=V
        const int h = (gcb & 1023) >> 6;
        const int bb = bm >> 11;
        const float pre = 0.125f * 1.4426950408889634f;
        const float2* cs2 = (const float2*)g_cs;

        #pragma unroll
        for (int t = 0; t < 2; t++) {
            const int ta = (bm & 2047) + wm * 32 + t * 16 + g;
            const int tb = ta + 8;
            const size_t rowA = ((size_t)bb * NHEADS + h) * TSEQ + ta;
            const size_t wA = rowA * 32;            // 32 half2 words per row
            const size_t wB = wA + 8 * 32;
            #pragma unroll
            for (int nt = 0; nt < 4; nt++) {
                const int c0 = nt * 8 + 2 * tg;          // < 32
                const int wlo = nt * 4 + tg;             // half2 word index
                const float bl0 = bias[gcb + c0],      bl1 = bias[gcb + c0 + 1];
                const float bh0 = bias[gcb + c0 + 32], bh1 = bias[gcb + c0 + 33];
                float xA0 = acc[t][nt][0] + bl0,     xA1 = acc[t][nt][1] + bl1;
                float xB0 = acc[t][nt][2] + bl0,     xB1 = acc[t][nt][3] + bl1;
                float yA0 = acc[t][nt + 4][0] + bh0, yA1 = acc[t][nt + 4][1] + bh1;
                float yB0 = acc[t][nt + 4][2] + bh0, yB1 = acc[t][nt + 4][3] + bh1;

                if (region == 2) {
                    const size_t vb = ((size_t)bb * NHEADS + h) * HDIM;
                    g_vtr[(vb + c0)      * TSEQ + ta] = __float2half_rn(xA0);
                    g_vtr[(vb + c0 + 1)  * TSEQ + ta] = __float2half_rn(xA1);
                    g_vtr[(vb + c0 + 32) * TSEQ + ta] = __float2half_rn(yA0);
                    g_vtr[(vb + c0 + 33) * TSEQ + ta] = __float2half_rn(yA1);
                    g_vtr[(vb + c0)      * TSEQ + tb] = __float2half_rn(xB0);
                    g_vtr[(vb + c0 + 1)  * TSEQ + tb] = __float2half_rn(xB1);
                    g_vtr[(vb + c0 + 32) * TSEQ + tb] = __float2half_rn(yB0);
                    g_vtr[(vb + c0 + 33) * TSEQ + tb] = __float2half_rn(yB1);
                } else {
                    float2 ca0 = cs2[ta * 32 + c0];
                    float2 ca1 = cs2[ta * 32 + c0 + 1];
                    float2 cb0 = cs2[tb * 32 + c0];
                    float2 cb1 = cs2[tb * 32 + c0 + 1];
                    float loA0 = xA0 * ca0.x - yA0 * ca0.y, hiA0 = yA0 * ca0.x + xA0 * ca0.y;
                    float loA1 = xA1 * ca1.x - yA1 * ca1.y, hiA1 = yA1 * ca1.x + xA1 * ca1.y;
                    float loB0 = xB0 * cb0.x - yB0 * cb0.y, hiB0 = yB0 * cb0.x + xB0 * cb0.y;
                    float loB1 = xB1 * cb1.x - yB1 * cb1.y, hiB1 = yB1 * cb1.x + xB1 * cb1.y;
                    if (region == 0) {
                        g_qt[wA + wlo]      = h2bits(loA0 * pre, loA1 * pre);
                        g_qt[wA + wlo + 16] = h2bits(hiA0 * pre, hiA1 * pre);
                        g_qt[wB + wlo]      = h2bits(loB0 * pre, loB1 * pre);
                        g_qt[wB + wlo + 16] = h2bits(hiB0 * pre, hiB1 * pre);
                    } else {
                        g_kt[wA + wlo]      = h2bits(loA0, loA1);
                        g_kt[wA + wlo + 16] = h2bits(hiA0, hiA1);
                        g_kt[wB + wlo]      = h2bits(loB0, loB1);
                        g_kt[wB + wlo + 16] = h2bits(hiB0, hiB1);
                    }
                }
            }
        }
    }
}

// ---------------- RoPE table (fp32 sincos of the fp32 angle, matching reference) ------
__global__ void rope_table_kernel()
{
    int idx = blockIdx.x * blockDim.x + threadIdx.x;
    if (idx >= TSEQ * 32) return;
    int t = idx >> 5;
    int j = idx & 31;
    float invf = powf(10000.0f, -((float)(2 * j) / 64.0f));
    float angle = (float)t * invf;
    float s, c;
    sincosf(angle, &s, &c);
    g_cs[idx * 2 + 0] = c;
    g_cs[idx * 2 + 1] = s;
}

// ================= flash attention: fp16 mma.sync (shuffle-free PV) ==========
#define FBQ 128
#define FBKV 32
#define KSTR 36          // words per K row (32 payload + 4 pad)
#define VSTR 20          // words per V row (16 payload + 4 pad)
#define KTILE_B (FBKV * KSTR * 4)
#define VTILE_B (HDIM * VSTR * 4)

__global__ __launch_bounds__(256, 2) void flash_mma_kernel()
{
    const int tid  = threadIdx.x;
    const int w    = tid >> 5;
    const int lane = tid & 31;
    const int g    = lane >> 2;
    const int tg   = lane & 3;
    const int qt = (gridDim.x - 1) - blockIdx.x;
    const int h  = blockIdx.y;
    const int b  = blockIdx.z;
    const int qb = qt * FBQ;
    const int wb = qb + w * 16;
    const int rA = wb + g;
    const int rB = rA + 8;

    const float NEG = __int_as_float(0xff800000);

    __shared__ uint32_t Ks[2][FBKV * KSTR];
    __shared__ uint32_t Vs[2][HDIM * VSTR];

    // Q fragments: half2 words, prescaled, 4 k16 groups
    uint32_t qf[4][4];
    {
        const size_t base = (((size_t)b * NHEADS + h) * TSEQ) * 32;
        const uint32_t* q0 = g_qt + base + (size_t)rA * 32;
        const uint32_t* q1 = g_qt + base + (size_t)rB * 32;
        #pragma unroll
        for (int kc = 0; kc < 4; kc++) {
            qf[kc][0] = q0[kc * 8 + tg];
            qf[kc][1] = q1[kc * 8 + tg];
            qf[kc][2] = q0[kc * 8 + tg + 4];
            qf[kc][3] = q1[kc * 8 + tg + 4];
        }
    }

    float o[8][4];
    #pragma unroll
    for (int n = 0; n < 8; n++)
        #pragma unroll
        for (int j = 0; j < 4; j++) o[n][j] = 0.f;
    float mA = NEG, mB = NEG, lA = 0.f, lB = 0.f;

    const int ntiles = qb / FBKV + 4;      // always even

    const uint32_t* kSrc = g_kt + (((size_t)b * NHEADS + h) * TSEQ) * 32 + tid * 4;
    const int vd = tid >> 2, vc = tid & 3;
    const uint32_t* vSrc = (const uint32_t*)g_vtr
        + (((size_t)b * NHEADS + h) * HDIM + vd) * (TSEQ / 2) + vc * 4;
    const uint32_t kDst = s2u(&Ks[0][(tid >> 3) * KSTR + (tid & 7) * 4]);
    const uint32_t vDst = s2u(&Vs[0][vd * VSTR + vc * 4]);

    #define FLOAD(t0_, S_) do {                                                    \
        cp16(kDst + (S_) * KTILE_B, kSrc + (t0_) * 1024);                          \
        cp16(vDst + (S_) * VTILE_B, vSrc + (t0_) * 16);                            \
        asm volatile("cp.async.commit_group;" ::: "memory");                       \
    } while (0)

    #define FBODY(t0_, S_) do {                                                    \
        const int j0 = (t0_) * FBKV;                                               \
        asm volatile("cp.async.wait_group 0;" ::: "memory");                       \
        __syncthreads();                                                           \
        if ((t0_) + 1 < ntiles) FLOAD((t0_) + 1, ((S_) + 1) & 1);                  \
        if (j0 <= wb) {                                                            \
            const uint32_t* ksm = Ks[S_];                                          \
            const uint32_t* vsm = Vs[S_];                                          \
            float s[4][4];                                                         \
            _Pragma("unroll")                                                      \
            for (int nt = 0; nt < 4; nt++) {                                       \
                s[nt][0] = 0.f; s[nt][1] = 0.f; s[nt][2] = 0.f; s[nt][3] = 0.f;    \
            }                                                                      \
            _Pragma("unroll")                                                      \
            for (int kc = 0; kc < 4; kc++) {                                       \
                _Pragma("unroll")                                                  \
                for (int nt = 0; nt < 4; nt++) {                                   \
                    uint32_t b0 = ksm[(nt * 8 + g) * KSTR + kc * 8 + tg];          \
                    uint32_t b1 = ksm[(nt * 8 + g) * KSTR + kc * 8 + tg + 4];      \
                    mma16(s[nt], qf[kc], b0, b1);                                  \
                }                                                                  \
            }                                                                      \
            float mtA = mA, mtB = mB;                                              \
            _Pragma("unroll")                                                      \
            for (int nt = 0; nt < 4; nt++) {                                       \
                const int jc = j0 + nt * 8 + 2 * tg;                               \
                s[nt][0] = (jc     <= rA) ? s[nt][0] : NEG;                        \
                s[nt][1] = (jc + 1 <= rA) ? s[nt][1] : NEG;                        \
                s[nt][2] = (jc     <= rB) ? s[nt][2] : NEG;                        \
                s[nt][3] = (jc + 1 <= rB) ? s[nt][3] : NEG;                        \
                mtA = fmaxf(mtA, fmaxf(s[nt][0], s[nt][1]));                       \
                mtB = fmaxf(mtB, fmaxf(s[nt][2], s[nt][3]));                       \
            }                                                                      \
            mtA = fmaxf(mtA, __shfl_xor_sync(0xffffffffu, mtA, 1));                \
            mtA = fmaxf(mtA, __shfl_xor_sync(0xffffffffu, mtA, 2));                \
            mtB = fmaxf(mtB, __shfl_xor_sync(0xffffffffu, mtB, 1));                \
            mtB = fmaxf(mtB, __shfl_xor_sync(0xffffffffu, mtB, 2));                \
            const float corrA = ex2(mA - mtA);                                     \
            const float corrB = ex2(mB - mtB);                                     \
            mA = mtA; mB = mtB;                                                    \
            uint32_t phA[4], phB[4];                                               \
            float sumA = 0.f, sumB = 0.f;                                          \
            _Pragma("unroll")                                                      \
            for (int nt = 0; nt < 4; nt++) {                                       \
                float pA0 = ex2(s[nt][0] - mtA), pA1 = ex2(s[nt][1] - mtA);        \
                float pB0 = ex2(s[nt][2] - mtB), pB1 = ex2(s[nt][3] - mtB);        \
                sumA += pA0 + pA1; sumB += pB0 + pB1;                              \
                phA[nt] = h2bits(pA0, pA1);                                        \
                phB[nt] = h2bits(pB0, pB1);                                        \
            }                                                                      \
            sumA += __shfl_xor_sync(0xffffffffu, sumA, 1);                         \
            sumA += __shfl_xor_sync(0xffffffffu, sumA, 2);                         \
            sumB += __shfl_xor_sync(0xffffffffu, sumB, 1);                         \
            sumB += __shfl_xor_sync(0xffffffffu, sumB, 2);                         \
            lA = lA * corrA + sumA;                                                \
            lB = lB * corrB + sumB;                                                \
            _Pragma("unroll")                                                      \
            for (int n = 0; n < 8; n++) {                                          \
                o[n][0] *= corrA; o[n][1] *= corrA;                                \
                o[n][2] *= corrB; o[n][3] *= corrB;                                \
            }                                                                      \
            _Pragma("unroll")                                                      \
            for (int kc2 = 0; kc2 < 2; kc2++) {                                    \
                uint32_t af[4];                                                    \
                af[0] = phA[2 * kc2];                                              \
                af[1] = phB[2 * kc2];                                              \
                af[2] = phA[2 * kc2 + 1];                                          \
                af[3] = phB[2 * kc2 + 1];                                          \
                _Pragma("unroll")                                                  \
                for (int nt2 = 0; nt2 < 8; nt2++) {                                \
                    uint32_t b0 = vsm[(nt2 * 8 + g) * VSTR + kc2 * 8 + tg];        \
                    uint32_t b1 = vsm[(nt2 * 8 + g) * VSTR + kc2 * 8 + tg + 4];    \
                    mma16(o[nt2], af, b0, b1);                                     \
                }                                                                  \
            }                                                                      \
        }                                                                          \
    } while (0)

    FLOAD(0, 0);

    #pragma unroll 1
    for (int t0 = 0; t0 < ntiles; t0 += 2) {
        FBODY(t0, 0);
        FBODY(t0 + 1, 1);
    }
    #undef FLOAD
    #undef FBODY

    // ---- epilogue: O/l -> half2 word-permuted rows of g_attnt [B*T, 512 words] ----
    const float iA = 1.f / lA;
    const float iB = 1.f / lB;
    uint32_t* opA = g_attnt + ((size_t)b * TSEQ + rA) * RWORDS + h * 32;
    uint32_t* opB = g_attnt + ((size_t)b * TSEQ + rB) * RWORDS + h * 32;
    #pragma unroll
    for (int nt2 = 0; nt2 < 8; nt2++) {
        const int c = nt2 * 4 + tg;              // word index within head block
        const int p = (c & 3) * 8 + (c >> 2);    // permuted position
        opA[p] = h2bits(o[nt2][0] * iA, o[nt2][1] * iA);
        opB[p] = h2bits(o[nt2][2] * iB, o[nt2][3] * iB);
    }
}

// ---------------- launch ----------------
extern "C" void kernel_launch(void* const* d_in, const int* in_sizes, int n_in,
                              void* d_out, int out_size)
{
    const float* x      = (const float*)d_in[0];
    const float* qkv_w  = (const float*)d_in[1];
    const float* qkv_b  = (const float*)d_in[2];
    const float* proj_w = (const float*)d_in[3];
    const float* proj_b = (const float*)d_in[4];
    float* out = (float*)d_out;

    cudaFuncSetAttribute(f16_gemm_kernel<QKV_N, 1>,
                         cudaFuncAttributeMaxDynamicSharedMemorySize, GEMM_SMEM_B);
    cudaFuncSetAttribute(f16_gemm_kernel<DMODEL, 0>,
                         cudaFuncAttributeMaxDynamicSharedMemorySize, GEMM_SMEM_B);

    uint32_t *d_xt, *d_wqkvt, *d_wprojt, *d_attnt;
    cudaGetSymbolAddress((void**)&d_xt, g_xt);
    cudaGetSymbolAddress((void**)&d_wqkvt, g_wqkvt);
    cudaGetSymbolAddress((void**)&d_wprojt, g_wprojt);
    cudaGetSymbolAddress((void**)&d_attnt, g_attnt);

    // 0) RoPE cos/sin table (fp32)
    rope_table_kernel<<<(TSEQ * 32 + 255) / 256, 256>>>();

    // 1) convert+pair-permute ALL operands in one launch
    convert_all_kernel<<<(NW_X + NW_WQ + NW_WP) / 256, 256>>>(x, qkv_w, proj_w);

    // 2) QKV GEMM with fused RoPE epilogue -> g_qt/g_kt/g_vtr
    f16_gemm_kernel<QKV_N, 1><<<dim3(QKV_N / 128, ROWS / 128), 256, GEMM_SMEM_B>>>(
        d_xt, d_wqkvt, qkv_b, nullptr);

    // 3) causal flash attention (fp16 mma) -> permuted O into g_attnt
    flash_mma_kernel<<<dim3(TSEQ / FBQ, NHEADS, BATCH), 256>>>();

    // 4) out = attn @ proj_w^T + proj_b
    f16_gemm_kernel<DMODEL, 0><<<dim3(DMODEL / 128, ROWS / 128), 256, GEMM_SMEM_B>>>(
        d_attnt, d_wprojt, proj_b, out);
}

// round 16
// speedup vs baseline: 7.0943x; 1.0367x over previous
#include <cuda_runtime.h>
#include <cuda_fp16.h>
#include <math.h>
#include <cstdint>

// Problem constants
#define BATCH 2
#define TSEQ  2048
#define DMODEL 1024
#define NHEADS 16
#define HDIM  64
#define ROWS (BATCH * TSEQ)          // 4096
#define QKV_N (3 * DMODEL)           // 3072
#define RWORDS (DMODEL / 2)          // 512 half2 words per row

// ---------------- scratch (no allocation allowed) ----------------
__device__ uint32_t g_qt[BATCH * NHEADS * TSEQ * HDIM / 2];  // half2, prescaled
__device__ uint32_t g_kt[BATCH * NHEADS * TSEQ * HDIM / 2];  // half2
__device__ __half   g_vtr[BATCH * NHEADS * HDIM * TSEQ];     // V transposed [b,h,d,t]
__device__ float    g_cs[TSEQ * 32 * 2];                     // cos,sin per (t, freq)
// half2 column-pair-permuted operands for the GEMMs
__device__ uint32_t g_xt[ROWS * RWORDS];
__device__ uint32_t g_wqkvt[QKV_N * RWORDS];
__device__ uint32_t g_wprojt[DMODEL * RWORDS];
__device__ uint32_t g_attnt[ROWS * RWORDS];                  // flash writes permuted O

// ================= helpers =================
__device__ __forceinline__ uint32_t s2u(const void* p) {
    uint32_t a;
    asm("{ .reg .u64 t; cvta.to.shared.u64 t, %1; cvt.u32.u64 %0, t; }"
        : "=r"(a) : "l"(p));
    return a;
}
__device__ __forceinline__ float ex2(float x) {
    float y;
    asm("ex2.approx.ftz.f32 %0, %1;" : "=f"(y) : "f"(x));
    return y;
}
__device__ __forceinline__ void cp16(uint32_t dst, const void* src) {
    asm volatile("cp.async.cg.shared.global [%0], [%1], 16;" :: "r"(dst), "l"(src));
}
__device__ __forceinline__ uint32_t h2bits(float lo, float hi) {
    __half2 h = __floats2half2_rn(lo, hi);
    return *(uint32_t*)&h;
}
__device__ __forceinline__ void mma16(float* d, const uint32_t* a, uint32_t b0, uint32_t b1) {
    asm volatile(
        "mma.sync.aligned.m16n8k16.row.col.f32.f16.f16.f32 "
        "{%0,%1,%2,%3}, {%4,%5,%6,%7}, {%8,%9}, {%0,%1,%2,%3};"
        : "+f"(d[0]), "+f"(d[1]), "+f"(d[2]), "+f"(d[3])
        : "r"(a[0]), "r"(a[1]), "r"(a[2]), "r"(a[3]), "r"(b0), "r"(b1));
}

// ------- ONE kernel converts all three operands: f32 -> half2, pair-permuted -------
#define NW_X   (ROWS * RWORDS)
#define NW_WQ  (QKV_N * RWORDS)
#define NW_WP  (DMODEL * RWORDS)
__global__ void convert_all_kernel(const float* __restrict__ x,
                                   const float* __restrict__ wqkv,
                                   const float* __restrict__ wproj)
{
    int idx = blockIdx.x * blockDim.x + threadIdx.x;
    const float* src;
    uint32_t* dst;
    int rel;
    if (idx < NW_X)                { src = x;     dst = g_xt;     rel = idx; }
    else if (idx < NW_X + NW_WQ)   { src = wqkv;  dst = g_wqkvt;  rel = idx - NW_X; }
    else                           { src = wproj; dst = g_wprojt; rel = idx - NW_X - NW_WQ; }
    int p = rel & 31;
    int c = (p & 7) * 4 + (p >> 3);
    int base = rel & ~31;
    float2 v = *(const float2*)(src + 2 * (size_t)(base + c));
    dst[rel] = h2bits(v.x, v.y);
}

// ================= fp16 mma GEMM (unchanged from R15) =================
#define GSTR 36
#define GTILEW (128 * GSTR)
#define GSTAGEW (2 * GTILEW)
#define GSTAGES 3
#define GEMM_SMEM_B (GSTAGES * GSTAGEW * 4)      // 110592 bytes

template<int NCOLS, int MODE>
__global__ __launch_bounds__(256, 2) void f16_gemm_kernel(
    const uint32_t* __restrict__ A,
    const uint32_t* __restrict__ W,
    const float* __restrict__ bias,
    float* __restrict__ C)
{
    extern __shared__ uint32_t smw[];
    const int tid = threadIdx.x;
    const int wid = tid >> 5, lane = tid & 31;
    const int g = lane >> 2, tg = lane & 3;
    const int wm = wid & 3, wn = wid >> 2;
    const int bm = blockIdx.y * 128, bn = blockIdx.x * 128;

    float acc[2][8][4];
    #pragma unroll
    for (int t = 0; t < 2; t++)
        #pragma unroll
        for (int nt = 0; nt < 8; nt++)
            #pragma unroll
            for (int j = 0; j < 4; j++) acc[t][nt][j] = 0.f;

    const int fo = 8 * (tg ^ (g & 3));

    uint32_t aDst[4], bDst[4];
    const uint32_t* aSrcB[4];
    const uint32_t* bSrcB[4];
    #pragma unroll
    for (int i = 0; i < 4; i++) {
        const int idx = i * 256 + tid;
        const int row = idx >> 3, q = idx & 7;
        const int sq = q ^ ((row & 3) << 1);
        aDst[i] = s2u(smw + row * GSTR + sq * 4);
        bDst[i] = aDst[i] + GTILEW * 4;
        aSrcB[i] = A + (size_t)(bm + row) * RWORDS + q * 4;
        bSrcB[i] = W + (size_t)(bn + row) * RWORDS + q * 4;
    }
    const uint32_t* aF = smw + (wm * 32 + g) * GSTR + fo;
    const uint32_t* bF = smw + GTILEW + (wn * 64 + g) * GSTR + fo;

    #define LOAD_CHUNK(c_, S_) do {                                                \
        _Pragma("unroll")                                                          \
        for (int i_ = 0; i_ < 4; i_++) {                                           \
            cp16(aDst[i_] + (S_) * GSTAGEW * 4, aSrcB[i_] + (c_) * 32);            \
            cp16(bDst[i_] + (S_) * GSTAGEW * 4, bSrcB[i_] + (c_) * 32);            \
        }                                                                          \
        asm volatile("cp.async.commit_group;" ::: "memory");                       \
    } while (0)

    #define GBODY(c_, S_, PF_) do {                                                \
        asm volatile("cp.async.wait_group 1;" ::: "memory");                       \
        __syncthreads();                                                           \
        if (PF_) { LOAD_CHUNK((c_) + 2, ((S_) + 2) % GSTAGES); }                   \
        else { asm volatile("cp.async.commit_group;" ::: "memory"); }              \
        const uint32_t* as_ = aF + (S_) * GSTAGEW;                                 \
        const uint32_t* bs_ = bF + (S_) * GSTAGEW;                                 \
        uint32_t a_[2][4][4];                                                      \
        _Pragma("unroll")                                                          \
        for (int t_ = 0; t_ < 2; t_++) {                                           \
            uint4 x0 = *(const uint4*)(as_ + t_ * 16 * GSTR);                      \
            uint4 x1 = *(const uint4*)(as_ + t_ * 16 * GSTR + 4);                  \
            uint4 y0 = *(const uint4*)(as_ + (t_ * 16 + 8) * GSTR);                \
            uint4 y1 = *(const uint4*)(as_ + (t_ * 16 + 8) * GSTR + 4);            \
            a_[t_][0][0]=x0.x; a_[t_][0][1]=y0.x; a_[t_][0][2]=x0.y; a_[t_][0][3]=y0.y; \
            a_[t_][1][0]=x0.z; a_[t_][1][1]=y0.z; a_[t_][1][2]=x0.w; a_[t_][1][3]=y0.w; \
            a_[t_][2][0]=x1.x; a_[t_][2][1]=y1.x; a_[t_][2][2]=x1.y; a_[t_][2][3]=y1.y; \
            a_[t_][3][0]=x1.z; a_[t_][3][1]=y1.z; a_[t_][3][2]=x1.w; a_[t_][3][3]=y1.w; \
        }                                                                          \
        _Pragma("unroll")                                                          \
        for (int nt_ = 0; nt_ < 8; nt_++) {                                        \
            uint4 b0 = *(const uint4*)(bs_ + nt_ * 8 * GSTR);                      \
            uint4 b1 = *(const uint4*)(bs_ + nt_ * 8 * GSTR + 4);                  \
            mma16(acc[0][nt_], a_[0][0], b0.x, b0.y);                              \
            mma16(acc[1][nt_], a_[1][0], b0.x, b0.y);                              \
            mma16(acc[0][nt_], a_[0][1], b0.z, b0.w);                              \
            mma16(acc[1][nt_], a_[1][1], b0.z, b0.w);                              \
            mma16(acc[0][nt_], a_[0][2], b1.x, b1.y);                              \
            mma16(acc[1][nt_], a_[1][2], b1.x, b1.y);                              \
            mma16(acc[0][nt_], a_[0][3], b1.z, b1.w);                              \
            mma16(acc[1][nt_], a_[1][3], b1.z, b1.w);                              \
        }                                                                          \
    } while (0)

    LOAD_CHUNK(0, 0);
    LOAD_CHUNK(1, 1);

    #pragma unroll 1
    for (int cb = 0; cb < 12; cb += 3) {
        GBODY(cb + 0, 0, 1);
        GBODY(cb + 1, 1, 1);
        GBODY(cb + 2, 2, 1);
    }
    GBODY(12, 0, 1);
    GBODY(13, 1, 1);
    GBODY(14, 2, 0);
    GBODY(15, 0, 0);
    #undef LOAD_CHUNK
    #undef GBODY

    if (MODE == 0) {
        #pragma unroll
        for (int t = 0; t < 2; t++) {
            const int r0 = bm + wm * 32 + t * 16 + g;
            #pragma unroll
            for (int nt = 0; nt < 8; nt++) {
                const int cc = bn + wn * 64 + nt * 8 + 2 * tg;
                const float b0 = bias[cc], b1 = bias[cc + 1];
                *(float2*)(C + (size_t)r0 * NCOLS + cc) =
                    make_float2(acc[t][nt][0] + b0, acc[t][nt][1] + b1);
                *(float2*)(C + (size_t)(r0 + 8) * NCOLS + cc) =
                    make_float2(acc[t][nt][2] + b0, acc[t][nt][3] + b1);
            }
        }
    } else {
        const int gcb = bn + wn * 64;
        const int region = gcb >> 10;           // 0=Q 1=K 2=V
        const int h = (gcb & 1023) >> 6;
        const int bb = bm >> 11;
        const float pre = 0.125f * 1.4426950408889634f;
        const float2* cs2 = (const float2*)g_cs;

        #pragma unroll
        for (int t = 0; t < 2; t++) {
            const int ta = (bm & 2047) + wm * 32 + t * 16 + g;
            const int tb = ta + 8;
            const size_t rowA = ((size_t)bb * NHEADS + h) * TSEQ + ta;
            const size_t wA = rowA * 32;
            const size_t wB = wA + 8 * 32;
            #pragma unroll
            for (int nt = 0; nt < 4; nt++) {
                const int c0 = nt * 8 + 2 * tg;
                const int wlo = nt * 4 + tg;
                const float bl0 = bias[gcb + c0],      bl1 = bias[gcb + c0 + 1];
                const float bh0 = bias[gcb + c0 + 32], bh1 = bias[gcb + c0 + 33];
                float xA0 = acc[t][nt][0] + bl0,     xA1 = acc[t][nt][1] + bl1;
                float xB0 = acc[t][nt][2] + bl0,     xB1 = acc[t][nt][3] + bl1;
                float yA0 = acc[t][nt + 4][0] + bh0, yA1 = acc[t][nt + 4][1] + bh1;
                float yB0 = acc[t][nt + 4][2] + bh0, yB1 = acc[t][nt + 4][3] + bh1;

                if (region == 2) {
                    const size_t vb = ((size_t)bb * NHEADS + h) * HDIM;
                    g_vtr[(vb + c0)      * TSEQ + ta] = __float2half_rn(xA0);
                    g_vtr[(vb + c0 + 1)  * TSEQ + ta] = __float2half_rn(xA1);
                    g_vtr[(vb + c0 + 32) * TSEQ + ta] = __float2half_rn(yA0);
                    g_vtr[(vb + c0 + 33) * TSEQ + ta] = __float2half_rn(yA1);
                    g_vtr[(vb + c0)      * TSEQ + tb] = __float2half_rn(xB0);
                    g_vtr[(vb + c0 + 1)  * TSEQ + tb] = __float2half_rn(xB1);
                    g_vtr[(vb + c0 + 32) * TSEQ + tb] = __float2half_rn(yB0);
                    g_vtr[(vb + c0 + 33) * TSEQ + tb] = __float2half_rn(yB1);
                } else {
                    float2 ca0 = cs2[ta * 32 + c0];
                    float2 ca1 = cs2[ta * 32 + c0 + 1];
                    float2 cb0 = cs2[tb * 32 + c0];
                    float2 cb1 = cs2[tb * 32 + c0 + 1];
                    float loA0 = xA0 * ca0.x - yA0 * ca0.y, hiA0 = yA0 * ca0.x + xA0 * ca0.y;
                    float loA1 = xA1 * ca1.x - yA1 * ca1.y, hiA1 = yA1 * ca1.x + xA1 * ca1.y;
                    float loB0 = xB0 * cb0.x - yB0 * cb0.y, hiB0 = yB0 * cb0.x + xB0 * cb0.y;
                    float loB1 = xB1 * cb1.x - yB1 * cb1.y, hiB1 = yB1 * cb1.x + xB1 * cb1.y;
                    if (region == 0) {
                        g_qt[wA + wlo]      = h2bits(loA0 * pre, loA1 * pre);
                        g_qt[wA + wlo + 16] = h2bits(hiA0 * pre, hiA1 * pre);
                        g_qt[wB + wlo]      = h2bits(loB0 * pre, loB1 * pre);
                        g_qt[wB + wlo + 16] = h2bits(hiB0 * pre, hiB1 * pre);
                    } else {
                        g_kt[wA + wlo]      = h2bits(loA0, loA1);
                        g_kt[wA + wlo + 16] = h2bits(hiA0, hiA1);
                        g_kt[wB + wlo]      = h2bits(loB0, loB1);
                        g_kt[wB + wlo + 16] = h2bits(hiB0, hiB1);
                    }
                }
            }
        }
    }
}

// ---------------- RoPE table (fp32) ----------------
__global__ void rope_table_kernel()
{
    int idx = blockIdx.x * blockDim.x + threadIdx.x;
    if (idx >= TSEQ * 32) return;
    int t = idx >> 5;
    int j = idx & 31;
    float invf = powf(10000.0f, -((float)(2 * j) / 64.0f));
    float angle = (float)t * invf;
    float s, c;
    sincosf(angle, &s, &c);
    g_cs[idx * 2 + 0] = c;
    g_cs[idx * 2 + 1] = s;
}

// ================= flash attention: fp16 mma, 64-key tiles, branch-free interior =====
#define FBQ 128
#define FBKV 32
#define FTILE 64
#define KSTR 36          // words per K key-row (32 payload + 4 pad)
#define VSTR 36          // words per V d-row (32 payload = 64 keys + 4 pad)
#define KTILE_B (FTILE * KSTR * 4)
#define VTILE_B (HDIM * VSTR * 4)

__global__ __launch_bounds__(256, 2) void flash_mma_kernel()
{
    const int tid  = threadIdx.x;
    const int w    = tid >> 5;
    const int lane = tid & 31;
    const int g    = lane >> 2;
    const int tg   = lane & 3;
    const int qt = (gridDim.x - 1) - blockIdx.x;
    const int h  = blockIdx.y;
    const int b  = blockIdx.z;
    const int qb = qt * FBQ;
    const int wb = qb + w * 16;
    const int rA = wb + g;
    const int rB = rA + 8;

    const float NEG = __int_as_float(0xff800000);

    __shared__ uint32_t Ks[2][FTILE * KSTR];
    __shared__ uint32_t Vs[2][HDIM * VSTR];

    // Q fragments
    uint32_t qf[4][4];
    {
        const size_t base = (((size_t)b * NHEADS + h) * TSEQ) * 32;
        const uint32_t* q0 = g_qt + base + (size_t)rA * 32;
        const uint32_t* q1 = g_qt + base + (size_t)rB * 32;
        #pragma unroll
        for (int kc = 0; kc < 4; kc++) {
            qf[kc][0] = q0[kc * 8 + tg];
            qf[kc][1] = q1[kc * 8 + tg];
            qf[kc][2] = q0[kc * 8 + tg + 4];
            qf[kc][3] = q1[kc * 8 + tg + 4];
        }
    }

    float o[8][4];
    #pragma unroll
    for (int n = 0; n < 8; n++)
        #pragma unroll
        for (int j = 0; j < 4; j++) o[n][j] = 0.f;
    float mA = NEG, mB = NEG, lA = 0.f, lB = 0.f;

    const int nt64 = (qb + FBQ) / FTILE;      // = 2*qt + 2, always even

    // hoisted cp.async addressing (stage 0): 2 K + 2 V cp16 per thread per 64-key tile
    uint32_t kDst[2], vDst[2];
    const uint32_t* kSrcB[2];
    const uint32_t* vSrcB[2];
    #pragma unroll
    for (int i = 0; i < 2; i++) {
        const int idx = i * 256 + tid;
        const int row = idx >> 3, q = idx & 7;
        kDst[i] = s2u(&Ks[0][row * KSTR + q * 4]);
        vDst[i] = s2u(&Vs[0][row * VSTR + q * 4]);
        kSrcB[i] = g_kt + (((size_t)b * NHEADS + h) * TSEQ) * 32 + (size_t)idx * 4;
        vSrcB[i] = (const uint32_t*)g_vtr
            + (((size_t)b * NHEADS + h) * HDIM + row) * (TSEQ / 2) + q * 4;
    }

    #define FLOAD(t64_, S_) do {                                                   \
        _Pragma("unroll")                                                          \
        for (int i_ = 0; i_ < 2; i_++) {                                           \
            cp16(kDst[i_] + (S_) * KTILE_B, kSrcB[i_] + (t64_) * 2048);            \
            cp16(vDst[i_] + (S_) * VTILE_B, vSrcB[i_] + (t64_) * 32);              \
        }                                                                          \
        asm volatile("cp.async.commit_group;" ::: "memory");                       \
    } while (0)

    // 32-key subtile: KB_ = Ks row base, VOFF_ = word offset in V rows
    #define FSUB(j0s_, KB_, vsm_, VOFF_) do {                                       \
        float s[4][4];                                                             \
        _Pragma("unroll")                                                          \
        for (int nt = 0; nt < 4; nt++) {                                           \
            s[nt][0] = 0.f; s[nt][1] = 0.f; s[nt][2] = 0.f; s[nt][3] = 0.f;        \
        }                                                                          \
        _Pragma("unroll")                                                          \
        for (int kc = 0; kc < 4; kc++) {                                           \
            _Pragma("unroll")                                                      \
            for (int nt = 0; nt < 4; nt++) {                                       \
                uint32_t b0 = (KB_)[(nt * 8 + g) * KSTR + kc * 8 + tg];            \
                uint32_t b1 = (KB_)[(nt * 8 + g) * KSTR + kc * 8 + tg + 4];        \
                mma16(s[nt], qf[kc], b0, b1);                                      \
            }                                                                      \
        }                                                                          \
        if ((j0s_) + FBKV - 1 > wb) {   /* diagonal subtile only */                \
            _Pragma("unroll")                                                      \
            for (int nt = 0; nt < 4; nt++) {                                       \
                const int jc = (j0s_) + nt * 8 + 2 * tg;                           \
                s[nt][0] = (jc     <= rA) ? s[nt][0] : NEG;                        \
                s[nt][1] = (jc + 1 <= rA) ? s[nt][1] : NEG;                        \
                s[nt][2] = (jc     <= rB) ? s[nt][2] : NEG;                        \
                s[nt][3] = (jc + 1 <= rB) ? s[nt][3] : NEG;                        \
            }                                                                      \
        }                                                                          \
        float mtA = mA, mtB = mB;                                                  \
        _Pragma("unroll")                                                          \
        for (int nt = 0; nt < 4; nt++) {                                           \
            mtA = fmaxf(mtA, fmaxf(s[nt][0], s[nt][1]));                           \
            mtB = fmaxf(mtB, fmaxf(s[nt][2], s[nt][3]));                           \
        }                                                                          \
        mtA = fmaxf(mtA, __shfl_xor_sync(0xffffffffu, mtA, 1));                    \
        mtA = fmaxf(mtA, __shfl_xor_sync(0xffffffffu, mtA, 2));                    \
        mtB = fmaxf(mtB, __shfl_xor_sync(0xffffffffu, mtB, 1));                    \
        mtB = fmaxf(mtB, __shfl_xor_sync(0xffffffffu, mtB, 2));                    \
        const float corrA = ex2(mA - mtA);                                         \
        const float corrB = ex2(mB - mtB);                                         \
        mA = mtA; mB = mtB;                                                        \
        uint32_t phA[4], phB[4];                                                   \
        float sumA = 0.f, sumB = 0.f;                                              \
        _Pragma("unroll")                                                          \
        for (int nt = 0; nt < 4; nt++) {                                           \
            float pA0 = ex2(s[nt][0] - mtA), pA1 = ex2(s[nt][1] - mtA);            \
            float pB0 = ex2(s[nt][2] - mtB), pB1 = ex2(s[nt][3] - mtB);            \
            sumA += pA0 + pA1; sumB += pB0 + pB1;                                  \
            phA[nt] = h2bits(pA0, pA1);                                            \
            phB[nt] = h2bits(pB0, pB1);                                            \
        }                                                                          \
        sumA += __shfl_xor_sync(0xffffffffu, sumA, 1);                             \
        sumA += __shfl_xor_sync(0xffffffffu, sumA, 2);                             \
        sumB += __shfl_xor_sync(0xffffffffu, sumB, 1);                             \
        sumB += __shfl_xor_sync(0xffffffffu, sumB, 2);                             \
        lA = lA * corrA + sumA;                                                    \
        lB = lB * corrB + sumB;                                                    \
        _Pragma("unroll")                                                          \
        for (int n = 0; n < 8; n++) {                                              \
            o[n][0] *= corrA; o[n][1] *= corrA;                                    \
            o[n][2] *= corrB; o[n][3] *= corrB;                                    \
        }                                                                          \
        _Pragma("unroll")                                                          \
        for (int kc2 = 0; kc2 < 2; kc2++) {                                        \
            uint32_t af[4];                                                        \
            af[0] = phA[2 * kc2];                                                  \
            af[1] = phB[2 * kc2];                                                  \
            af[2] = phA[2 * kc2 + 1];                                              \
            af[3] = phB[2 * kc2 + 1];                                              \
            _Pragma("unroll")                                                      \
            for (int nt2 = 0; nt2 < 8; nt2++) {                                    \
                uint32_t b0 = (vsm_)[(nt2 * 8 + g) * VSTR + (VOFF_) + kc2 * 8 + tg];      \
                uint32_t b1 = (vsm_)[(nt2 * 8 + g) * VSTR + (VOFF_) + kc2 * 8 + tg + 4];  \
                mma16(o[nt2], af, b0, b1);                                         \
            }                                                                      \
        }                                                                          \
    } while (0)

    #define FBODY64(t64_, S_) do {                                                 \
        const int j0 = (t64_) * FTILE;                                             \
        asm volatile("cp.async.wait_group 0;" ::: "memory");                       \
        __syncthreads();                                                           \
        if ((t64_) + 1 < nt64) FLOAD((t64_) + 1, ((S_) + 1) & 1);                  \
        if (j0 <= wb) {                                                            \
            const uint32_t* ksm = Ks[S_];                                          \
            const uint32_t* vsm = Vs[S_];                                          \
            FSUB(j0, ksm, vsm, 0);                                                 \
            const int j1 = j0 + FBKV;                                              \
            if (j1 <= wb) { FSUB(j1, ksm + 32 * KSTR, vsm, 16); }                  \
        }                                                                          \
    } while (0)

    FLOAD(0, 0);

    #pragma unroll 1
    for (int t64 = 0; t64 < nt64; t64 += 2) {
        FBODY64(t64, 0);
        FBODY64(t64 + 1, 1);
    }
    #undef FLOAD
    #undef FSUB
    #undef FBODY64

    // ---- epilogue: O/l -> half2 word-permuted rows of g_attnt ----
    const float iA = 1.f / lA;
    const float iB = 1.f / lB;
    uint32_t* opA = g_attnt + ((size_t)b * TSEQ + rA) * RWORDS + h * 32;
    uint32_t* opB = g_attnt + ((size_t)b * TSEQ + rB) * RWORDS + h * 32;
    #pragma unroll
    for (int nt2 = 0; nt2 < 8; nt2++) {
        const int c = nt2 * 4 + tg;
        const int p = (c & 3) * 8 + (c >> 2);
        opA[p] = h2bits(o[nt2][0] * iA, o[nt2][1] * iA);
        opB[p] = h2bits(o[nt2][2] * iB, o[nt2][3] * iB);
    }
}

// ---------------- launch ----------------
extern "C" void kernel_launch(void* const* d_in, const int* in_sizes, int n_in,
                              void* d_out, int out_size)
{
    const float* x      = (const float*)d_in[0];
    const float* qkv_w  = (const float*)d_in[1];
    const float* qkv_b  = (const float*)d_in[2];
    const float* proj_w = (const float*)d_in[3];
    const float* proj_b = (const float*)d_in[4];
    float* out = (float*)d_out;

    cudaFuncSetAttribute(f16_gemm_kernel<QKV_N, 1>,
                         cudaFuncAttributeMaxDynamicSharedMemorySize, GEMM_SMEM_B);
    cudaFuncSetAttribute(f16_gemm_kernel<DMODEL, 0>,
                         cudaFuncAttributeMaxDynamicSharedMemorySize, GEMM_SMEM_B);

    uint32_t *d_xt, *d_wqkvt, *d_wprojt, *d_attnt;
    cudaGetSymbolAddress((void**)&d_xt, g_xt);
    cudaGetSymbolAddress((void**)&d_wqkvt, g_wqkvt);
    cudaGetSymbolAddress((void**)&d_wprojt, g_wprojt);
    cudaGetSymbolAddress((void**)&d_attnt, g_attnt);

    // 0) RoPE cos/sin table
    rope_table_kernel<<<(TSEQ * 32 + 255) / 256, 256>>>();

    // 1) convert+pair-permute ALL operands in one launch
    convert_all_kernel<<<(NW_X + NW_WQ + NW_WP) / 256, 256>>>(x, qkv_w, proj_w);

    // 2) QKV GEMM with fused RoPE epilogue -> g_qt/g_kt/g_vtr
    f16_gemm_kernel<QKV_N, 1><<<dim3(QKV_N / 128, ROWS / 128), 256, GEMM_SMEM_B>>>(
        d_xt, d_wqkvt, qkv_b, nullptr);

    // 3) causal flash attention (fp16 mma) -> permuted O into g_attnt
    flash_mma_kernel<<<dim3(TSEQ / FBQ, NHEADS, BATCH), 256>>>();

    // 4) out = attn @ proj_w^T + proj_b
    f16_gemm_kernel<DMODEL, 0><<<dim3(DMODEL / 128, ROWS / 128), 256, GEMM_SMEM_B>>>(
        d_attnt, d_wprojt, proj_b, out);
}

// round 17
// speedup vs baseline: 7.2755x; 1.0255x over previous
#include <cuda_runtime.h>
#include <cuda_fp16.h>
#include <math.h>
#include <cstdint>

// Problem constants
#define BATCH 2
#define TSEQ  2048
#define DMODEL 1024
#define NHEADS 16
#define HDIM  64
#define ROWS (BATCH * TSEQ)          // 4096
#define QKV_N (3 * DMODEL)           // 3072
#define RWORDS (DMODEL / 2)          // 512 half2 words per row

// ---------------- scratch (no allocation allowed) ----------------
__device__ uint32_t g_qt[BATCH * NHEADS * TSEQ * HDIM / 2];  // half2, prescaled
__device__ uint32_t g_kt[BATCH * NHEADS * TSEQ * HDIM / 2];  // half2
__device__ __half   g_vtr[BATCH * NHEADS * HDIM * TSEQ];     // V transposed [b,h,d,t]
__device__ float    g_cs[TSEQ * 32 * 2];                     // cos,sin per (t, freq)
__device__ uint32_t g_xt[ROWS * RWORDS];
__device__ uint32_t g_wqkvt[QKV_N * RWORDS];
__device__ uint32_t g_wprojt[DMODEL * RWORDS];
__device__ uint32_t g_attnt[ROWS * RWORDS];                  // flash writes permuted O

// ================= helpers =================
__device__ __forceinline__ uint32_t s2u(const void* p) {
    uint32_t a;
    asm("{ .reg .u64 t; cvta.to.shared.u64 t, %1; cvt.u32.u64 %0, t; }"
        : "=r"(a) : "l"(p));
    return a;
}
__device__ __forceinline__ float ex2(float x) {
    float y;
    asm("ex2.approx.ftz.f32 %0, %1;" : "=f"(y) : "f"(x));
    return y;
}
__device__ __forceinline__ void cp16(uint32_t dst, const void* src) {
    asm volatile("cp.async.cg.shared.global [%0], [%1], 16;" :: "r"(dst), "l"(src));
}
__device__ __forceinline__ uint32_t h2bits(float lo, float hi) {
    __half2 h = __floats2half2_rn(lo, hi);
    return *(uint32_t*)&h;
}
__device__ __forceinline__ void mma16(float* d, const uint32_t* a, uint32_t b0, uint32_t b1) {
    asm volatile(
        "mma.sync.aligned.m16n8k16.row.col.f32.f16.f16.f32 "
        "{%0,%1,%2,%3}, {%4,%5,%6,%7}, {%8,%9}, {%0,%1,%2,%3};"
        : "+f"(d[0]), "+f"(d[1]), "+f"(d[2]), "+f"(d[3])
        : "r"(a[0]), "r"(a[1]), "r"(a[2]), "r"(a[3]), "r"(b0), "r"(b1));
}

// ------- ONE kernel: rope table + convert all three operands -------
#define NW_X   (ROWS * RWORDS)
#define NW_WQ  (QKV_N * RWORDS)
#define NW_WP  (DMODEL * RWORDS)
__global__ void convert_all_kernel(const float* __restrict__ x,
                                   const float* __restrict__ wqkv,
                                   const float* __restrict__ wproj)
{
    int idx = blockIdx.x * blockDim.x + threadIdx.x;

    if (idx < TSEQ * 32) {           // rope table side-job
        int t = idx >> 5;
        int j = idx & 31;
        float invf = powf(10000.0f, -((float)(2 * j) / 64.0f));
        float angle = (float)t * invf;
        float s, c;
        sincosf(angle, &s, &c);
        g_cs[idx * 2 + 0] = c;
        g_cs[idx * 2 + 1] = s;
    }

    const float* src;
    uint32_t* dst;
    int rel;
    if (idx < NW_X)                { src = x;     dst = g_xt;     rel = idx; }
    else if (idx < NW_X + NW_WQ)   { src = wqkv;  dst = g_wqkvt;  rel = idx - NW_X; }
    else                           { src = wproj; dst = g_wprojt; rel = idx - NW_X - NW_WQ; }
    int p = rel & 31;
    int c = (p & 7) * 4 + (p >> 3);
    int base = rel & ~31;
    float2 v = *(const float2*)(src + 2 * (size_t)(base + c));
    dst[rel] = h2bits(v.x, v.y);
}

// ================= fp16 mma GEMM (unchanged) =================
#define GSTR 36
#define GTILEW (128 * GSTR)
#define GSTAGEW (2 * GTILEW)
#define GSTAGES 3
#define GEMM_SMEM_B (GSTAGES * GSTAGEW * 4)      // 110592 bytes

template<int NCOLS, int MODE>
__global__ __launch_bounds__(256, 2) void f16_gemm_kernel(
    const uint32_t* __restrict__ A,
    const uint32_t* __restrict__ W,
    const float* __restrict__ bias,
    float* __restrict__ C)
{
    extern __shared__ uint32_t smw[];
    const int tid = threadIdx.x;
    const int wid = tid >> 5, lane = tid & 31;
    const int g = lane >> 2, tg = lane & 3;
    const int wm = wid & 3, wn = wid >> 2;
    const int bm = blockIdx.y * 128, bn = blockIdx.x * 128;

    float acc[2][8][4];
    #pragma unroll
    for (int t = 0; t < 2; t++)
        #pragma unroll
        for (int nt = 0; nt < 8; nt++)
            #pragma unroll
            for (int j = 0; j < 4; j++) acc[t][nt][j] = 0.f;

    const int fo = 8 * (tg ^ (g & 3));

    uint32_t aDst[4], bDst[4];
    const uint32_t* aSrcB[4];
    const uint32_t* bSrcB[4];
    #pragma unroll
    for (int i = 0; i < 4; i++) {
        const int idx = i * 256 + tid;
        const int row = idx >> 3, q = idx & 7;
        const int sq = q ^ ((row & 3) << 1);
        aDst[i] = s2u(smw + row * GSTR + sq * 4);
        bDst[i] = aDst[i] + GTILEW * 4;
        aSrcB[i] = A + (size_t)(bm + row) * RWORDS + q * 4;
        bSrcB[i] = W + (size_t)(bn + row) * RWORDS + q * 4;
    }
    const uint32_t* aF = smw + (wm * 32 + g) * GSTR + fo;
    const uint32_t* bF = smw + GTILEW + (wn * 64 + g) * GSTR + fo;

    #define LOAD_CHUNK(c_, S_) do {                                                \
        _Pragma("unroll")                                                          \
        for (int i_ = 0; i_ < 4; i_++) {                                           \
            cp16(aDst[i_] + (S_) * GSTAGEW * 4, aSrcB[i_] + (c_) * 32);            \
            cp16(bDst[i_] + (S_) * GSTAGEW * 4, bSrcB[i_] + (c_) * 32);            \
        }                                                                          \
        asm volatile("cp.async.commit_group;" ::: "memory");                       \
    } while (0)

    #define GBODY(c_, S_, PF_) do {                                                \
        asm volatile("cp.async.wait_group 1;" ::: "memory");                       \
        __syncthreads();                                                           \
        if (PF_) { LOAD_CHUNK((c_) + 2, ((S_) + 2) % GSTAGES); }                   \
        else { asm volatile("cp.async.commit_group;" ::: "memory"); }              \
        const uint32_t* as_ = aF + (S_) * GSTAGEW;                                 \
        const uint32_t* bs_ = bF + (S_) * GSTAGEW;                                 \
        uint32_t a_[2][4][4];                                                      \
        _Pragma("unroll")                                                          \
        for (int t_ = 0; t_ < 2; t_++) {                                           \
            uint4 x0 = *(const uint4*)(as_ + t_ * 16 * GSTR);                      \
            uint4 x1 = *(const uint4*)(as_ + t_ * 16 * GSTR + 4);                  \
            uint4 y0 = *(const uint4*)(as_ + (t_ * 16 + 8) * GSTR);                \
            uint4 y1 = *(const uint4*)(as_ + (t_ * 16 + 8) * GSTR + 4);            \
            a_[t_][0][0]=x0.x; a_[t_][0][1]=y0.x; a_[t_][0][2]=x0.y; a_[t_][0][3]=y0.y; \
            a_[t_][1][0]=x0.z; a_[t_][1][1]=y0.z; a_[t_][1][2]=x0.w; a_[t_][1][3]=y0.w; \
            a_[t_][2][0]=x1.x; a_[t_][2][1]=y1.x; a_[t_][2][2]=x1.y; a_[t_][2][3]=y1.y; \
            a_[t_][3][0]=x1.z; a_[t_][3][1]=y1.z; a_[t_][3][2]=x1.w; a_[t_][3][3]=y1.w; \
        }                                                                          \
        _Pragma("unroll")                                                          \
        for (int nt_ = 0; nt_ < 8; nt_++) {                                        \
            uint4 b0 = *(const uint4*)(bs_ + nt_ * 8 * GSTR);                      \
            uint4 b1 = *(const uint4*)(bs_ + nt_ * 8 * GSTR + 4);                  \
            mma16(acc[0][nt_], a_[0][0], b0.x, b0.y);                              \
            mma16(acc[1][nt_], a_[1][0], b0.x, b0.y);                              \
            mma16(acc[0][nt_], a_[0][1], b0.z, b0.w);                              \
            mma16(acc[1][nt_], a_[1][1], b0.z, b0.w);                              \
            mma16(acc[0][nt_], a_[0][2], b1.x, b1.y);                              \
            mma16(acc[1][nt_], a_[1][2], b1.x, b1.y);                              \
            mma16(acc[0][nt_], a_[0][3], b1.z, b1.w);                              \
            mma16(acc[1][nt_], a_[1][3], b1.z, b1.w);                              \
        }                                                                          \
    } while (0)

    LOAD_CHUNK(0, 0);
    LOAD_CHUNK(1, 1);

    #pragma unroll 1
    for (int cb = 0; cb < 12; cb += 3) {
        GBODY(cb + 0, 0, 1);
        GBODY(cb + 1, 1, 1);
        GBODY(cb + 2, 2, 1);
    }
    GBODY(12, 0, 1);
    GBODY(13, 1, 1);
    GBODY(14, 2, 0);
    GBODY(15, 0, 0);
    #undef LOAD_CHUNK
    #undef GBODY

    if (MODE == 0) {
        #pragma unroll
        for (int t = 0; t < 2; t++) {
            const int r0 = bm + wm * 32 + t * 16 + g;
            #pragma unroll
            for (int nt = 0; nt < 8; nt++) {
                const int cc = bn + wn * 64 + nt * 8 + 2 * tg;
                const float b0 = bias[cc], b1 = bias[cc + 1];
                *(float2*)(C + (size_t)r0 * NCOLS + cc) =
                    make_float2(acc[t][nt][0] + b0, acc[t][nt][1] + b1);
                *(float2*)(C + (size_t)(r0 + 8) * NCOLS + cc) =
                    make_float2(acc[t][nt][2] + b0, acc[t][nt][3] + b1);
            }
        }
    } else {
        const int gcb = bn + wn * 64;
        const int region = gcb >> 10;           // 0=Q 1=K 2=V
        const int h = (gcb & 1023) >> 6;
        const int bb = bm >> 11;
        const float pre = 0.125f * 1.4426950408889634f;
        const float2* cs2 = (const float2*)g_cs;

        #pragma unroll
        for (int t = 0; t < 2; t++) {
            const int ta = (bm & 2047) + wm * 32 + t * 16 + g;
            const int tb = ta + 8;
            const size_t rowA = ((size_t)bb * NHEADS + h) * TSEQ + ta;
            const size_t wA = rowA * 32;
            const size_t wB = wA + 8 * 32;
            #pragma unroll
            for (int nt = 0; nt < 4; nt++) {
                const int c0 = nt * 8 + 2 * tg;
                const int wlo = nt * 4 + tg;
                const float bl0 = bias[gcb + c0],      bl1 = bias[gcb + c0 + 1];
                const float bh0 = bias[gcb + c0 + 32], bh1 = bias[gcb + c0 + 33];
                float xA0 = acc[t][nt][0] + bl0,     xA1 = acc[t][nt][1] + bl1;
                float xB0 = acc[t][nt][2] + bl0,     xB1 = acc[t][nt][3] + bl1;
                float yA0 = acc[t][nt + 4][0] + bh0, yA1 = acc[t][nt + 4][1] + bh1;
                float yB0 = acc[t][nt + 4][2] + bh0, yB1 = acc[t][nt + 4][3] + bh1;

                if (region == 2) {
                    const size_t vb = ((size_t)bb * NHEADS + h) * HDIM;
                    g_vtr[(vb + c0)      * TSEQ + ta] = __float2half_rn(xA0);
                    g_vtr[(vb + c0 + 1)  * TSEQ + ta] = __float2half_rn(xA1);
                    g_vtr[(vb + c0 + 32) * TSEQ + ta] = __float2half_rn(yA0);
                    g_vtr[(vb + c0 + 33) * TSEQ + ta] = __float2half_rn(yA1);
                    g_vtr[(vb + c0)      * TSEQ + tb] = __float2half_rn(xB0);
                    g_vtr[(vb + c0 + 1)  * TSEQ + tb] = __float2half_rn(xB1);
                    g_vtr[(vb + c0 + 32) * TSEQ + tb] = __float2half_rn(yB0);
                    g_vtr[(vb + c0 + 33) * TSEQ + tb] = __float2half_rn(yB1);
                } else {
                    float2 ca0 = cs2[ta * 32 + c0];
                    float2 ca1 = cs2[ta * 32 + c0 + 1];
                    float2 cb0 = cs2[tb * 32 + c0];
                    float2 cb1 = cs2[tb * 32 + c0 + 1];
                    float loA0 = xA0 * ca0.x - yA0 * ca0.y, hiA0 = yA0 * ca0.x + xA0 * ca0.y;
                    float loA1 = xA1 * ca1.x - yA1 * ca1.y, hiA1 = yA1 * ca1.x + xA1 * ca1.y;
                    float loB0 = xB0 * cb0.x - yB0 * cb0.y, hiB0 = yB0 * cb0.x + xB0 * cb0.y;
                    float loB1 = xB1 * cb1.x - yB1 * cb1.y, hiB1 = yB1 * cb1.x + xB1 * cb1.y;
                    if (region == 0) {
                        g_qt[wA + wlo]      = h2bits(loA0 * pre, loA1 * pre);
                        g_qt[wA + wlo + 16] = h2bits(hiA0 * pre, hiA1 * pre);
                        g_qt[wB + wlo]      = h2bits(loB0 * pre, loB1 * pre);
                        g_qt[wB + wlo + 16] = h2bits(hiB0 * pre, hiB1 * pre);
                    } else {
                        g_kt[wA + wlo]      = h2bits(loA0, loA1);
                        g_kt[wA + wlo + 16] = h2bits(hiA0, hiA1);
                        g_kt[wB + wlo]      = h2bits(loB0, loB1);
                        g_kt[wB + wlo + 16] = h2bits(hiB0, hiB1);
                    }
                }
            }
        }
    }
}

// ================= flash attention: fp16 mma, 64-key tiles, merged softmax =====
#define FBQ 128
#define FBKV 32
#define FTILE 64
#define KSTR 36
#define VSTR 36
#define KTILE_B (FTILE * KSTR * 4)
#define VTILE_B (HDIM * VSTR * 4)

__global__ __launch_bounds__(256, 2) void flash_mma_kernel()
{
    const int tid  = threadIdx.x;
    const int w    = tid >> 5;
    const int lane = tid & 31;
    const int g    = lane >> 2;
    const int tg   = lane & 3;
    const int qt = (gridDim.x - 1) - blockIdx.x;
    const int h  = blockIdx.y;
    const int b  = blockIdx.z;
    const int qb = qt * FBQ;
    const int wb = qb + w * 16;
    const int rA = wb + g;
    const int rB = rA + 8;

    const float NEG = __int_as_float(0xff800000);

    __shared__ uint32_t Ks[2][FTILE * KSTR];
    __shared__ uint32_t Vs[2][HDIM * VSTR];

    uint32_t qf[4][4];
    {
        const size_t base = (((size_t)b * NHEADS + h) * TSEQ) * 32;
        const uint32_t* q0 = g_qt + base + (size_t)rA * 32;
        const uint32_t* q1 = g_qt + base + (size_t)rB * 32;
        #pragma unroll
        for (int kc = 0; kc < 4; kc++) {
            qf[kc][0] = q0[kc * 8 + tg];
            qf[kc][1] = q1[kc * 8 + tg];
            qf[kc][2] = q0[kc * 8 + tg + 4];
            qf[kc][3] = q1[kc * 8 + tg + 4];
        }
    }

    float o[8][4];
    #pragma unroll
    for (int n = 0; n < 8; n++)
        #pragma unroll
        for (int j = 0; j < 4; j++) o[n][j] = 0.f;
    float mA = NEG, mB = NEG, lA = 0.f, lB = 0.f;

    const int nt64 = (qb + FBQ) / FTILE;      // always even

    uint32_t kDst[2], vDst[2];
    const uint32_t* kSrcB[2];
    const uint32_t* vSrcB[2];
    #pragma unroll
    for (int i = 0; i < 2; i++) {
        const int idx = i * 256 + tid;
        const int row = idx >> 3, q = idx & 7;
        kDst[i] = s2u(&Ks[0][row * KSTR + q * 4]);
        vDst[i] = s2u(&Vs[0][row * VSTR + q * 4]);
        kSrcB[i] = g_kt + (((size_t)b * NHEADS + h) * TSEQ) * 32 + (size_t)idx * 4;
        vSrcB[i] = (const uint32_t*)g_vtr
            + (((size_t)b * NHEADS + h) * HDIM + row) * (TSEQ / 2) + q * 4;
    }

    #define FLOAD(t64_, S_) do {                                                   \
        _Pragma("unroll")                                                          \
        for (int i_ = 0; i_ < 2; i_++) {                                           \
            cp16(kDst[i_] + (S_) * KTILE_B, kSrcB[i_] + (t64_) * 2048);            \
            cp16(vDst[i_] + (S_) * VTILE_B, vSrcB[i_] + (t64_) * 32);              \
        }                                                                          \
        asm volatile("cp.async.commit_group;" ::: "memory");                       \
    } while (0)

    // QK for one 32-key subtile into s_[4][4]
    #define QK32(KB_, s_) do {                                                     \
        _Pragma("unroll")                                                          \
        for (int nt = 0; nt < 4; nt++) {                                           \
            s_[nt][0] = 0.f; s_[nt][1] = 0.f; s_[nt][2] = 0.f; s_[nt][3] = 0.f;    \
        }                                                                          \
        _Pragma("unroll")                                                          \
        for (int kc = 0; kc < 4; kc++) {                                           \
            _Pragma("unroll")                                                      \
            for (int nt = 0; nt < 4; nt++) {                                       \
                uint32_t b0 = (KB_)[(nt * 8 + g) * KSTR + kc * 8 + tg];            \
                uint32_t b1 = (KB_)[(nt * 8 + g) * KSTR + kc * 8 + tg + 4];        \
                mma16(s_[nt], qf[kc], b0, b1);                                     \
            }                                                                      \
        }                                                                          \
    } while (0)

    #define MASK32(j0s_, s_) do {                                                  \
        _Pragma("unroll")                                                          \
        for (int nt = 0; nt < 4; nt++) {                                           \
            const int jc = (j0s_) + nt * 8 + 2 * tg;                               \
            s_[nt][0] = (jc     <= rA) ? s_[nt][0] : NEG;                          \
            s_[nt][1] = (jc + 1 <= rA) ? s_[nt][1] : NEG;                          \
            s_[nt][2] = (jc     <= rB) ? s_[nt][2] : NEG;                          \
            s_[nt][3] = (jc + 1 <= rB) ? s_[nt][3] : NEG;                          \
        }                                                                          \
    } while (0)

    #define MAX32(s_, mtA_, mtB_) do {                                             \
        _Pragma("unroll")                                                          \
        for (int nt = 0; nt < 4; nt++) {                                           \
            mtA_ = fmaxf(mtA_, fmaxf(s_[nt][0], s_[nt][1]));                       \
            mtB_ = fmaxf(mtB_, fmaxf(s_[nt][2], s_[nt][3]));                       \
        }                                                                          \
    } while (0)

    // exp(s - m) -> ph, accumulate sums (uses updated mA/mB)
    #define EXP32(s_, phA_, phB_) do {                                             \
        _Pragma("unroll")                                                          \
        for (int nt = 0; nt < 4; nt++) {                                           \
            float pA0 = ex2(s_[nt][0] - mA), pA1 = ex2(s_[nt][1] - mA);            \
            float pB0 = ex2(s_[nt][2] - mB), pB1 = ex2(s_[nt][3] - mB);            \
            sumA += pA0 + pA1; sumB += pB0 + pB1;                                  \
            phA_[nt] = h2bits(pA0, pA1);                                           \
            phB_[nt] = h2bits(pB0, pB1);                                           \
        }                                                                          \
    } while (0)

    #define PV32(phA_, phB_, vsm_, VOFF_) do {                                     \
        _Pragma("unroll")                                                          \
        for (int kc2 = 0; kc2 < 2; kc2++) {                                        \
            uint32_t af[4];                                                        \
            af[0] = phA_[2 * kc2];                                                 \
            af[1] = phB_[2 * kc2];                                                 \
            af[2] = phA_[2 * kc2 + 1];                                             \
            af[3] = phB_[2 * kc2 + 1];                                             \
            _Pragma("unroll")                                                      \
            for (int nt2 = 0; nt2 < 8; nt2++) {                                    \
                uint32_t b0 = (vsm_)[(nt2 * 8 + g) * VSTR + (VOFF_) + kc2 * 8 + tg];      \
                uint32_t b1 = (vsm_)[(nt2 * 8 + g) * VSTR + (VOFF_) + kc2 * 8 + tg + 4];  \
                mma16(o[nt2], af, b0, b1);                                         \
            }                                                                      \
        }                                                                          \
    } while (0)

    #define RESCALE_O(cA_, cB_) do {                                               \
        _Pragma("unroll")                                                          \
        for (int n = 0; n < 8; n++) {                                              \
            o[n][0] *= cA_; o[n][1] *= cA_;                                        \
            o[n][2] *= cB_; o[n][3] *= cB_;                                        \
        }                                                                          \
    } while (0)

    #define REDUCE_MAX() do {                                                      \
        mtA = fmaxf(mtA, __shfl_xor_sync(0xffffffffu, mtA, 1));                    \
        mtA = fmaxf(mtA, __shfl_xor_sync(0xffffffffu, mtA, 2));                    \
        mtB = fmaxf(mtB, __shfl_xor_sync(0xffffffffu, mtB, 1));                    \
        mtB = fmaxf(mtB, __shfl_xor_sync(0xffffffffu, mtB, 2));                    \
    } while (0)

    #define REDUCE_SUM_L() do {                                                    \
        sumA += __shfl_xor_sync(0xffffffffu, sumA, 1);                             \
        sumA += __shfl_xor_sync(0xffffffffu, sumA, 2);                             \
        sumB += __shfl_xor_sync(0xffffffffu, sumB, 1);                             \
        sumB += __shfl_xor_sync(0xffffffffu, sumB, 2);                             \
        lA = lA * corrA + sumA;                                                    \
        lB = lB * corrB + sumB;                                                    \
    } while (0)

    #define FBODY64(t64_, S_) do {                                                 \
        const int j0 = (t64_) * FTILE;                                             \
        asm volatile("cp.async.wait_group 0;" ::: "memory");                       \
        __syncthreads();                                                           \
        if ((t64_) + 1 < nt64) FLOAD((t64_) + 1, ((S_) + 1) & 1);                  \
        if (j0 <= wb) {                                                            \
            const uint32_t* ksm = Ks[S_];                                          \
            const uint32_t* vsm = Vs[S_];                                          \
            const int j1 = j0 + FBKV;                                              \
            float s0[4][4];                                                        \
            QK32(ksm, s0);                                                         \
            if (j1 <= wb) {     /* both subtiles, ONE softmax over 64 keys */      \
                float s1[4][4];                                                    \
                QK32(ksm + 32 * KSTR, s1);                                         \
                if (j1 + FBKV - 1 > wb) MASK32(j1, s1);   /* s0 never diagonal */  \
                float mtA = mA, mtB = mB;                                          \
                MAX32(s0, mtA, mtB);                                               \
                MAX32(s1, mtA, mtB);                                               \
                REDUCE_MAX();                                                      \
                const float corrA = ex2(mA - mtA);                                 \
                const float corrB = ex2(mB - mtB);                                 \
                mA = mtA; mB = mtB;                                                \
                RESCALE_O(corrA, corrB);                                           \
                float sumA = 0.f, sumB = 0.f;                                      \
                uint32_t phA[4], phB[4];                                           \
                EXP32(s0, phA, phB);                                               \
                PV32(phA, phB, vsm, 0);                                            \
                EXP32(s1, phA, phB);                                               \
                PV32(phA, phB, vsm, 16);                                           \
                REDUCE_SUM_L();                                                    \
            } else {            /* diagonal 32-key subtile only */                 \
                MASK32(j0, s0);                                                    \
                float mtA = mA, mtB = mB;                                          \
                MAX32(s0, mtA, mtB);                                               \
                REDUCE_MAX();                                                      \
                const float corrA = ex2(mA - mtA);                                 \
                const float corrB = ex2(mB - mtB);                                 \
                mA = mtA; mB = mtB;                                                \
                RESCALE_O(corrA, corrB);                                           \
                float sumA = 0.f, sumB = 0.f;                                      \
                uint32_t phA[4], phB[4];                                           \
                EXP32(s0, phA, phB);                                               \
                PV32(phA, phB, vsm, 0);                                            \
                REDUCE_SUM_L();                                                    \
            }                                                                      \
        }                                                                          \
    } while (0)

    FLOAD(0, 0);

    #pragma unroll 1
    for (int t64 = 0; t64 < nt64; t64 += 2) {
        FBODY64(t64, 0);
        FBODY64(t64 + 1, 1);
    }
    #undef FLOAD
    #undef QK32
    #undef MASK32
    #undef MAX32
    #undef EXP32
    #undef PV32
    #undef RESCALE_O
    #undef REDUCE_MAX
    #undef REDUCE_SUM_L
    #undef FBODY64

    // ---- epilogue: O/l -> half2 word-permuted rows of g_attnt ----
    const float iA = 1.f / lA;
    const float iB = 1.f / lB;
    uint32_t* opA = g_attnt + ((size_t)b * TSEQ + rA) * RWORDS + h * 32;
    uint32_t* opB = g_attnt + ((size_t)b * TSEQ + rB) * RWORDS + h * 32;
    #pragma unroll
    for (int nt2 = 0; nt2 < 8; nt2++) {
        const int c = nt2 * 4 + tg;
        const int p = (c & 3) * 8 + (c >> 2);
        opA[p] = h2bits(o[nt2][0] * iA, o[nt2][1] * iA);
        opB[p] = h2bits(o[nt2][2] * iB, o[nt2][3] * iB);
    }
}

// ---------------- launch ----------------
extern "C" void kernel_launch(void* const* d_in, const int* in_sizes, int n_in,
                              void* d_out, int out_size)
{
    const float* x      = (const float*)d_in[0];
    const float* qkv_w  = (const float*)d_in[1];
    const float* qkv_b  = (const float*)d_in[2];
    const float* proj_w = (const float*)d_in[3];
    const float* proj_b = (const float*)d_in[4];
    float* out = (float*)d_out;

    cudaFuncSetAttribute(f16_gemm_kernel<QKV_N, 1>,
                         cudaFuncAttributeMaxDynamicSharedMemorySize, GEMM_SMEM_B);
    cudaFuncSetAttribute(f16_gemm_kernel<DMODEL, 0>,
                         cudaFuncAttributeMaxDynamicSharedMemorySize, GEMM_SMEM_B);

    uint32_t *d_xt, *d_wqkvt, *d_wprojt, *d_attnt;
    cudaGetSymbolAddress((void**)&d_xt, g_xt);
    cudaGetSymbolAddress((void**)&d_wqkvt, g_wqkvt);
    cudaGetSymbolAddress((void**)&d_wprojt, g_wprojt);
    cudaGetSymbolAddress((void**)&d_attnt, g_attnt);

    // 0) rope table + convert+pair-permute ALL operands in one launch
    convert_all_kernel<<<(NW_X + NW_WQ + NW_WP) / 256, 256>>>(x, qkv_w, proj_w);

    // 1) QKV GEMM with fused RoPE epilogue -> g_qt/g_kt/g_vtr
    f16_gemm_kernel<QKV_N, 1><<<dim3(QKV_N / 128, ROWS / 128), 256, GEMM_SMEM_B>>>(
        d_xt, d_wqkvt, qkv_b, nullptr);

    // 2) causal flash attention (fp16 mma) -> permuted O into g_attnt
    flash_mma_kernel<<<dim3(TSEQ / FBQ, NHEADS, BATCH), 256>>>();

    // 3) out = attn @ proj_w^T + proj_b
    f16_gemm_kernel<DMODEL, 0><<<dim3(DMODEL / 128, ROWS / 128), 256, GEMM_SMEM_B>>>(
        d_attnt, d_wprojt, proj_b, out);
}